// round 1
// baseline (speedup 1.0000x reference)
#include <cuda_runtime.h>
#include <cuda_bf16.h>
#include <math.h>

// Problem constants
#define BATCH 2
#define SEQ   2048
#define DMODEL 1024
#define NHEAD 16
#define DHEAD 64
#define M_ROWS (BATCH * SEQ)          // 4096
#define QKV_COLS (3 * DMODEL)         // 3072
#define ATT_SCALE 0.125f              // 1/sqrt(64)

// Scratch (static device globals; no allocations allowed)
__device__ float g_qkv[(size_t)M_ROWS * QKV_COLS];   // 50.3 MB
__device__ float g_ctx[(size_t)M_ROWS * DMODEL];     // 16.8 MB

// ---------------------------------------------------------------------------
// Tiled SGEMM: C = A(MxK) @ B(KxN), all row-major, M%128==0, N%128==0, K%8==0
// 128x128 tile, BK=8, 256 threads, 8x8 per-thread microtile.
// ---------------------------------------------------------------------------
#define BM 128
#define BN 128
#define BK 8
#define TM 8
#define TN 8

__global__ __launch_bounds__(256) void sgemm_kernel(
    const float* __restrict__ A, const float* __restrict__ B,
    float* __restrict__ C, int M, int N, int K)
{
    __shared__ float As[BK][BM];
    __shared__ float Bs[BK][BN];

    const int tid = threadIdx.x;
    const int tx = tid % 16;          // 0..15 -> col microtile
    const int ty = tid / 16;          // 0..15 -> row microtile
    const int row0 = blockIdx.y * BM;
    const int col0 = blockIdx.x * BN;

    // global->shared load mapping
    const int a_row = tid >> 1;             // 0..127
    const int a_col = (tid & 1) * 4;        // 0 or 4
    const int b_row = tid >> 5;             // 0..7
    const int b_col = (tid & 31) * 4;       // 0..124

    float acc[TM][TN];
#pragma unroll
    for (int i = 0; i < TM; i++)
#pragma unroll
        for (int j = 0; j < TN; j++) acc[i][j] = 0.f;

    for (int k0 = 0; k0 < K; k0 += BK) {
        float4 av = *(const float4*)&A[(size_t)(row0 + a_row) * K + k0 + a_col];
        float4 bv = *(const float4*)&B[(size_t)(k0 + b_row) * N + col0 + b_col];
        __syncthreads();
        As[a_col + 0][a_row] = av.x;
        As[a_col + 1][a_row] = av.y;
        As[a_col + 2][a_row] = av.z;
        As[a_col + 3][a_row] = av.w;
        *(float4*)&Bs[b_row][b_col] = bv;
        __syncthreads();

#pragma unroll
        for (int kk = 0; kk < BK; kk++) {
            float ar[TM], br[TN];
#pragma unroll
            for (int i = 0; i < TM; i++) ar[i] = As[kk][ty * TM + i];
#pragma unroll
            for (int j = 0; j < TN; j++) br[j] = Bs[kk][tx * TN + j];
#pragma unroll
            for (int i = 0; i < TM; i++)
#pragma unroll
                for (int j = 0; j < TN; j++)
                    acc[i][j] = fmaf(ar[i], br[j], acc[i][j]);
        }
    }

#pragma unroll
    for (int i = 0; i < TM; i++) {
        float* crow = &C[(size_t)(row0 + ty * TM + i) * N + col0 + tx * TN];
        float4 v0 = make_float4(acc[i][0], acc[i][1], acc[i][2], acc[i][3]);
        float4 v1 = make_float4(acc[i][4], acc[i][5], acc[i][6], acc[i][7]);
        *(float4*)(crow)     = v0;
        *(float4*)(crow + 4) = v1;
    }
}

// ---------------------------------------------------------------------------
// Flash attention, causal, fp32: one thread per query row.
// grid: (SEQ/128, NHEAD, BATCH), block: 128 threads.
// qkv layout per token row (3072 floats): [Q(1024) | K(1024) | V(1024)],
// head h occupies cols h*64..h*64+63 within each section.
// Writes ctx[b, t, h*64+d].
// ---------------------------------------------------------------------------
#define KT 32   // keys per smem tile

__global__ __launch_bounds__(128) void flash_kernel(
    const float* __restrict__ qkv, float* __restrict__ ctx)
{
    __shared__ float ks[KT][DHEAD];
    __shared__ float vs[KT][DHEAD];

    const int tid = threadIdx.x;
    const int h = blockIdx.y;
    const int b = blockIdx.z;
    const int q_idx = blockIdx.x * 128 + tid;

    const float* base = qkv + (size_t)b * SEQ * QKV_COLS;

    // load q row, pre-scaled
    float q[DHEAD];
    {
        const float* qp = base + (size_t)q_idx * QKV_COLS + h * DHEAD;
#pragma unroll
        for (int d = 0; d < DHEAD; d += 4) {
            float4 v = *(const float4*)(qp + d);
            q[d + 0] = v.x * ATT_SCALE;
            q[d + 1] = v.y * ATT_SCALE;
            q[d + 2] = v.z * ATT_SCALE;
            q[d + 3] = v.w * ATT_SCALE;
        }
    }

    float o[DHEAD];
#pragma unroll
    for (int d = 0; d < DHEAD; d++) o[d] = 0.f;
    float m = -1e30f;
    float l = 0.f;

    const int kend = blockIdx.x * 128 + 128;   // causal bound for this block
    for (int k0 = 0; k0 < kend; k0 += KT) {
        __syncthreads();
        // cooperative load of KT keys + values (each thread: 4 float4 per array)
#pragma unroll
        for (int it = 0; it < 4; it++) {
            int f = tid + it * 128;            // 0..511
            int key = f >> 4;
            int d4 = (f & 15) * 4;
            const float* kp = base + (size_t)(k0 + key) * QKV_COLS + DMODEL + h * DHEAD + d4;
            *(float4*)&ks[key][d4] = *(const float4*)kp;
            *(float4*)&vs[key][d4] = *(const float4*)(kp + DMODEL);
        }
        __syncthreads();

        int jmax = q_idx - k0 + 1;
        if (jmax > KT) jmax = KT;
        for (int j = 0; j < jmax; j++) {
            float s8[8];
#pragma unroll
            for (int u = 0; u < 8; u++) s8[u] = 0.f;
#pragma unroll
            for (int d = 0; d < DHEAD; d += 8)
#pragma unroll
                for (int u = 0; u < 8; u++)
                    s8[u] = fmaf(q[d + u], ks[j][d + u], s8[u]);
            float s = ((s8[0] + s8[1]) + (s8[2] + s8[3])) +
                      ((s8[4] + s8[5]) + (s8[6] + s8[7]));

            if (s > m) {                       // deferred rescale (rare)
                float corr = __expf(m - s);
                l *= corr;
#pragma unroll
                for (int d = 0; d < DHEAD; d++) o[d] *= corr;
                m = s;
            }
            float p = __expf(s - m);
            l += p;
#pragma unroll
            for (int d = 0; d < DHEAD; d++)
                o[d] = fmaf(p, vs[j][d], o[d]);
        }
    }

    const float inv = 1.f / l;
    float* op = ctx + (size_t)(b * SEQ + q_idx) * DMODEL + h * DHEAD;
#pragma unroll
    for (int d = 0; d < DHEAD; d += 4) {
        float4 v = make_float4(o[d] * inv, o[d + 1] * inv, o[d + 2] * inv, o[d + 3] * inv);
        *(float4*)(op + d) = v;
    }
}

// ---------------------------------------------------------------------------
extern "C" void kernel_launch(void* const* d_in, const int* in_sizes, int n_in,
                              void* d_out, int out_size)
{
    const float* x     = (const float*)d_in[0];   // (B,T,1024)
    const float* W_qkv = (const float*)d_in[1];   // (1024, 3072)
    const float* W_o   = (const float*)d_in[2];   // (1024, 1024)
    float* out = (float*)d_out;                   // (B,T,1024)

    float* qkv = nullptr;
    float* ctx = nullptr;
    cudaGetSymbolAddress((void**)&qkv, g_qkv);
    cudaGetSymbolAddress((void**)&ctx, g_ctx);

    // 1) qkv = x @ W_qkv   (4096 x 3072 x 1024)
    {
        dim3 grid(QKV_COLS / BN, M_ROWS / BM);
        sgemm_kernel<<<grid, 256>>>(x, W_qkv, qkv, M_ROWS, QKV_COLS, DMODEL);
    }
    // 2) causal flash attention -> ctx (4096 x 1024)
    {
        dim3 grid(SEQ / 128, NHEAD, BATCH);
        flash_kernel<<<grid, 128>>>(qkv, ctx);
    }
    // 3) out = ctx @ W_o   (4096 x 1024 x 1024)
    {
        dim3 grid(DMODEL / BN, M_ROWS / BM);
        sgemm_kernel<<<grid, 256>>>(ctx, W_o, out, M_ROWS, DMODEL, DMODEL);
    }
}

// round 3
// speedup vs baseline: 1.4014x; 1.4014x over previous
#include <cuda_runtime.h>
#include <cuda_bf16.h>
#include <math.h>
#include <stdint.h>

// Problem constants
#define BATCH 2
#define SEQ   2048
#define DMODEL 1024
#define NHEAD 16
#define DHEAD 64
#define MROWS (BATCH * SEQ)           // 4096
#define QKV_COLS (3 * DMODEL)         // 3072
#define K3 (3 * DMODEL)               // 3072 = interleaved K' for split-bf16
#define ATT_SCALE 0.125f

// ---------------------------------------------------------------------------
// Scratch (static device globals; allocations are forbidden)
// ---------------------------------------------------------------------------
__device__ float g_qkv[(size_t)MROWS * QKV_COLS];          // 50 MB
__device__ float g_ctx[(size_t)MROWS * DMODEL];            // 17 MB
__device__ __nv_bfloat16 g_aP[(size_t)MROWS * K3];         // 25 MB (split-interleaved activations)
__device__ __nv_bfloat16 g_w1P[(size_t)QKV_COLS * K3];     // 19 MB (W_qkv^T split-interleaved)
__device__ __nv_bfloat16 g_w2P[(size_t)DMODEL * K3];       // 6 MB  (W_o^T split-interleaved)

__device__ __forceinline__ uint32_t smem_u32(const void* p) {
    uint32_t a;
    asm("{ .reg .u64 t; cvta.to.shared.u64 t, %1; cvt.u32.u64 %0, t; }" : "=r"(a) : "l"(p));
    return a;
}

// ---------------------------------------------------------------------------
// Conversion: fp32 activations (M x 1024) -> split-interleaved bf16 (M x 3072)
// out[3k] = hi(v), out[3k+1] = lo(v), out[3k+2] = hi(v)
// Each thread handles one input pair -> 3 aligned bf16x2 stores.
// ---------------------------------------------------------------------------
__global__ void conv_act_kernel(const float* __restrict__ in,
                                __nv_bfloat16* __restrict__ out)
{
    size_t j = (size_t)blockIdx.x * blockDim.x + threadIdx.x;   // pair index
    float2 v = *(const float2*)(in + 2 * j);
    __nv_bfloat16 h0 = __float2bfloat16_rn(v.x);
    __nv_bfloat16 h1 = __float2bfloat16_rn(v.y);
    __nv_bfloat16 l0 = __float2bfloat16_rn(v.x - __bfloat162float(h0));
    __nv_bfloat16 l1 = __float2bfloat16_rn(v.y - __bfloat162float(h1));
    __nv_bfloat16* o = out + 6 * j;
    *(__nv_bfloat162*)(o + 0) = __nv_bfloat162(h0, l0);
    *(__nv_bfloat162*)(o + 2) = __nv_bfloat162(h0, h1);
    *(__nv_bfloat162*)(o + 4) = __nv_bfloat162(l1, h1);
}

// ---------------------------------------------------------------------------
// Conversion: W (K x N fp32, row-major) -> B' (N x 3K bf16)
// B'[n][3k] = hi(W[k][n]), [3k+1] = hi, [3k+2] = lo
// ---------------------------------------------------------------------------
__global__ void conv_weight_kernel(const float* __restrict__ W,
                                   __nv_bfloat16* __restrict__ out,
                                   int N /*cols of W*/)
{
    __shared__ float t[32][33];
    const int tid = threadIdx.y * 32 + threadIdx.x;   // blockDim (32,8)
    const int tx = threadIdx.x, ty = threadIdx.y;
#pragma unroll
    for (int i = 0; i < 4; i++) {
        int k = blockIdx.y * 32 + ty + 8 * i;
        int n = blockIdx.x * 32 + tx;
        t[ty + 8 * i][tx] = W[(size_t)k * N + n];
    }
    __syncthreads();
    const int w = tid >> 5, l = tid & 31;
#pragma unroll
    for (int r = 0; r < 4; r++) {
        int nl = w * 4 + r;
        int n = blockIdx.x * 32 + nl;
        float v = t[l][nl];
        __nv_bfloat16 hi = __float2bfloat16_rn(v);
        __nv_bfloat16 lo = __float2bfloat16_rn(v - __bfloat162float(hi));
        __nv_bfloat16* o = out + (size_t)n * K3 + (size_t)(blockIdx.y * 32 + l) * 3;
        o[0] = hi; o[1] = hi; o[2] = lo;
    }
}

// ---------------------------------------------------------------------------
// bf16 mma.sync GEMM: C[M x N] fp32 = A'[M x K'] * B'[N x K']^T
// CTA 128x128, BK=32, 256 threads (8 warps, 4x2), warp tile 32x64.
// cp.async double buffer, 80B-padded smem rows (conflict-free ldmatrix).
// ---------------------------------------------------------------------------
#define GBK 32
#define ROWB 80                      // padded row bytes (32 bf16 = 64B data)
#define TILEB (128 * ROWB)           // 10240 B

__global__ void __launch_bounds__(256, 2) mma_gemm_kernel(
    const __nv_bfloat16* __restrict__ A, const __nv_bfloat16* __restrict__ B,
    float* __restrict__ C, int N, int K)
{
    __shared__ char smA[2][TILEB];
    __shared__ char smB[2][TILEB];

    const int tid = threadIdx.x;
    const int wid = tid >> 5;
    const int lane = tid & 31;
    const int bm = blockIdx.y * 128;
    const int bn = blockIdx.x * 128;

    // warp tile origin
    const int wm0 = (wid >> 1) * 32;
    const int wn0 = (wid & 1) * 64;

    // cp.async mapping: f = tid + 256*i -> row = f>>2, chunk = f&3 (16B)
    const int ld_row = tid >> 2;           // 0..63  (+64 for i=1)
    const int ld_ch = tid & 3;

    // ldmatrix per-lane offsets
    const int a_row_off = (lane & 7) + ((lane >> 3) & 1) * 8;   // row within m16
    const int a_kch = (lane >> 4);                               // k8 chunk 0/1
    const int b_row_off = (lane & 7) + ((lane >> 4) & 1) * 8;   // row within n16
    const int b_kch = (lane >> 3) & 1;

    const uint32_t sA[2] = { smem_u32(smA[0]), smem_u32(smA[1]) };
    const uint32_t sB[2] = { smem_u32(smB[0]), smem_u32(smB[1]) };

    float acc[2][8][4];
#pragma unroll
    for (int mi = 0; mi < 2; mi++)
#pragma unroll
        for (int ni = 0; ni < 8; ni++)
#pragma unroll
            for (int r = 0; r < 4; r++) acc[mi][ni][r] = 0.f;

    const int NIT = K / GBK;

    // ---- load one stage ----
    auto load_stage = [&](int st, int k0) {
#pragma unroll
        for (int i = 0; i < 2; i++) {
            int row = ld_row + i * 64;
            uint32_t dA = sA[st] + row * ROWB + ld_ch * 16;
            uint32_t dB = sB[st] + row * ROWB + ld_ch * 16;
            const __nv_bfloat16* pA = A + (size_t)(bm + row) * K + k0 + ld_ch * 8;
            const __nv_bfloat16* pB = B + (size_t)(bn + row) * K + k0 + ld_ch * 8;
            asm volatile("cp.async.cg.shared.global [%0], [%1], 16;\n" :: "r"(dA), "l"(pA) : "memory");
            asm volatile("cp.async.cg.shared.global [%0], [%1], 16;\n" :: "r"(dB), "l"(pB) : "memory");
        }
        asm volatile("cp.async.commit_group;\n" ::: "memory");
    };

    load_stage(0, 0);

    for (int it = 0; it < NIT; it++) {
        asm volatile("cp.async.wait_group 0;\n" ::: "memory");
        __syncthreads();
        if (it + 1 < NIT) load_stage((it + 1) & 1, (it + 1) * GBK);

        const int st = it & 1;
#pragma unroll
        for (int ks = 0; ks < 2; ks++) {
            // A fragments: 2 x ldmatrix.x4
            uint32_t af[2][4];
#pragma unroll
            for (int mi = 0; mi < 2; mi++) {
                uint32_t addr = sA[st] + (wm0 + mi * 16 + a_row_off) * ROWB +
                                (ks * 2 + a_kch) * 16;
                asm volatile("ldmatrix.sync.aligned.m8n8.x4.shared.b16 {%0,%1,%2,%3}, [%4];"
                    : "=r"(af[mi][0]), "=r"(af[mi][1]), "=r"(af[mi][2]), "=r"(af[mi][3])
                    : "r"(addr));
            }
            // B fragments: 4 x ldmatrix.x4 (each covers n16 x k16)
            uint32_t bf[4][4];
#pragma unroll
            for (int nj = 0; nj < 4; nj++) {
                uint32_t addr = sB[st] + (wn0 + nj * 16 + b_row_off) * ROWB +
                                (ks * 2 + b_kch) * 16;
                asm volatile("ldmatrix.sync.aligned.m8n8.x4.shared.b16 {%0,%1,%2,%3}, [%4];"
                    : "=r"(bf[nj][0]), "=r"(bf[nj][1]), "=r"(bf[nj][2]), "=r"(bf[nj][3])
                    : "r"(addr));
            }
#pragma unroll
            for (int mi = 0; mi < 2; mi++)
#pragma unroll
                for (int ni = 0; ni < 8; ni++) {
                    uint32_t b0 = bf[ni >> 1][(ni & 1) * 2 + 0];
                    uint32_t b1 = bf[ni >> 1][(ni & 1) * 2 + 1];
                    asm volatile(
                        "mma.sync.aligned.m16n8k16.row.col.f32.bf16.bf16.f32 "
                        "{%0,%1,%2,%3}, {%4,%5,%6,%7}, {%8,%9}, {%0,%1,%2,%3};"
                        : "+f"(acc[mi][ni][0]), "+f"(acc[mi][ni][1]),
                          "+f"(acc[mi][ni][2]), "+f"(acc[mi][ni][3])
                        : "r"(af[mi][0]), "r"(af[mi][1]), "r"(af[mi][2]), "r"(af[mi][3]),
                          "r"(b0), "r"(b1));
                }
        }
        __syncthreads();
    }

    // epilogue: D layout m16n8: d0,d1 -> (row=g, col=tc,tc+1); d2,d3 -> row+8
    const int gr = lane >> 2;
    const int tc = (lane & 3) * 2;
#pragma unroll
    for (int mi = 0; mi < 2; mi++) {
#pragma unroll
        for (int ni = 0; ni < 8; ni++) {
            size_t r0 = (size_t)(bm + wm0 + mi * 16 + gr);
            int col = bn + wn0 + ni * 8 + tc;
            *(float2*)&C[r0 * N + col] = make_float2(acc[mi][ni][0], acc[mi][ni][1]);
            *(float2*)&C[(r0 + 8) * N + col] = make_float2(acc[mi][ni][2], acc[mi][ni][3]);
        }
    }
}

// ---------------------------------------------------------------------------
// Flash attention, causal, fp32, one thread per query, float4 smem reads.
// grid: (SEQ/128, NHEAD, BATCH), block: 128.
// ---------------------------------------------------------------------------
#define KT 32

__global__ void __launch_bounds__(128) flash_kernel(
    const float* __restrict__ qkv, float* __restrict__ ctx)
{
    __shared__ float ks[KT][DHEAD];
    __shared__ float vs[KT][DHEAD];

    const int tid = threadIdx.x;
    const int h = blockIdx.y;
    const int b = blockIdx.z;
    const int qt = gridDim.x - 1 - blockIdx.x;     // heavy tiles first
    const int q_idx = qt * 128 + tid;

    const float* base = qkv + (size_t)b * SEQ * QKV_COLS;

    float q[DHEAD];
    {
        const float* qp = base + (size_t)q_idx * QKV_COLS + h * DHEAD;
#pragma unroll
        for (int d = 0; d < DHEAD; d += 4) {
            float4 v = *(const float4*)(qp + d);
            q[d + 0] = v.x * ATT_SCALE; q[d + 1] = v.y * ATT_SCALE;
            q[d + 2] = v.z * ATT_SCALE; q[d + 3] = v.w * ATT_SCALE;
        }
    }

    float o[DHEAD];
#pragma unroll
    for (int d = 0; d < DHEAD; d++) o[d] = 0.f;
    float m = -1e30f, l = 0.f;

    const int kend = qt * 128 + 128;
    const float* kbase = base + (size_t)DMODEL + h * DHEAD;
    for (int k0 = 0; k0 < kend; k0 += KT) {
        __syncthreads();
#pragma unroll
        for (int it = 0; it < 4; it++) {
            int f = tid + it * 128;
            int key = f >> 4;
            int d4 = (f & 15) * 4;
            const float* kp = kbase + (size_t)(k0 + key) * QKV_COLS + d4;
            *(float4*)&ks[key][d4] = *(const float4*)kp;
            *(float4*)&vs[key][d4] = *(const float4*)(kp + DMODEL);
        }
        __syncthreads();

        int jmax = q_idx - k0 + 1;
        if (jmax > KT) jmax = KT;
        for (int j = 0; j < jmax; j++) {
            float sx = 0.f, sy = 0.f, sz = 0.f, sw = 0.f;
#pragma unroll
            for (int d4 = 0; d4 < DHEAD / 4; d4++) {
                float4 kv = *(const float4*)&ks[j][d4 * 4];
                sx = fmaf(q[d4 * 4 + 0], kv.x, sx);
                sy = fmaf(q[d4 * 4 + 1], kv.y, sy);
                sz = fmaf(q[d4 * 4 + 2], kv.z, sz);
                sw = fmaf(q[d4 * 4 + 3], kv.w, sw);
            }
            float s = (sx + sy) + (sz + sw);

            if (s > m) {
                float corr = __expf(m - s);
                l *= corr;
#pragma unroll
                for (int d = 0; d < DHEAD; d++) o[d] *= corr;
                m = s;
            }
            float p = __expf(s - m);
            l += p;
#pragma unroll
            for (int d4 = 0; d4 < DHEAD / 4; d4++) {
                float4 vv = *(const float4*)&vs[j][d4 * 4];
                o[d4 * 4 + 0] = fmaf(p, vv.x, o[d4 * 4 + 0]);
                o[d4 * 4 + 1] = fmaf(p, vv.y, o[d4 * 4 + 1]);
                o[d4 * 4 + 2] = fmaf(p, vv.z, o[d4 * 4 + 2]);
                o[d4 * 4 + 3] = fmaf(p, vv.w, o[d4 * 4 + 3]);
            }
        }
    }

    const float inv = 1.f / l;
    float* op = ctx + (size_t)(b * SEQ + q_idx) * DMODEL + h * DHEAD;
#pragma unroll
    for (int d = 0; d < DHEAD; d += 4) {
        *(float4*)(op + d) = make_float4(o[d] * inv, o[d + 1] * inv,
                                         o[d + 2] * inv, o[d + 3] * inv);
    }
}

// ---------------------------------------------------------------------------
extern "C" void kernel_launch(void* const* d_in, const int* in_sizes, int n_in,
                              void* d_out, int out_size)
{
    const float* x     = (const float*)d_in[0];   // (B,T,1024)
    const float* W_qkv = (const float*)d_in[1];   // (1024, 3072)
    const float* W_o   = (const float*)d_in[2];   // (1024, 1024)
    float* out = (float*)d_out;

    float *qkv = nullptr, *ctx = nullptr;
    __nv_bfloat16 *aP, *w1P, *w2P;
    cudaGetSymbolAddress((void**)&qkv, g_qkv);
    cudaGetSymbolAddress((void**)&ctx, g_ctx);
    cudaGetSymbolAddress((void**)&aP, g_aP);
    cudaGetSymbolAddress((void**)&w1P, g_w1P);
    cudaGetSymbolAddress((void**)&w2P, g_w2P);

    // weight conversions (transpose + split-interleave)
    {
        dim3 g(QKV_COLS / 32, DMODEL / 32);
        conv_weight_kernel<<<g, dim3(32, 8)>>>(W_qkv, w1P, QKV_COLS);
    }
    {
        dim3 g(DMODEL / 32, DMODEL / 32);
        conv_weight_kernel<<<g, dim3(32, 8)>>>(W_o, w2P, DMODEL);
    }
    // activation conversion
    conv_act_kernel<<<(MROWS * DMODEL / 2) / 256, 256>>>(x, aP);

    // 1) qkv = x @ W_qkv   (split-bf16 mma.sync, K'=3072)
    {
        dim3 grid(QKV_COLS / 128, MROWS / 128);
        mma_gemm_kernel<<<grid, 256>>>(aP, w1P, qkv, QKV_COLS, K3);
    }
    // 2) causal flash attention
    {
        dim3 grid(SEQ / 128, NHEAD, BATCH);
        flash_kernel<<<grid, 128>>>(qkv, ctx);
    }
    // 3) out = ctx @ W_o
    conv_act_kernel<<<(MROWS * DMODEL / 2) / 256, 256>>>(ctx, aP);
    {
        dim3 grid(DMODEL / 128, MROWS / 128);
        mma_gemm_kernel<<<grid, 256>>>(aP, w2P, out, DMODEL, K3);
    }
}

// round 4
// speedup vs baseline: 2.8273x; 2.0175x over previous
#include <cuda_runtime.h>
#include <cuda_bf16.h>
#include <math.h>
#include <stdint.h>

// Problem constants
#define BATCH 2
#define SEQ   2048
#define DMODEL 1024
#define NHEAD 16
#define DHEAD 64
#define MROWS (BATCH * SEQ)           // 4096
#define QKV_COLS (3 * DMODEL)         // 3072
#define K3 (3 * DMODEL)               // 3072 = interleaved K' for split-bf16
#define QSCALE 0.18033688f            // 0.125 * log2(e)

// ---------------------------------------------------------------------------
// Scratch (static device globals; allocations are forbidden)
// ---------------------------------------------------------------------------
__device__ float g_qkv[(size_t)MROWS * QKV_COLS];          // 50 MB
__device__ float g_ctx[(size_t)MROWS * DMODEL];            // 17 MB
__device__ __nv_bfloat16 g_aP[(size_t)MROWS * K3];         // 25 MB
__device__ __nv_bfloat16 g_w1P[(size_t)QKV_COLS * K3];     // 19 MB
__device__ __nv_bfloat16 g_w2P[(size_t)DMODEL * K3];       // 6 MB
// Attention operands
__device__ __nv_bfloat16 g_qp[(size_t)BATCH * NHEAD * SEQ * 192];  // 25 MB
__device__ __nv_bfloat16 g_kp[(size_t)BATCH * NHEAD * SEQ * 192];  // 25 MB
__device__ __nv_bfloat16 g_vthi[(size_t)BATCH * NHEAD * DHEAD * SEQ]; // 8.4 MB
__device__ __nv_bfloat16 g_vtlo[(size_t)BATCH * NHEAD * DHEAD * SEQ]; // 8.4 MB

__device__ __forceinline__ uint32_t smem_u32(const void* p) {
    uint32_t a;
    asm("{ .reg .u64 t; cvta.to.shared.u64 t, %1; cvt.u32.u64 %0, t; }" : "=r"(a) : "l"(p));
    return a;
}
__device__ __forceinline__ float fast_exp2(float x) {
    float y; asm("ex2.approx.ftz.f32 %0, %1;" : "=f"(y) : "f"(x)); return y;
}
// pack: low half = lo, high half = hi
__device__ __forceinline__ uint32_t pack_bf16x2(float lo, float hi) {
    uint32_t r; asm("cvt.rn.bf16x2.f32 %0, %1, %2;" : "=r"(r) : "f"(hi), "f"(lo)); return r;
}
__device__ __forceinline__ float bf16lo_f(uint32_t u) { return __uint_as_float(u << 16); }
__device__ __forceinline__ float bf16hi_f(uint32_t u) { return __uint_as_float(u & 0xffff0000u); }

#define LDMATRIX_X4(r0, r1, r2, r3, addr) \
    asm volatile("ldmatrix.sync.aligned.m8n8.x4.shared.b16 {%0,%1,%2,%3}, [%4];" \
        : "=r"(r0), "=r"(r1), "=r"(r2), "=r"(r3) : "r"(addr))

#define MMA_BF16(acc, a0, a1, a2, a3, b0, b1) \
    asm volatile( \
        "mma.sync.aligned.m16n8k16.row.col.f32.bf16.bf16.f32 " \
        "{%0,%1,%2,%3}, {%4,%5,%6,%7}, {%8,%9}, {%0,%1,%2,%3};" \
        : "+f"((acc)[0]), "+f"((acc)[1]), "+f"((acc)[2]), "+f"((acc)[3]) \
        : "r"(a0), "r"(a1), "r"(a2), "r"(a3), "r"(b0), "r"(b1))

// ---------------------------------------------------------------------------
// Conversion: fp32 activations (M x 1024) -> split-interleaved bf16 (M x 3072)
// out[3k]=hi, out[3k+1]=lo, out[3k+2]=hi   (A-side pattern)
// ---------------------------------------------------------------------------
__global__ void conv_act_kernel(const float* __restrict__ in,
                                __nv_bfloat16* __restrict__ out)
{
    size_t j = (size_t)blockIdx.x * blockDim.x + threadIdx.x;
    float2 v = *(const float2*)(in + 2 * j);
    __nv_bfloat16 h0 = __float2bfloat16_rn(v.x);
    __nv_bfloat16 h1 = __float2bfloat16_rn(v.y);
    __nv_bfloat16 l0 = __float2bfloat16_rn(v.x - __bfloat162float(h0));
    __nv_bfloat16 l1 = __float2bfloat16_rn(v.y - __bfloat162float(h1));
    __nv_bfloat16* o = out + 6 * j;
    *(__nv_bfloat162*)(o + 0) = __nv_bfloat162(h0, l0);
    *(__nv_bfloat162*)(o + 2) = __nv_bfloat162(h0, h1);
    *(__nv_bfloat162*)(o + 4) = __nv_bfloat162(l1, h1);
}

// ---------------------------------------------------------------------------
// Conversion: W (K x N fp32, row-major) -> B' (N x 3K bf16): hi,hi,lo
// ---------------------------------------------------------------------------
__global__ void conv_weight_kernel(const float* __restrict__ W,
                                   __nv_bfloat16* __restrict__ out,
                                   int N)
{
    __shared__ float t[32][33];
    const int tid = threadIdx.y * 32 + threadIdx.x;
    const int tx = threadIdx.x, ty = threadIdx.y;
#pragma unroll
    for (int i = 0; i < 4; i++) {
        int k = blockIdx.y * 32 + ty + 8 * i;
        int n = blockIdx.x * 32 + tx;
        t[ty + 8 * i][tx] = W[(size_t)k * N + n];
    }
    __syncthreads();
    const int w = tid >> 5, l = tid & 31;
#pragma unroll
    for (int r = 0; r < 4; r++) {
        int nl = w * 4 + r;
        int n = blockIdx.x * 32 + nl;
        float v = t[l][nl];
        __nv_bfloat16 hi = __float2bfloat16_rn(v);
        __nv_bfloat16 lo = __float2bfloat16_rn(v - __bfloat162float(hi));
        __nv_bfloat16* o = out + (size_t)n * K3 + (size_t)(blockIdx.y * 32 + l) * 3;
        o[0] = hi; o[1] = hi; o[2] = lo;
    }
}

// ---------------------------------------------------------------------------
// Conversion: g_qkv -> Q' (scaled, split-interleaved A-pattern) and
//                     K' (split-interleaved B-pattern), layout [b,h,t,192].
// 1M threads, each handles 4 head-dims of one (b,h,t).
// ---------------------------------------------------------------------------
__global__ void qk_conv_kernel(const float* __restrict__ qkv,
                               __nv_bfloat16* __restrict__ qp,
                               __nv_bfloat16* __restrict__ kp)
{
    uint32_t flat = blockIdx.x * blockDim.x + threadIdx.x;
    int dc = flat & 15;              // d-chunk (4 dims)
    int t = (flat >> 4) & (SEQ - 1);
    int h = (flat >> 15) & (NHEAD - 1);
    int b = flat >> 19;
    const float* src = qkv + ((size_t)(b * SEQ + t) * QKV_COLS) + h * DHEAD + dc * 4;
    float4 qv = *(const float4*)src;
    float4 kv = *(const float4*)(src + DMODEL);

    union { __nv_bfloat16 h[12]; uint2 u[3]; } oq, ok;
    float qs[4] = { qv.x * QSCALE, qv.y * QSCALE, qv.z * QSCALE, qv.w * QSCALE };
    float ks[4] = { kv.x, kv.y, kv.z, kv.w };
#pragma unroll
    for (int e = 0; e < 4; e++) {
        __nv_bfloat16 qh = __float2bfloat16_rn(qs[e]);
        __nv_bfloat16 ql = __float2bfloat16_rn(qs[e] - __bfloat162float(qh));
        oq.h[3 * e + 0] = qh; oq.h[3 * e + 1] = ql; oq.h[3 * e + 2] = qh;
        __nv_bfloat16 kh = __float2bfloat16_rn(ks[e]);
        __nv_bfloat16 kl = __float2bfloat16_rn(ks[e] - __bfloat162float(kh));
        ok.h[3 * e + 0] = kh; ok.h[3 * e + 1] = kh; ok.h[3 * e + 2] = kl;
    }
    size_t base = ((size_t)((b * NHEAD + h) * SEQ + t)) * 192 + dc * 12;
    uint2* qo = (uint2*)(qp + base);
    uint2* ko = (uint2*)(kp + base);
#pragma unroll
    for (int i = 0; i < 3; i++) { qo[i] = oq.u[i]; ko[i] = ok.u[i]; }
}

// ---------------------------------------------------------------------------
// Conversion: V (from g_qkv) -> transposed split Vt[b,h,d,t] hi/lo bf16.
// grid (SEQ/32, 2, B*H), block (32,8).
// ---------------------------------------------------------------------------
__global__ void vt_conv_kernel(const float* __restrict__ qkv,
                               __nv_bfloat16* __restrict__ vthi,
                               __nv_bfloat16* __restrict__ vtlo)
{
    __shared__ float sm[32][33];
    const int tx = threadIdx.x, ty = threadIdx.y;
    const int t0 = blockIdx.x * 32;
    const int dblk = blockIdx.y;
    const int bh = blockIdx.z;
    const int b = bh >> 4, h = bh & 15;
#pragma unroll
    for (int i = 0; i < 4; i++) {
        int tl = ty + 8 * i;
        sm[tl][tx] = qkv[((size_t)(b * SEQ + t0 + tl)) * QKV_COLS +
                         2 * DMODEL + h * DHEAD + dblk * 32 + tx];
    }
    __syncthreads();
#pragma unroll
    for (int i = 0; i < 4; i++) {
        int dl = ty + 8 * i;
        float v = sm[tx][dl];
        __nv_bfloat16 hi = __float2bfloat16_rn(v);
        __nv_bfloat16 lo = __float2bfloat16_rn(v - __bfloat162float(hi));
        size_t o = ((size_t)(bh * DHEAD + dblk * 32 + dl)) * SEQ + t0 + tx;
        vthi[o] = hi;
        vtlo[o] = lo;
    }
}

// ---------------------------------------------------------------------------
// bf16 mma.sync GEMM: C[M x N] fp32 = A'[M x K'] * B'[N x K']^T   (unchanged R3)
// ---------------------------------------------------------------------------
#define GBK 32
#define ROWB 80
#define TILEB (128 * ROWB)

__global__ void __launch_bounds__(256, 2) mma_gemm_kernel(
    const __nv_bfloat16* __restrict__ A, const __nv_bfloat16* __restrict__ B,
    float* __restrict__ C, int N, int K)
{
    __shared__ char smA[2][TILEB];
    __shared__ char smB[2][TILEB];

    const int tid = threadIdx.x;
    const int wid = tid >> 5;
    const int lane = tid & 31;
    const int bm = blockIdx.y * 128;
    const int bn = blockIdx.x * 128;
    const int wm0 = (wid >> 1) * 32;
    const int wn0 = (wid & 1) * 64;
    const int ld_row = tid >> 2;
    const int ld_ch = tid & 3;
    const int a_row_off = (lane & 7) + ((lane >> 3) & 1) * 8;
    const int a_kch = (lane >> 4);
    const int b_row_off = (lane & 7) + ((lane >> 4) & 1) * 8;
    const int b_kch = (lane >> 3) & 1;

    const uint32_t sA[2] = { smem_u32(smA[0]), smem_u32(smA[1]) };
    const uint32_t sB[2] = { smem_u32(smB[0]), smem_u32(smB[1]) };

    float acc[2][8][4];
#pragma unroll
    for (int mi = 0; mi < 2; mi++)
#pragma unroll
        for (int ni = 0; ni < 8; ni++)
#pragma unroll
            for (int r = 0; r < 4; r++) acc[mi][ni][r] = 0.f;

    const int NIT = K / GBK;

    auto load_stage = [&](int st, int k0) {
#pragma unroll
        for (int i = 0; i < 2; i++) {
            int row = ld_row + i * 64;
            uint32_t dA = sA[st] + row * ROWB + ld_ch * 16;
            uint32_t dB = sB[st] + row * ROWB + ld_ch * 16;
            const __nv_bfloat16* pA = A + (size_t)(bm + row) * K + k0 + ld_ch * 8;
            const __nv_bfloat16* pB = B + (size_t)(bn + row) * K + k0 + ld_ch * 8;
            asm volatile("cp.async.cg.shared.global [%0], [%1], 16;\n" :: "r"(dA), "l"(pA) : "memory");
            asm volatile("cp.async.cg.shared.global [%0], [%1], 16;\n" :: "r"(dB), "l"(pB) : "memory");
        }
        asm volatile("cp.async.commit_group;\n" ::: "memory");
    };

    load_stage(0, 0);

    for (int it = 0; it < NIT; it++) {
        asm volatile("cp.async.wait_group 0;\n" ::: "memory");
        __syncthreads();
        if (it + 1 < NIT) load_stage((it + 1) & 1, (it + 1) * GBK);

        const int st = it & 1;
#pragma unroll
        for (int ks = 0; ks < 2; ks++) {
            uint32_t af[2][4];
#pragma unroll
            for (int mi = 0; mi < 2; mi++) {
                uint32_t addr = sA[st] + (wm0 + mi * 16 + a_row_off) * ROWB +
                                (ks * 2 + a_kch) * 16;
                LDMATRIX_X4(af[mi][0], af[mi][1], af[mi][2], af[mi][3], addr);
            }
            uint32_t bfr[4][4];
#pragma unroll
            for (int nj = 0; nj < 4; nj++) {
                uint32_t addr = sB[st] + (wn0 + nj * 16 + b_row_off) * ROWB +
                                (ks * 2 + b_kch) * 16;
                LDMATRIX_X4(bfr[nj][0], bfr[nj][1], bfr[nj][2], bfr[nj][3], addr);
            }
#pragma unroll
            for (int mi = 0; mi < 2; mi++)
#pragma unroll
                for (int ni = 0; ni < 8; ni++)
                    MMA_BF16(acc[mi][ni], af[mi][0], af[mi][1], af[mi][2], af[mi][3],
                             bfr[ni >> 1][(ni & 1) * 2 + 0], bfr[ni >> 1][(ni & 1) * 2 + 1]);
        }
        __syncthreads();
    }

    const int gr = lane >> 2;
    const int tc = (lane & 3) * 2;
#pragma unroll
    for (int mi = 0; mi < 2; mi++) {
#pragma unroll
        for (int ni = 0; ni < 8; ni++) {
            size_t r0 = (size_t)(bm + wm0 + mi * 16 + gr);
            int col = bn + wn0 + ni * 8 + tc;
            *(float2*)&C[r0 * N + col] = make_float2(acc[mi][ni][0], acc[mi][ni][1]);
            *(float2*)&C[(r0 + 8) * N + col] = make_float2(acc[mi][ni][2], acc[mi][ni][3]);
        }
    }
}

// ---------------------------------------------------------------------------
// Tensor-core flash attention (FA2), causal.
// CTA: 64 queries x 1 head; 4 warps, each m16 x 64 keys.
// S = Q'.K'^T (split-interleaved K'=192). PV = Phi.Vhi + Plo.Vhi + Phi.Vlo.
// grid (SEQ/64, NHEAD, BATCH), block 128, dynamic smem double-buffered.
// ---------------------------------------------------------------------------
#define KPITCH 400                  // 192 bf16 = 384B data + 16 pad
#define VPITCH 144                  // 64 bf16 = 128B data + 16 pad
#define KS_BYTES (64 * KPITCH)      // 25600
#define VS_BYTES (64 * VPITCH)      // 9216
#define FSTAGE (KS_BYTES + 2 * VS_BYTES)  // 44032
#define FSMEM (2 * FSTAGE)          // 88064

__global__ void __launch_bounds__(128, 2) flash_mma_kernel(
    const __nv_bfloat16* __restrict__ qp, const __nv_bfloat16* __restrict__ kp,
    const __nv_bfloat16* __restrict__ vthi, const __nv_bfloat16* __restrict__ vtlo,
    float* __restrict__ ctx)
{
    extern __shared__ char fsm[];
    const int tid = threadIdx.x;
    const int warp = tid >> 5;
    const int lane = tid & 31;
    const int qt = gridDim.x - 1 - blockIdx.x;       // heavy tiles first
    const int h = blockIdx.y;
    const int b = blockIdx.z;
    const int bh = b * NHEAD + h;
    const int q0 = qt * 64;

    const uint32_t sb = smem_u32(fsm);
    const int gr = lane >> 2;
    const int tc = lane & 3;
    const int a_row_off = (lane & 7) + ((lane >> 3) & 1) * 8;
    const int a_kch = lane >> 4;
    const int b_row_off = (lane & 7) + ((lane >> 4) & 1) * 8;
    const int b_kch = (lane >> 3) & 1;

    // ---- stage Q' tile into stage-0 K area, extract A fragments
    {
        const __nv_bfloat16* qsrc = qp + ((size_t)(bh * SEQ + q0)) * 192;
#pragma unroll
        for (int i = 0; i < 12; i++) {
            int c = i * 128 + tid;           // 0..1535
            int row = c / 24, ch = c % 24;
            uint32_t dst = sb + row * KPITCH + ch * 16;
            const __nv_bfloat16* src = qsrc + (size_t)row * 192 + ch * 8;
            asm volatile("cp.async.cg.shared.global [%0], [%1], 16;\n" :: "r"(dst), "l"(src) : "memory");
        }
        asm volatile("cp.async.commit_group;\ncp.async.wait_group 0;\n" ::: "memory");
        __syncthreads();
    }
    uint32_t qf[12][4];
#pragma unroll
    for (int ck = 0; ck < 12; ck++) {
        uint32_t addr = sb + (warp * 16 + a_row_off) * KPITCH + ck * 32 + a_kch * 16;
        LDMATRIX_X4(qf[ck][0], qf[ck][1], qf[ck][2], qf[ck][3], addr);
    }
    __syncthreads();

    float oacc[8][4];
#pragma unroll
    for (int t = 0; t < 8; t++)
#pragma unroll
        for (int r = 0; r < 4; r++) oacc[t][r] = 0.f;
    float m0 = -1e30f, m1 = -1e30f, l0 = 0.f, l1 = 0.f;

    auto load_tile = [&](int kt, int st) {
        const int kt0 = kt * 64;
        uint32_t ks = sb + st * FSTAGE;
        uint32_t vh = ks + KS_BYTES;
        uint32_t vl = vh + VS_BYTES;
        const __nv_bfloat16* ksrc = kp + ((size_t)(bh * SEQ + kt0)) * 192;
#pragma unroll
        for (int i = 0; i < 12; i++) {
            int c = i * 128 + tid;
            int row = c / 24, ch = c % 24;
            uint32_t dst = ks + row * KPITCH + ch * 16;
            const __nv_bfloat16* src = ksrc + (size_t)row * 192 + ch * 8;
            asm volatile("cp.async.cg.shared.global [%0], [%1], 16;\n" :: "r"(dst), "l"(src) : "memory");
        }
#pragma unroll
        for (int i = 0; i < 4; i++) {
            int c = i * 128 + tid;            // 0..511
            int row = c >> 3, ch = c & 7;     // row = d
            size_t so = ((size_t)(bh * DHEAD + row)) * SEQ + kt0 + ch * 8;
            uint32_t dsh = vh + row * VPITCH + ch * 16;
            uint32_t dsl = vl + row * VPITCH + ch * 16;
            asm volatile("cp.async.cg.shared.global [%0], [%1], 16;\n" :: "r"(dsh), "l"(vthi + so) : "memory");
            asm volatile("cp.async.cg.shared.global [%0], [%1], 16;\n" :: "r"(dsl), "l"(vtlo + so) : "memory");
        }
    };

    load_tile(0, 0);
    asm volatile("cp.async.commit_group;\n" ::: "memory");
    if (qt >= 1) load_tile(1, 1);
    asm volatile("cp.async.commit_group;\n" ::: "memory");

    for (int kt = 0; kt <= qt; kt++) {
        asm volatile("cp.async.wait_group 1;\n" ::: "memory");
        __syncthreads();
        const int st = kt & 1;
        uint32_t ks = sb + st * FSTAGE;
        uint32_t vh = ks + KS_BYTES;
        uint32_t vl = vh + VS_BYTES;

        // ---- S = Q'.K'^T
        float sacc[8][4];
#pragma unroll
        for (int t = 0; t < 8; t++)
#pragma unroll
            for (int r = 0; r < 4; r++) sacc[t][r] = 0.f;
#pragma unroll
        for (int ck = 0; ck < 12; ck++) {
            uint32_t bfr[4][4];
#pragma unroll
            for (int nj = 0; nj < 4; nj++) {
                uint32_t addr = ks + (nj * 16 + b_row_off) * KPITCH + ck * 32 + b_kch * 16;
                LDMATRIX_X4(bfr[nj][0], bfr[nj][1], bfr[nj][2], bfr[nj][3], addr);
            }
#pragma unroll
            for (int ni = 0; ni < 8; ni++)
                MMA_BF16(sacc[ni], qf[ck][0], qf[ck][1], qf[ck][2], qf[ck][3],
                         bfr[ni >> 1][(ni & 1) * 2 + 0], bfr[ni >> 1][(ni & 1) * 2 + 1]);
        }

        // ---- causal mask on diagonal tile
        if (kt == qt) {
            int rq0 = warp * 16 + gr;
            int rq1 = rq0 + 8;
#pragma unroll
            for (int t = 0; t < 8; t++) {
                int c0 = 8 * t + 2 * tc;
                if (c0 > rq0)     sacc[t][0] = -1e30f;
                if (c0 + 1 > rq0) sacc[t][1] = -1e30f;
                if (c0 > rq1)     sacc[t][2] = -1e30f;
                if (c0 + 1 > rq1) sacc[t][3] = -1e30f;
            }
        }

        // ---- online softmax
        float mx0 = -1e30f, mx1 = -1e30f;
#pragma unroll
        for (int t = 0; t < 8; t++) {
            mx0 = fmaxf(mx0, fmaxf(sacc[t][0], sacc[t][1]));
            mx1 = fmaxf(mx1, fmaxf(sacc[t][2], sacc[t][3]));
        }
        mx0 = fmaxf(mx0, __shfl_xor_sync(0xffffffffu, mx0, 1));
        mx0 = fmaxf(mx0, __shfl_xor_sync(0xffffffffu, mx0, 2));
        mx1 = fmaxf(mx1, __shfl_xor_sync(0xffffffffu, mx1, 1));
        mx1 = fmaxf(mx1, __shfl_xor_sync(0xffffffffu, mx1, 2));
        float mn0 = fmaxf(m0, mx0), mn1 = fmaxf(m1, mx1);
        float cr0 = fast_exp2(m0 - mn0), cr1 = fast_exp2(m1 - mn1);
        m0 = mn0; m1 = mn1;
        l0 *= cr0; l1 *= cr1;
#pragma unroll
        for (int t = 0; t < 8; t++) {
            oacc[t][0] *= cr0; oacc[t][1] *= cr0;
            oacc[t][2] *= cr1; oacc[t][3] *= cr1;
        }
        uint32_t phi[8][2], plo[8][2];
        float rs0 = 0.f, rs1 = 0.f;
#pragma unroll
        for (int t = 0; t < 8; t++) {
            float p0 = fast_exp2(sacc[t][0] - m0);
            float p1 = fast_exp2(sacc[t][1] - m0);
            float p2 = fast_exp2(sacc[t][2] - m1);
            float p3 = fast_exp2(sacc[t][3] - m1);
            rs0 += p0 + p1; rs1 += p2 + p3;
            uint32_t h01 = pack_bf16x2(p0, p1);
            uint32_t h23 = pack_bf16x2(p2, p3);
            phi[t][0] = h01; phi[t][1] = h23;
            plo[t][0] = pack_bf16x2(p0 - bf16lo_f(h01), p1 - bf16hi_f(h01));
            plo[t][1] = pack_bf16x2(p2 - bf16lo_f(h23), p3 - bf16hi_f(h23));
        }
        rs0 += __shfl_xor_sync(0xffffffffu, rs0, 1);
        rs0 += __shfl_xor_sync(0xffffffffu, rs0, 2);
        rs1 += __shfl_xor_sync(0xffffffffu, rs1, 1);
        rs1 += __shfl_xor_sync(0xffffffffu, rs1, 2);
        l0 += rs0; l1 += rs1;

        // ---- PV: O += Phi.Vhi + Plo.Vhi + Phi.Vlo
#pragma unroll
        for (int ck = 0; ck < 4; ck++) {
            uint32_t aph[4] = { phi[2 * ck][0], phi[2 * ck][1],
                                phi[2 * ck + 1][0], phi[2 * ck + 1][1] };
            uint32_t apl[4] = { plo[2 * ck][0], plo[2 * ck][1],
                                plo[2 * ck + 1][0], plo[2 * ck + 1][1] };
            uint32_t vhf[4][4], vlf[4][4];
#pragma unroll
            for (int dt = 0; dt < 4; dt++) {
                uint32_t ah = vh + (dt * 16 + b_row_off) * VPITCH + ck * 32 + b_kch * 16;
                uint32_t al = vl + (dt * 16 + b_row_off) * VPITCH + ck * 32 + b_kch * 16;
                LDMATRIX_X4(vhf[dt][0], vhf[dt][1], vhf[dt][2], vhf[dt][3], ah);
                LDMATRIX_X4(vlf[dt][0], vlf[dt][1], vlf[dt][2], vlf[dt][3], al);
            }
#pragma unroll
            for (int ni = 0; ni < 8; ni++) {
                uint32_t bh0 = vhf[ni >> 1][(ni & 1) * 2 + 0];
                uint32_t bh1 = vhf[ni >> 1][(ni & 1) * 2 + 1];
                uint32_t bl0 = vlf[ni >> 1][(ni & 1) * 2 + 0];
                uint32_t bl1 = vlf[ni >> 1][(ni & 1) * 2 + 1];
                MMA_BF16(oacc[ni], aph[0], aph[1], aph[2], aph[3], bh0, bh1);
                MMA_BF16(oacc[ni], apl[0], apl[1], apl[2], apl[3], bh0, bh1);
                MMA_BF16(oacc[ni], aph[0], aph[1], aph[2], aph[3], bl0, bl1);
            }
        }

        __syncthreads();
        if (kt + 2 <= qt) load_tile(kt + 2, st);
        asm volatile("cp.async.commit_group;\n" ::: "memory");
    }

    // ---- epilogue
    const float inv0 = 1.f / l0, inv1 = 1.f / l1;
    const int qr0 = q0 + warp * 16 + gr;
    const int qr1 = qr0 + 8;
#pragma unroll
    for (int t = 0; t < 8; t++) {
        int col = h * DHEAD + 8 * t + 2 * tc;
        *(float2*)&ctx[(size_t)(b * SEQ + qr0) * DMODEL + col] =
            make_float2(oacc[t][0] * inv0, oacc[t][1] * inv0);
        *(float2*)&ctx[(size_t)(b * SEQ + qr1) * DMODEL + col] =
            make_float2(oacc[t][2] * inv1, oacc[t][3] * inv1);
    }
}

// ---------------------------------------------------------------------------
extern "C" void kernel_launch(void* const* d_in, const int* in_sizes, int n_in,
                              void* d_out, int out_size)
{
    const float* x     = (const float*)d_in[0];
    const float* W_qkv = (const float*)d_in[1];
    const float* W_o   = (const float*)d_in[2];
    float* out = (float*)d_out;

    float *qkv, *ctx;
    __nv_bfloat16 *aP, *w1P, *w2P, *qp, *kp, *vthi, *vtlo;
    cudaGetSymbolAddress((void**)&qkv, g_qkv);
    cudaGetSymbolAddress((void**)&ctx, g_ctx);
    cudaGetSymbolAddress((void**)&aP, g_aP);
    cudaGetSymbolAddress((void**)&w1P, g_w1P);
    cudaGetSymbolAddress((void**)&w2P, g_w2P);
    cudaGetSymbolAddress((void**)&qp, g_qp);
    cudaGetSymbolAddress((void**)&kp, g_kp);
    cudaGetSymbolAddress((void**)&vthi, g_vthi);
    cudaGetSymbolAddress((void**)&vtlo, g_vtlo);

    cudaFuncSetAttribute(flash_mma_kernel,
                         cudaFuncAttributeMaxDynamicSharedMemorySize, FSMEM);

    // weight + activation conversions
    {
        dim3 g(QKV_COLS / 32, DMODEL / 32);
        conv_weight_kernel<<<g, dim3(32, 8)>>>(W_qkv, w1P, QKV_COLS);
    }
    {
        dim3 g(DMODEL / 32, DMODEL / 32);
        conv_weight_kernel<<<g, dim3(32, 8)>>>(W_o, w2P, DMODEL);
    }
    conv_act_kernel<<<(MROWS * DMODEL / 2) / 256, 256>>>(x, aP);

    // 1) qkv = x @ W_qkv
    {
        dim3 grid(QKV_COLS / 128, MROWS / 128);
        mma_gemm_kernel<<<grid, 256>>>(aP, w1P, qkv, QKV_COLS, K3);
    }
    // attention operand conversions
    qk_conv_kernel<<<(BATCH * NHEAD * SEQ * 16) / 256, 256>>>(qkv, qp, kp);
    {
        dim3 g(SEQ / 32, 2, BATCH * NHEAD);
        vt_conv_kernel<<<g, dim3(32, 8)>>>(qkv, vthi, vtlo);
    }
    // 2) flash attention (tensor)
    {
        dim3 grid(SEQ / 64, NHEAD, BATCH);
        flash_mma_kernel<<<grid, 128, FSMEM>>>(qp, kp, vthi, vtlo, ctx);
    }
    // 3) out = ctx @ W_o
    conv_act_kernel<<<(MROWS * DMODEL / 2) / 256, 256>>>(ctx, aP);
    {
        dim3 grid(DMODEL / 128, MROWS / 128);
        mma_gemm_kernel<<<grid, 256>>>(aP, w2P, out, DMODEL, K3);
    }
}

// round 5
// speedup vs baseline: 3.2314x; 1.1429x over previous
#include <cuda_runtime.h>
#include <cuda_bf16.h>
#include <math.h>
#include <stdint.h>

// Problem constants
#define BATCH 2
#define SEQ   2048
#define DMODEL 1024
#define NHEAD 16
#define DHEAD 64
#define MROWS (BATCH * SEQ)           // 4096
#define QKV_COLS (3 * DMODEL)         // 3072
#define K3 (3 * DMODEL)               // 3072 = interleaved K' for split-bf16
#define QSCALE 0.18033688f            // 0.125 * log2(e)

// ---------------------------------------------------------------------------
// Scratch (static device globals; allocations are forbidden)
// ---------------------------------------------------------------------------
__device__ float g_qkv[(size_t)MROWS * QKV_COLS];          // 50 MB
__device__ __nv_bfloat16 g_aP[(size_t)MROWS * K3];         // 25 MB
__device__ __nv_bfloat16 g_w1P[(size_t)QKV_COLS * K3];     // 19 MB
__device__ __nv_bfloat16 g_w2P[(size_t)DMODEL * K3];       // 6 MB
// Attention operands
__device__ __nv_bfloat16 g_qp[(size_t)BATCH * NHEAD * SEQ * 192];  // 25 MB
__device__ __nv_bfloat16 g_kp[(size_t)BATCH * NHEAD * SEQ * 192];  // 25 MB
__device__ __nv_bfloat16 g_vthi[(size_t)BATCH * NHEAD * DHEAD * SEQ]; // 8.4 MB
__device__ __nv_bfloat16 g_vtlo[(size_t)BATCH * NHEAD * DHEAD * SEQ]; // 8.4 MB

__device__ __forceinline__ uint32_t smem_u32(const void* p) {
    uint32_t a;
    asm("{ .reg .u64 t; cvta.to.shared.u64 t, %1; cvt.u32.u64 %0, t; }" : "=r"(a) : "l"(p));
    return a;
}
__device__ __forceinline__ float fast_exp2(float x) {
    float y; asm("ex2.approx.ftz.f32 %0, %1;" : "=f"(y) : "f"(x)); return y;
}
// pack: low half = lo, high half = hi
__device__ __forceinline__ uint32_t pack_bf16x2(float lo, float hi) {
    uint32_t r; asm("cvt.rn.bf16x2.f32 %0, %1, %2;" : "=r"(r) : "f"(hi), "f"(lo)); return r;
}
__device__ __forceinline__ float bf16lo_f(uint32_t u) { return __uint_as_float(u << 16); }
__device__ __forceinline__ float bf16hi_f(uint32_t u) { return __uint_as_float(u & 0xffff0000u); }

#define LDMATRIX_X4(r0, r1, r2, r3, addr) \
    asm volatile("ldmatrix.sync.aligned.m8n8.x4.shared.b16 {%0,%1,%2,%3}, [%4];" \
        : "=r"(r0), "=r"(r1), "=r"(r2), "=r"(r3) : "r"(addr))

#define MMA_BF16(acc, a0, a1, a2, a3, b0, b1) \
    asm volatile( \
        "mma.sync.aligned.m16n8k16.row.col.f32.bf16.bf16.f32 " \
        "{%0,%1,%2,%3}, {%4,%5,%6,%7}, {%8,%9}, {%0,%1,%2,%3};" \
        : "+f"((acc)[0]), "+f"((acc)[1]), "+f"((acc)[2]), "+f"((acc)[3]) \
        : "r"(a0), "r"(a1), "r"(a2), "r"(a3), "r"(b0), "r"(b1))

// ---------------------------------------------------------------------------
// Conversion: fp32 activations (M x 1024) -> split-interleaved bf16 (M x 3072)
// out[3k]=hi, out[3k+1]=lo, out[3k+2]=hi   (A-side pattern)
// ---------------------------------------------------------------------------
__global__ void conv_act_kernel(const float* __restrict__ in,
                                __nv_bfloat16* __restrict__ out)
{
    size_t j = (size_t)blockIdx.x * blockDim.x + threadIdx.x;
    float2 v = *(const float2*)(in + 2 * j);
    __nv_bfloat16 h0 = __float2bfloat16_rn(v.x);
    __nv_bfloat16 h1 = __float2bfloat16_rn(v.y);
    __nv_bfloat16 l0 = __float2bfloat16_rn(v.x - __bfloat162float(h0));
    __nv_bfloat16 l1 = __float2bfloat16_rn(v.y - __bfloat162float(h1));
    __nv_bfloat16* o = out + 6 * j;
    *(__nv_bfloat162*)(o + 0) = __nv_bfloat162(h0, l0);
    *(__nv_bfloat162*)(o + 2) = __nv_bfloat162(h0, h1);
    *(__nv_bfloat162*)(o + 4) = __nv_bfloat162(l1, h1);
}

// ---------------------------------------------------------------------------
// Conversion: W (K x N fp32, row-major) -> B' (N x 3K bf16): hi,hi,lo
// ---------------------------------------------------------------------------
__global__ void conv_weight_kernel(const float* __restrict__ W,
                                   __nv_bfloat16* __restrict__ out,
                                   int N)
{
    __shared__ float t[32][33];
    const int tid = threadIdx.y * 32 + threadIdx.x;
    const int tx = threadIdx.x, ty = threadIdx.y;
#pragma unroll
    for (int i = 0; i < 4; i++) {
        int k = blockIdx.y * 32 + ty + 8 * i;
        int n = blockIdx.x * 32 + tx;
        t[ty + 8 * i][tx] = W[(size_t)k * N + n];
    }
    __syncthreads();
    const int w = tid >> 5, l = tid & 31;
#pragma unroll
    for (int r = 0; r < 4; r++) {
        int nl = w * 4 + r;
        int n = blockIdx.x * 32 + nl;
        float v = t[l][nl];
        __nv_bfloat16 hi = __float2bfloat16_rn(v);
        __nv_bfloat16 lo = __float2bfloat16_rn(v - __bfloat162float(hi));
        __nv_bfloat16* o = out + (size_t)n * K3 + (size_t)(blockIdx.y * 32 + l) * 3;
        o[0] = hi; o[1] = hi; o[2] = lo;
    }
}

// ---------------------------------------------------------------------------
// Conversion: g_qkv -> Q' (scaled, split-interleaved A-pattern) and
//                     K' (split-interleaved B-pattern), layout [b,h,t,192].
// ---------------------------------------------------------------------------
__global__ void qk_conv_kernel(const float* __restrict__ qkv,
                               __nv_bfloat16* __restrict__ qp,
                               __nv_bfloat16* __restrict__ kp)
{
    uint32_t flat = blockIdx.x * blockDim.x + threadIdx.x;
    int dc = flat & 15;              // d-chunk (4 dims)
    int t = (flat >> 4) & (SEQ - 1);
    int h = (flat >> 15) & (NHEAD - 1);
    int b = flat >> 19;
    const float* src = qkv + ((size_t)(b * SEQ + t) * QKV_COLS) + h * DHEAD + dc * 4;
    float4 qv = *(const float4*)src;
    float4 kv = *(const float4*)(src + DMODEL);

    union { __nv_bfloat16 h[12]; uint2 u[3]; } oq, ok;
    float qs[4] = { qv.x * QSCALE, qv.y * QSCALE, qv.z * QSCALE, qv.w * QSCALE };
    float ks[4] = { kv.x, kv.y, kv.z, kv.w };
#pragma unroll
    for (int e = 0; e < 4; e++) {
        __nv_bfloat16 qh = __float2bfloat16_rn(qs[e]);
        __nv_bfloat16 ql = __float2bfloat16_rn(qs[e] - __bfloat162float(qh));
        oq.h[3 * e + 0] = qh; oq.h[3 * e + 1] = ql; oq.h[3 * e + 2] = qh;
        __nv_bfloat16 kh = __float2bfloat16_rn(ks[e]);
        __nv_bfloat16 kl = __float2bfloat16_rn(ks[e] - __bfloat162float(kh));
        ok.h[3 * e + 0] = kh; ok.h[3 * e + 1] = kh; ok.h[3 * e + 2] = kl;
    }
    size_t base = ((size_t)((b * NHEAD + h) * SEQ + t)) * 192 + dc * 12;
    uint2* qo = (uint2*)(qp + base);
    uint2* ko = (uint2*)(kp + base);
#pragma unroll
    for (int i = 0; i < 3; i++) { qo[i] = oq.u[i]; ko[i] = ok.u[i]; }
}

// ---------------------------------------------------------------------------
// Conversion: V (from g_qkv) -> transposed split Vt[b,h,d,t] hi/lo bf16.
// ---------------------------------------------------------------------------
__global__ void vt_conv_kernel(const float* __restrict__ qkv,
                               __nv_bfloat16* __restrict__ vthi,
                               __nv_bfloat16* __restrict__ vtlo)
{
    __shared__ float sm[32][33];
    const int tx = threadIdx.x, ty = threadIdx.y;
    const int t0 = blockIdx.x * 32;
    const int dblk = blockIdx.y;
    const int bh = blockIdx.z;
    const int b = bh >> 4, h = bh & 15;
#pragma unroll
    for (int i = 0; i < 4; i++) {
        int tl = ty + 8 * i;
        sm[tl][tx] = qkv[((size_t)(b * SEQ + t0 + tl)) * QKV_COLS +
                         2 * DMODEL + h * DHEAD + dblk * 32 + tx];
    }
    __syncthreads();
#pragma unroll
    for (int i = 0; i < 4; i++) {
        int dl = ty + 8 * i;
        float v = sm[tx][dl];
        __nv_bfloat16 hi = __float2bfloat16_rn(v);
        __nv_bfloat16 lo = __float2bfloat16_rn(v - __bfloat162float(hi));
        size_t o = ((size_t)(bh * DHEAD + dblk * 32 + dl)) * SEQ + t0 + tx;
        vthi[o] = hi;
        vtlo[o] = lo;
    }
}

// ---------------------------------------------------------------------------
// bf16 mma.sync GEMM: C[M x N] fp32 = A'[M x K'] * B'[N x K']^T
// CTA 128x128, 4 warps (warp tile 64x64), BK=32, 3-stage cp.async pipeline,
// one __syncthreads per K-iteration. Dynamic smem.
// ---------------------------------------------------------------------------
#define GBK 32
#define ROWB 80                      // padded row bytes (32 bf16 = 64B data)
#define STILE (128 * ROWB)           // 10240 B (one operand, one stage)
#define GSTAGE (2 * STILE)           // 20480 B (A+B, one stage)
#define GSMEM (3 * GSTAGE)           // 61440 B

__global__ void __launch_bounds__(128, 2) mma_gemm_kernel(
    const __nv_bfloat16* __restrict__ A, const __nv_bfloat16* __restrict__ B,
    float* __restrict__ C, int N, int K)
{
    extern __shared__ char gsm[];
    const int tid = threadIdx.x;
    const int warp = tid >> 5;
    const int lane = tid & 31;
    const int bm = blockIdx.y * 128;
    const int bn = blockIdx.x * 128;
    const int wm0 = (warp >> 1) * 64;
    const int wn0 = (warp & 1) * 64;
    const int ld_row = tid >> 2;         // 0..31 (+32*i)
    const int ld_ch = tid & 3;
    const int a_row_off = (lane & 7) + ((lane >> 3) & 1) * 8;
    const int a_kch = (lane >> 4);
    const int b_row_off = (lane & 7) + ((lane >> 4) & 1) * 8;
    const int b_kch = (lane >> 3) & 1;

    const uint32_t sbase = smem_u32(gsm);

    float acc[4][8][4];
#pragma unroll
    for (int mi = 0; mi < 4; mi++)
#pragma unroll
        for (int ni = 0; ni < 8; ni++)
#pragma unroll
            for (int r = 0; r < 4; r++) acc[mi][ni][r] = 0.f;

    const int NIT = K / GBK;

    auto load_stage = [&](int st, int k0) {
        uint32_t base = sbase + st * GSTAGE;
#pragma unroll
        for (int i = 0; i < 4; i++) {
            int row = ld_row + i * 32;
            uint32_t dA = base + row * ROWB + ld_ch * 16;
            uint32_t dB = dA + STILE;
            const __nv_bfloat16* pA = A + (size_t)(bm + row) * K + k0 + ld_ch * 8;
            const __nv_bfloat16* pB = B + (size_t)(bn + row) * K + k0 + ld_ch * 8;
            asm volatile("cp.async.cg.shared.global [%0], [%1], 16;\n" :: "r"(dA), "l"(pA) : "memory");
            asm volatile("cp.async.cg.shared.global [%0], [%1], 16;\n" :: "r"(dB), "l"(pB) : "memory");
        }
    };

    load_stage(0, 0);
    asm volatile("cp.async.commit_group;\n" ::: "memory");
    load_stage(1, GBK);
    asm volatile("cp.async.commit_group;\n" ::: "memory");

    int st = 0;
    for (int it = 0; it < NIT; it++) {
        asm volatile("cp.async.wait_group 1;\n" ::: "memory");
        __syncthreads();
        if (it + 2 < NIT) {
            int st2 = st + 2 >= 3 ? st - 1 : st + 2;
            load_stage(st2, (it + 2) * GBK);
        }
        asm volatile("cp.async.commit_group;\n" ::: "memory");

        uint32_t sA = sbase + st * GSTAGE;
        uint32_t sB = sA + STILE;
#pragma unroll
        for (int ks = 0; ks < 2; ks++) {
            uint32_t af[4][4];
#pragma unroll
            for (int mi = 0; mi < 4; mi++) {
                uint32_t addr = sA + (wm0 + mi * 16 + a_row_off) * ROWB +
                                (ks * 2 + a_kch) * 16;
                LDMATRIX_X4(af[mi][0], af[mi][1], af[mi][2], af[mi][3], addr);
            }
            uint32_t bfr[4][4];
#pragma unroll
            for (int nj = 0; nj < 4; nj++) {
                uint32_t addr = sB + (wn0 + nj * 16 + b_row_off) * ROWB +
                                (ks * 2 + b_kch) * 16;
                LDMATRIX_X4(bfr[nj][0], bfr[nj][1], bfr[nj][2], bfr[nj][3], addr);
            }
#pragma unroll
            for (int mi = 0; mi < 4; mi++)
#pragma unroll
                for (int ni = 0; ni < 8; ni++)
                    MMA_BF16(acc[mi][ni], af[mi][0], af[mi][1], af[mi][2], af[mi][3],
                             bfr[ni >> 1][(ni & 1) * 2 + 0], bfr[ni >> 1][(ni & 1) * 2 + 1]);
        }
        st = (st + 1 == 3) ? 0 : st + 1;
    }

    const int gr = lane >> 2;
    const int tc = (lane & 3) * 2;
#pragma unroll
    for (int mi = 0; mi < 4; mi++) {
#pragma unroll
        for (int ni = 0; ni < 8; ni++) {
            size_t r0 = (size_t)(bm + wm0 + mi * 16 + gr);
            int col = bn + wn0 + ni * 8 + tc;
            *(float2*)&C[r0 * N + col] = make_float2(acc[mi][ni][0], acc[mi][ni][1]);
            *(float2*)&C[(r0 + 8) * N + col] = make_float2(acc[mi][ni][2], acc[mi][ni][3]);
        }
    }
}

// ---------------------------------------------------------------------------
// Tensor-core flash attention (FA2), causal. Epilogue writes split-interleaved
// bf16 A-operand (hi,lo,hi) for the out-projection directly (no fp32 ctx pass).
// ---------------------------------------------------------------------------
#define KPITCH 400
#define VPITCH 144
#define KS_BYTES (64 * KPITCH)
#define VS_BYTES (64 * VPITCH)
#define FSTAGE (KS_BYTES + 2 * VS_BYTES)
#define FSMEM (2 * FSTAGE)

__global__ void __launch_bounds__(128, 2) flash_mma_kernel(
    const __nv_bfloat16* __restrict__ qp, const __nv_bfloat16* __restrict__ kp,
    const __nv_bfloat16* __restrict__ vthi, const __nv_bfloat16* __restrict__ vtlo,
    __nv_bfloat16* __restrict__ aP)
{
    extern __shared__ char fsm[];
    const int tid = threadIdx.x;
    const int warp = tid >> 5;
    const int lane = tid & 31;
    const int qt = gridDim.x - 1 - blockIdx.x;
    const int h = blockIdx.y;
    const int b = blockIdx.z;
    const int bh = b * NHEAD + h;
    const int q0 = qt * 64;

    const uint32_t sb = smem_u32(fsm);
    const int gr = lane >> 2;
    const int tc = lane & 3;
    const int a_row_off = (lane & 7) + ((lane >> 3) & 1) * 8;
    const int a_kch = lane >> 4;
    const int b_row_off = (lane & 7) + ((lane >> 4) & 1) * 8;
    const int b_kch = (lane >> 3) & 1;

    {
        const __nv_bfloat16* qsrc = qp + ((size_t)(bh * SEQ + q0)) * 192;
#pragma unroll
        for (int i = 0; i < 12; i++) {
            int c = i * 128 + tid;
            int row = c / 24, ch = c % 24;
            uint32_t dst = sb + row * KPITCH + ch * 16;
            const __nv_bfloat16* src = qsrc + (size_t)row * 192 + ch * 8;
            asm volatile("cp.async.cg.shared.global [%0], [%1], 16;\n" :: "r"(dst), "l"(src) : "memory");
        }
        asm volatile("cp.async.commit_group;\ncp.async.wait_group 0;\n" ::: "memory");
        __syncthreads();
    }
    uint32_t qf[12][4];
#pragma unroll
    for (int ck = 0; ck < 12; ck++) {
        uint32_t addr = sb + (warp * 16 + a_row_off) * KPITCH + ck * 32 + a_kch * 16;
        LDMATRIX_X4(qf[ck][0], qf[ck][1], qf[ck][2], qf[ck][3], addr);
    }
    __syncthreads();

    float oacc[8][4];
#pragma unroll
    for (int t = 0; t < 8; t++)
#pragma unroll
        for (int r = 0; r < 4; r++) oacc[t][r] = 0.f;
    float m0 = -1e30f, m1 = -1e30f, l0 = 0.f, l1 = 0.f;

    auto load_tile = [&](int kt, int st) {
        const int kt0 = kt * 64;
        uint32_t ks = sb + st * FSTAGE;
        uint32_t vh = ks + KS_BYTES;
        uint32_t vl = vh + VS_BYTES;
        const __nv_bfloat16* ksrc = kp + ((size_t)(bh * SEQ + kt0)) * 192;
#pragma unroll
        for (int i = 0; i < 12; i++) {
            int c = i * 128 + tid;
            int row = c / 24, ch = c % 24;
            uint32_t dst = ks + row * KPITCH + ch * 16;
            const __nv_bfloat16* src = ksrc + (size_t)row * 192 + ch * 8;
            asm volatile("cp.async.cg.shared.global [%0], [%1], 16;\n" :: "r"(dst), "l"(src) : "memory");
        }
#pragma unroll
        for (int i = 0; i < 4; i++) {
            int c = i * 128 + tid;
            int row = c >> 3, ch = c & 7;
            size_t so = ((size_t)(bh * DHEAD + row)) * SEQ + kt0 + ch * 8;
            uint32_t dsh = vh + row * VPITCH + ch * 16;
            uint32_t dsl = vl + row * VPITCH + ch * 16;
            asm volatile("cp.async.cg.shared.global [%0], [%1], 16;\n" :: "r"(dsh), "l"(vthi + so) : "memory");
            asm volatile("cp.async.cg.shared.global [%0], [%1], 16;\n" :: "r"(dsl), "l"(vtlo + so) : "memory");
        }
    };

    load_tile(0, 0);
    asm volatile("cp.async.commit_group;\n" ::: "memory");
    if (qt >= 1) load_tile(1, 1);
    asm volatile("cp.async.commit_group;\n" ::: "memory");

    for (int kt = 0; kt <= qt; kt++) {
        asm volatile("cp.async.wait_group 1;\n" ::: "memory");
        __syncthreads();
        const int st = kt & 1;
        uint32_t ks = sb + st * FSTAGE;
        uint32_t vh = ks + KS_BYTES;
        uint32_t vl = vh + VS_BYTES;

        float sacc[8][4];
#pragma unroll
        for (int t = 0; t < 8; t++)
#pragma unroll
            for (int r = 0; r < 4; r++) sacc[t][r] = 0.f;
#pragma unroll
        for (int ck = 0; ck < 12; ck++) {
            uint32_t bfr[4][4];
#pragma unroll
            for (int nj = 0; nj < 4; nj++) {
                uint32_t addr = ks + (nj * 16 + b_row_off) * KPITCH + ck * 32 + b_kch * 16;
                LDMATRIX_X4(bfr[nj][0], bfr[nj][1], bfr[nj][2], bfr[nj][3], addr);
            }
#pragma unroll
            for (int ni = 0; ni < 8; ni++)
                MMA_BF16(sacc[ni], qf[ck][0], qf[ck][1], qf[ck][2], qf[ck][3],
                         bfr[ni >> 1][(ni & 1) * 2 + 0], bfr[ni >> 1][(ni & 1) * 2 + 1]);
        }

        if (kt == qt) {
            int rq0 = warp * 16 + gr;
            int rq1 = rq0 + 8;
#pragma unroll
            for (int t = 0; t < 8; t++) {
                int c0 = 8 * t + 2 * tc;
                if (c0 > rq0)     sacc[t][0] = -1e30f;
                if (c0 + 1 > rq0) sacc[t][1] = -1e30f;
                if (c0 > rq1)     sacc[t][2] = -1e30f;
                if (c0 + 1 > rq1) sacc[t][3] = -1e30f;
            }
        }

        float mx0 = -1e30f, mx1 = -1e30f;
#pragma unroll
        for (int t = 0; t < 8; t++) {
            mx0 = fmaxf(mx0, fmaxf(sacc[t][0], sacc[t][1]));
            mx1 = fmaxf(mx1, fmaxf(sacc[t][2], sacc[t][3]));
        }
        mx0 = fmaxf(mx0, __shfl_xor_sync(0xffffffffu, mx0, 1));
        mx0 = fmaxf(mx0, __shfl_xor_sync(0xffffffffu, mx0, 2));
        mx1 = fmaxf(mx1, __shfl_xor_sync(0xffffffffu, mx1, 1));
        mx1 = fmaxf(mx1, __shfl_xor_sync(0xffffffffu, mx1, 2));
        float mn0 = fmaxf(m0, mx0), mn1 = fmaxf(m1, mx1);
        float cr0 = fast_exp2(m0 - mn0), cr1 = fast_exp2(m1 - mn1);
        m0 = mn0; m1 = mn1;
        l0 *= cr0; l1 *= cr1;
#pragma unroll
        for (int t = 0; t < 8; t++) {
            oacc[t][0] *= cr0; oacc[t][1] *= cr0;
            oacc[t][2] *= cr1; oacc[t][3] *= cr1;
        }
        uint32_t phi[8][2], plo[8][2];
        float rs0 = 0.f, rs1 = 0.f;
#pragma unroll
        for (int t = 0; t < 8; t++) {
            float p0 = fast_exp2(sacc[t][0] - m0);
            float p1 = fast_exp2(sacc[t][1] - m0);
            float p2 = fast_exp2(sacc[t][2] - m1);
            float p3 = fast_exp2(sacc[t][3] - m1);
            rs0 += p0 + p1; rs1 += p2 + p3;
            uint32_t h01 = pack_bf16x2(p0, p1);
            uint32_t h23 = pack_bf16x2(p2, p3);
            phi[t][0] = h01; phi[t][1] = h23;
            plo[t][0] = pack_bf16x2(p0 - bf16lo_f(h01), p1 - bf16hi_f(h01));
            plo[t][1] = pack_bf16x2(p2 - bf16lo_f(h23), p3 - bf16hi_f(h23));
        }
        rs0 += __shfl_xor_sync(0xffffffffu, rs0, 1);
        rs0 += __shfl_xor_sync(0xffffffffu, rs0, 2);
        rs1 += __shfl_xor_sync(0xffffffffu, rs1, 1);
        rs1 += __shfl_xor_sync(0xffffffffu, rs1, 2);
        l0 += rs0; l1 += rs1;

#pragma unroll
        for (int ck = 0; ck < 4; ck++) {
            uint32_t aph[4] = { phi[2 * ck][0], phi[2 * ck][1],
                                phi[2 * ck + 1][0], phi[2 * ck + 1][1] };
            uint32_t apl[4] = { plo[2 * ck][0], plo[2 * ck][1],
                                plo[2 * ck + 1][0], plo[2 * ck + 1][1] };
            uint32_t vhf[4][4], vlf[4][4];
#pragma unroll
            for (int dt = 0; dt < 4; dt++) {
                uint32_t ah = vh + (dt * 16 + b_row_off) * VPITCH + ck * 32 + b_kch * 16;
                uint32_t al = vl + (dt * 16 + b_row_off) * VPITCH + ck * 32 + b_kch * 16;
                LDMATRIX_X4(vhf[dt][0], vhf[dt][1], vhf[dt][2], vhf[dt][3], ah);
                LDMATRIX_X4(vlf[dt][0], vlf[dt][1], vlf[dt][2], vlf[dt][3], al);
            }
#pragma unroll
            for (int ni = 0; ni < 8; ni++) {
                uint32_t bh0 = vhf[ni >> 1][(ni & 1) * 2 + 0];
                uint32_t bh1 = vhf[ni >> 1][(ni & 1) * 2 + 1];
                uint32_t bl0 = vlf[ni >> 1][(ni & 1) * 2 + 0];
                uint32_t bl1 = vlf[ni >> 1][(ni & 1) * 2 + 1];
                MMA_BF16(oacc[ni], aph[0], aph[1], aph[2], aph[3], bh0, bh1);
                MMA_BF16(oacc[ni], apl[0], apl[1], apl[2], apl[3], bh0, bh1);
                MMA_BF16(oacc[ni], aph[0], aph[1], aph[2], aph[3], bl0, bl1);
            }
        }

        __syncthreads();
        if (kt + 2 <= qt) load_tile(kt + 2, st);
        asm volatile("cp.async.commit_group;\n" ::: "memory");
    }

    // ---- epilogue: write split-interleaved (hi,lo,hi) directly into aP
    const float inv0 = 1.f / l0, inv1 = 1.f / l1;
    const int qr0 = q0 + warp * 16 + gr;
    const int qr1 = qr0 + 8;
#pragma unroll
    for (int t = 0; t < 8; t++) {
        int col = h * DHEAD + 8 * t + 2 * tc;
        float c0 = oacc[t][0] * inv0, c1 = oacc[t][1] * inv0;
        float d0 = oacc[t][2] * inv1, d1 = oacc[t][3] * inv1;

        __nv_bfloat16 ch0 = __float2bfloat16_rn(c0);
        __nv_bfloat16 ch1 = __float2bfloat16_rn(c1);
        __nv_bfloat16 cl0 = __float2bfloat16_rn(c0 - __bfloat162float(ch0));
        __nv_bfloat16 cl1 = __float2bfloat16_rn(c1 - __bfloat162float(ch1));
        __nv_bfloat162* p0 = (__nv_bfloat162*)(aP + ((size_t)(b * SEQ + qr0)) * K3 + 3 * col);
        p0[0] = __nv_bfloat162(ch0, cl0);
        p0[1] = __nv_bfloat162(ch0, ch1);
        p0[2] = __nv_bfloat162(cl1, ch1);

        __nv_bfloat16 dh0 = __float2bfloat16_rn(d0);
        __nv_bfloat16 dh1 = __float2bfloat16_rn(d1);
        __nv_bfloat16 dl0 = __float2bfloat16_rn(d0 - __bfloat162float(dh0));
        __nv_bfloat16 dl1 = __float2bfloat16_rn(d1 - __bfloat162float(dh1));
        __nv_bfloat162* p1 = (__nv_bfloat162*)(aP + ((size_t)(b * SEQ + qr1)) * K3 + 3 * col);
        p1[0] = __nv_bfloat162(dh0, dl0);
        p1[1] = __nv_bfloat162(dh0, dh1);
        p1[2] = __nv_bfloat162(dl1, dh1);
    }
}

// ---------------------------------------------------------------------------
extern "C" void kernel_launch(void* const* d_in, const int* in_sizes, int n_in,
                              void* d_out, int out_size)
{
    const float* x     = (const float*)d_in[0];
    const float* W_qkv = (const float*)d_in[1];
    const float* W_o   = (const float*)d_in[2];
    float* out = (float*)d_out;

    float *qkv;
    __nv_bfloat16 *aP, *w1P, *w2P, *qp, *kp, *vthi, *vtlo;
    cudaGetSymbolAddress((void**)&qkv, g_qkv);
    cudaGetSymbolAddress((void**)&aP, g_aP);
    cudaGetSymbolAddress((void**)&w1P, g_w1P);
    cudaGetSymbolAddress((void**)&w2P, g_w2P);
    cudaGetSymbolAddress((void**)&qp, g_qp);
    cudaGetSymbolAddress((void**)&kp, g_kp);
    cudaGetSymbolAddress((void**)&vthi, g_vthi);
    cudaGetSymbolAddress((void**)&vtlo, g_vtlo);

    cudaFuncSetAttribute(flash_mma_kernel,
                         cudaFuncAttributeMaxDynamicSharedMemorySize, FSMEM);
    cudaFuncSetAttribute(mma_gemm_kernel,
                         cudaFuncAttributeMaxDynamicSharedMemorySize, GSMEM);

    // weight + activation conversions
    {
        dim3 g(QKV_COLS / 32, DMODEL / 32);
        conv_weight_kernel<<<g, dim3(32, 8)>>>(W_qkv, w1P, QKV_COLS);
    }
    {
        dim3 g(DMODEL / 32, DMODEL / 32);
        conv_weight_kernel<<<g, dim3(32, 8)>>>(W_o, w2P, DMODEL);
    }
    conv_act_kernel<<<(MROWS * DMODEL / 2) / 256, 256>>>(x, aP);

    // 1) qkv = x @ W_qkv
    {
        dim3 grid(QKV_COLS / 128, MROWS / 128);
        mma_gemm_kernel<<<grid, 128, GSMEM>>>(aP, w1P, qkv, QKV_COLS, K3);
    }
    // attention operand conversions
    qk_conv_kernel<<<(BATCH * NHEAD * SEQ * 16) / 256, 256>>>(qkv, qp, kp);
    {
        dim3 g(SEQ / 32, 2, BATCH * NHEAD);
        vt_conv_kernel<<<g, dim3(32, 8)>>>(qkv, vthi, vtlo);
    }
    // 2) flash attention (tensor); writes split-interleaved aP for out-proj
    {
        dim3 grid(SEQ / 64, NHEAD, BATCH);
        flash_mma_kernel<<<grid, 128, FSMEM>>>(qp, kp, vthi, vtlo, aP);
    }
    // 3) out = attn_out @ W_o
    {
        dim3 grid(DMODEL / 128, MROWS / 128);
        mma_gemm_kernel<<<grid, 128, GSMEM>>>(aP, w2P, out, DMODEL, K3);
    }
}

// round 6
// speedup vs baseline: 3.9987x; 1.2375x over previous
#include <cuda_runtime.h>
#include <cuda_bf16.h>
#include <cuda_fp16.h>
#include <math.h>
#include <stdint.h>

// Problem constants
#define BATCH 2
#define SEQ   2048
#define DMODEL 1024
#define NHEAD 16
#define DHEAD 64
#define MROWS (BATCH * SEQ)           // 4096
#define QKV_COLS (3 * DMODEL)         // 3072
#define K2 (2 * DMODEL)               // 2048 = interleaved K' for fp16 2-term
#define QSCALE 0.18033688f            // 0.125 * log2(e)

// ---------------------------------------------------------------------------
// Scratch (static device globals; allocations are forbidden)
// ---------------------------------------------------------------------------
__device__ float g_vf[(size_t)MROWS * DMODEL];             // 17 MB (V fp32)
__device__ __half g_aP[(size_t)MROWS * K2];                // 17 MB (A' for both GEMMs)
__device__ __half g_w1P[(size_t)QKV_COLS * K2];            // 12.6 MB
__device__ __half g_w2P[(size_t)DMODEL * K2];              // 4.2 MB
// Attention operands (bf16 3-term, unchanged)
__device__ __nv_bfloat16 g_qp[(size_t)BATCH * NHEAD * SEQ * 192];     // 25 MB
__device__ __nv_bfloat16 g_kp[(size_t)BATCH * NHEAD * SEQ * 192];     // 25 MB
__device__ __nv_bfloat16 g_vthi[(size_t)BATCH * NHEAD * DHEAD * SEQ]; // 8.4 MB
__device__ __nv_bfloat16 g_vtlo[(size_t)BATCH * NHEAD * DHEAD * SEQ]; // 8.4 MB

__device__ __forceinline__ uint32_t smem_u32(const void* p) {
    uint32_t a;
    asm("{ .reg .u64 t; cvta.to.shared.u64 t, %1; cvt.u32.u64 %0, t; }" : "=r"(a) : "l"(p));
    return a;
}
__device__ __forceinline__ float fast_exp2(float x) {
    float y; asm("ex2.approx.ftz.f32 %0, %1;" : "=f"(y) : "f"(x)); return y;
}
__device__ __forceinline__ uint32_t pack_bf16x2(float lo, float hi) {
    uint32_t r; asm("cvt.rn.bf16x2.f32 %0, %1, %2;" : "=r"(r) : "f"(hi), "f"(lo)); return r;
}
__device__ __forceinline__ float bf16lo_f(uint32_t u) { return __uint_as_float(u << 16); }
__device__ __forceinline__ float bf16hi_f(uint32_t u) { return __uint_as_float(u & 0xffff0000u); }

#define LDMATRIX_X4(r0, r1, r2, r3, addr) \
    asm volatile("ldmatrix.sync.aligned.m8n8.x4.shared.b16 {%0,%1,%2,%3}, [%4];" \
        : "=r"(r0), "=r"(r1), "=r"(r2), "=r"(r3) : "r"(addr))

#define MMA_BF16(acc, a0, a1, a2, a3, b0, b1) \
    asm volatile( \
        "mma.sync.aligned.m16n8k16.row.col.f32.bf16.bf16.f32 " \
        "{%0,%1,%2,%3}, {%4,%5,%6,%7}, {%8,%9}, {%0,%1,%2,%3};" \
        : "+f"((acc)[0]), "+f"((acc)[1]), "+f"((acc)[2]), "+f"((acc)[3]) \
        : "r"(a0), "r"(a1), "r"(a2), "r"(a3), "r"(b0), "r"(b1))

#define MMA_F16(acc, a0, a1, a2, a3, b0, b1) \
    asm volatile( \
        "mma.sync.aligned.m16n8k16.row.col.f32.f16.f16.f32 " \
        "{%0,%1,%2,%3}, {%4,%5,%6,%7}, {%8,%9}, {%0,%1,%2,%3};" \
        : "+f"((acc)[0]), "+f"((acc)[1]), "+f"((acc)[2]), "+f"((acc)[3]) \
        : "r"(a0), "r"(a1), "r"(a2), "r"(a3), "r"(b0), "r"(b1))

// ---------------------------------------------------------------------------
// Conversion: fp32 activations (M x 1024) -> fp16 (hi,lo) interleaved (M x 2048)
// ---------------------------------------------------------------------------
__global__ void conv_act_kernel(const float* __restrict__ in,
                                __half* __restrict__ out)
{
    size_t j = (size_t)blockIdx.x * blockDim.x + threadIdx.x;
    float2 v = *(const float2*)(in + 2 * j);
    __half h0 = __float2half_rn(v.x);
    __half h1 = __float2half_rn(v.y);
    __half l0 = __float2half_rn(v.x - __half2float(h0));
    __half l1 = __float2half_rn(v.y - __half2float(h1));
    __half2* o = (__half2*)(out + 4 * j);
    o[0] = __half2(h0, l0);
    o[1] = __half2(h1, l1);
}

// ---------------------------------------------------------------------------
// Conversion: W (K x N fp32, row-major) -> B' (N x 2K fp16): (hi, hi)
// ---------------------------------------------------------------------------
__global__ void conv_weight_kernel(const float* __restrict__ W,
                                   __half* __restrict__ out,
                                   int N)
{
    __shared__ float t[32][33];
    const int tid = threadIdx.y * 32 + threadIdx.x;
    const int tx = threadIdx.x, ty = threadIdx.y;
#pragma unroll
    for (int i = 0; i < 4; i++) {
        int k = blockIdx.y * 32 + ty + 8 * i;
        int n = blockIdx.x * 32 + tx;
        t[ty + 8 * i][tx] = W[(size_t)k * N + n];
    }
    __syncthreads();
    const int w = tid >> 5, l = tid & 31;
#pragma unroll
    for (int r = 0; r < 4; r++) {
        int nl = w * 4 + r;
        int n = blockIdx.x * 32 + nl;
        __half hi = __float2half_rn(t[l][nl]);
        __half2* o = (__half2*)(out + (size_t)n * K2 + (size_t)(blockIdx.y * 32 + l) * 2);
        o[0] = __half2(hi, hi);
    }
}

// ---------------------------------------------------------------------------
// Conversion: V (fp32 [b,t,1024]) -> transposed split Vt[b,h,d,t] hi/lo bf16.
// ---------------------------------------------------------------------------
__global__ void vt_conv_kernel(const float* __restrict__ vf,
                               __nv_bfloat16* __restrict__ vthi,
                               __nv_bfloat16* __restrict__ vtlo)
{
    __shared__ float sm[32][33];
    const int tx = threadIdx.x, ty = threadIdx.y;
    const int t0 = blockIdx.x * 32;
    const int dblk = blockIdx.y;
    const int bh = blockIdx.z;
    const int b = bh >> 4, h = bh & 15;
#pragma unroll
    for (int i = 0; i < 4; i++) {
        int tl = ty + 8 * i;
        sm[tl][tx] = vf[((size_t)(b * SEQ + t0 + tl)) * DMODEL +
                        h * DHEAD + dblk * 32 + tx];
    }
    __syncthreads();
#pragma unroll
    for (int i = 0; i < 4; i++) {
        int dl = ty + 8 * i;
        float v = sm[tx][dl];
        __nv_bfloat16 hi = __float2bfloat16_rn(v);
        __nv_bfloat16 lo = __float2bfloat16_rn(v - __bfloat162float(hi));
        size_t o = ((size_t)(bh * DHEAD + dblk * 32 + dl)) * SEQ + t0 + tx;
        vthi[o] = hi;
        vtlo[o] = lo;
    }
}

// ---------------------------------------------------------------------------
// GEMM mainloop shared pieces (fp16 2-term, CTA 128x128, 4 warps 64x64,
// BK=32, 4-stage cp.async, one sync per iter).
// ---------------------------------------------------------------------------
#define GBK 32
#define ROWB 80                      // padded row bytes (32 fp16 = 64B data)
#define STILE (128 * ROWB)           // 10240 B
#define GSTAGE (2 * STILE)           // 20480 B
#define GSMEM (4 * GSTAGE)           // 81920 B

#define GEMM_PROLOGUE_AND_LOOP(EXTRA_EPILOGUE_UNUSED)                          \
    const int tid = threadIdx.x;                                               \
    const int warp = tid >> 5;                                                 \
    const int lane = tid & 31;                                                 \
    const int bm = blockIdx.y * 128;                                           \
    const int bn = blockIdx.x * 128;                                           \
    const int wm0 = (warp >> 1) * 64;                                          \
    const int wn0 = (warp & 1) * 64;                                           \
    const int ld_row = tid >> 2;                                               \
    const int ld_ch = tid & 3;                                                 \
    const int a_row_off = (lane & 7) + ((lane >> 3) & 1) * 8;                  \
    const int a_kch = (lane >> 4);                                             \
    const int b_row_off = (lane & 7) + ((lane >> 4) & 1) * 8;                  \
    const int b_kch = (lane >> 3) & 1;                                         \
    const uint32_t sbase = smem_u32(gsm);                                      \
    float acc[4][8][4];                                                        \
    _Pragma("unroll")                                                          \
    for (int mi = 0; mi < 4; mi++)                                             \
        _Pragma("unroll")                                                      \
        for (int ni = 0; ni < 8; ni++)                                         \
            _Pragma("unroll")                                                  \
            for (int r = 0; r < 4; r++) acc[mi][ni][r] = 0.f;                  \
    const int NIT = K / GBK;                                                   \
    auto load_stage = [&](int st, int k0) {                                    \
        uint32_t base = sbase + st * GSTAGE;                                   \
        _Pragma("unroll")                                                      \
        for (int i = 0; i < 4; i++) {                                          \
            int row = ld_row + i * 32;                                         \
            uint32_t dA = base + row * ROWB + ld_ch * 16;                      \
            uint32_t dB = dA + STILE;                                          \
            const __half* pA = A + (size_t)(bm + row) * K + k0 + ld_ch * 8;    \
            const __half* pB = B + (size_t)(bn + row) * K + k0 + ld_ch * 8;    \
            asm volatile("cp.async.cg.shared.global [%0], [%1], 16;\n" :: "r"(dA), "l"(pA) : "memory"); \
            asm volatile("cp.async.cg.shared.global [%0], [%1], 16;\n" :: "r"(dB), "l"(pB) : "memory"); \
        }                                                                      \
    };                                                                         \
    load_stage(0, 0);                                                          \
    asm volatile("cp.async.commit_group;\n" ::: "memory");                     \
    load_stage(1, GBK);                                                        \
    asm volatile("cp.async.commit_group;\n" ::: "memory");                     \
    load_stage(2, 2 * GBK);                                                    \
    asm volatile("cp.async.commit_group;\n" ::: "memory");                     \
    int st = 0;                                                                \
    for (int it = 0; it < NIT; it++) {                                         \
        asm volatile("cp.async.wait_group 2;\n" ::: "memory");                 \
        __syncthreads();                                                       \
        if (it + 3 < NIT) load_stage((st + 3) & 3, (it + 3) * GBK);            \
        asm volatile("cp.async.commit_group;\n" ::: "memory");                 \
        uint32_t sA = sbase + st * GSTAGE;                                     \
        uint32_t sB = sA + STILE;                                              \
        _Pragma("unroll")                                                      \
        for (int ks = 0; ks < 2; ks++) {                                       \
            uint32_t af[4][4];                                                 \
            _Pragma("unroll")                                                  \
            for (int mi = 0; mi < 4; mi++) {                                   \
                uint32_t addr = sA + (wm0 + mi * 16 + a_row_off) * ROWB +      \
                                (ks * 2 + a_kch) * 16;                         \
                LDMATRIX_X4(af[mi][0], af[mi][1], af[mi][2], af[mi][3], addr); \
            }                                                                  \
            uint32_t bfr[4][4];                                                \
            _Pragma("unroll")                                                  \
            for (int nj = 0; nj < 4; nj++) {                                   \
                uint32_t addr = sB + (wn0 + nj * 16 + b_row_off) * ROWB +      \
                                (ks * 2 + b_kch) * 16;                         \
                LDMATRIX_X4(bfr[nj][0], bfr[nj][1], bfr[nj][2], bfr[nj][3], addr); \
            }                                                                  \
            _Pragma("unroll")                                                  \
            for (int mi = 0; mi < 4; mi++)                                     \
                _Pragma("unroll")                                              \
                for (int ni = 0; ni < 8; ni++)                                 \
                    MMA_F16(acc[mi][ni], af[mi][0], af[mi][1], af[mi][2], af[mi][3], \
                            bfr[ni >> 1][(ni & 1) * 2 + 0], bfr[ni >> 1][(ni & 1) * 2 + 1]); \
        }                                                                      \
        st = (st + 1) & 3;                                                     \
    }

// ---------------------------------------------------------------------------
// GEMM #2 (out-projection): plain fp32 epilogue.
// ---------------------------------------------------------------------------
__global__ void __launch_bounds__(128, 2) mma_gemm_kernel(
    const __half* __restrict__ A, const __half* __restrict__ B,
    float* __restrict__ C, int N, int K)
{
    extern __shared__ char gsm[];
    GEMM_PROLOGUE_AND_LOOP(0)

    const int gr = lane >> 2;
    const int tc = (lane & 3) * 2;
#pragma unroll
    for (int mi = 0; mi < 4; mi++) {
#pragma unroll
        for (int ni = 0; ni < 8; ni++) {
            size_t r0 = (size_t)(bm + wm0 + mi * 16 + gr);
            int col = bn + wn0 + ni * 8 + tc;
            *(float2*)&C[r0 * N + col] = make_float2(acc[mi][ni][0], acc[mi][ni][1]);
            *(float2*)&C[(r0 + 8) * N + col] = make_float2(acc[mi][ni][2], acc[mi][ni][3]);
        }
    }
}

// ---------------------------------------------------------------------------
// GEMM #1 (QKV): fused epilogue writes Q'/K' bf16 split layouts + V fp32.
// Section per CTA: bn in [0,1024) -> Q, [1024,2048) -> K, [2048,3072) -> V.
// ---------------------------------------------------------------------------
__global__ void __launch_bounds__(128, 2) mma_gemm_qkv_kernel(
    const __half* __restrict__ A, const __half* __restrict__ B,
    __nv_bfloat16* __restrict__ qp, __nv_bfloat16* __restrict__ kp,
    float* __restrict__ vf, int N, int K)
{
    extern __shared__ char gsm[];
    GEMM_PROLOGUE_AND_LOOP(0)

    const int gr = lane >> 2;
    const int tc = (lane & 3) * 2;
    const int sec = bn >> 10;                 // 0=Q, 1=K, 2=V
    const int colbase = (bn & 1023) + wn0;

#pragma unroll
    for (int mi = 0; mi < 4; mi++) {
#pragma unroll
        for (int rr = 0; rr < 2; rr++) {
            const int row = bm + wm0 + mi * 16 + gr + rr * 8;
            const int b = row >> 11;
            const int t = row & (SEQ - 1);
#pragma unroll
            for (int ni = 0; ni < 8; ni++) {
                const int col = colbase + ni * 8 + tc;    // within section
                float v0 = acc[mi][ni][rr * 2 + 0];
                float v1 = acc[mi][ni][rr * 2 + 1];
                if (sec == 2) {
                    *(float2*)&vf[(size_t)(b * SEQ + t) * DMODEL + col] =
                        make_float2(v0, v1);
                } else {
                    const int h = col >> 6;
                    const int d = col & 63;
                    size_t base = ((size_t)((b * NHEAD + h) * SEQ + t)) * 192 + d * 3;
                    if (sec == 0) {
                        v0 *= QSCALE; v1 *= QSCALE;
                        __nv_bfloat16 h0 = __float2bfloat16_rn(v0);
                        __nv_bfloat16 h1 = __float2bfloat16_rn(v1);
                        __nv_bfloat16 l0 = __float2bfloat16_rn(v0 - __bfloat162float(h0));
                        __nv_bfloat16 l1 = __float2bfloat16_rn(v1 - __bfloat162float(h1));
                        __nv_bfloat162* p = (__nv_bfloat162*)(qp + base);
                        p[0] = __nv_bfloat162(h0, l0);     // (hi,lo,hi) per element
                        p[1] = __nv_bfloat162(h0, h1);
                        p[2] = __nv_bfloat162(l1, h1);
                    } else {
                        __nv_bfloat16 h0 = __float2bfloat16_rn(v0);
                        __nv_bfloat16 h1 = __float2bfloat16_rn(v1);
                        __nv_bfloat16 l0 = __float2bfloat16_rn(v0 - __bfloat162float(h0));
                        __nv_bfloat16 l1 = __float2bfloat16_rn(v1 - __bfloat162float(h1));
                        __nv_bfloat162* p = (__nv_bfloat162*)(kp + base);
                        p[0] = __nv_bfloat162(h0, h0);     // (hi,hi,lo) per element
                        p[1] = __nv_bfloat162(l0, h1);
                        p[2] = __nv_bfloat162(h1, l1);
                    }
                }
            }
        }
    }
}

// ---------------------------------------------------------------------------
// Tensor-core flash attention (FA2), causal. bf16 3-term QK and PV.
// Epilogue writes fp16 (hi,lo) K2-layout A-operand for the out-projection.
// ---------------------------------------------------------------------------
#define KPITCH 400
#define VPITCH 144
#define KS_BYTES (64 * KPITCH)
#define VS_BYTES (64 * VPITCH)
#define FSTAGE (KS_BYTES + 2 * VS_BYTES)
#define FSMEM (2 * FSTAGE)

__global__ void __launch_bounds__(128, 2) flash_mma_kernel(
    const __nv_bfloat16* __restrict__ qp, const __nv_bfloat16* __restrict__ kp,
    const __nv_bfloat16* __restrict__ vthi, const __nv_bfloat16* __restrict__ vtlo,
    __half* __restrict__ aP)
{
    extern __shared__ char fsm[];
    const int tid = threadIdx.x;
    const int warp = tid >> 5;
    const int lane = tid & 31;
    const int qt = gridDim.x - 1 - blockIdx.x;
    const int h = blockIdx.y;
    const int b = blockIdx.z;
    const int bh = b * NHEAD + h;
    const int q0 = qt * 64;

    const uint32_t sb = smem_u32(fsm);
    const int gr = lane >> 2;
    const int tc = lane & 3;
    const int a_row_off = (lane & 7) + ((lane >> 3) & 1) * 8;
    const int a_kch = lane >> 4;
    const int b_row_off = (lane & 7) + ((lane >> 4) & 1) * 8;
    const int b_kch = (lane >> 3) & 1;

    {
        const __nv_bfloat16* qsrc = qp + ((size_t)(bh * SEQ + q0)) * 192;
#pragma unroll
        for (int i = 0; i < 12; i++) {
            int c = i * 128 + tid;
            int row = c / 24, ch = c % 24;
            uint32_t dst = sb + row * KPITCH + ch * 16;
            const __nv_bfloat16* src = qsrc + (size_t)row * 192 + ch * 8;
            asm volatile("cp.async.cg.shared.global [%0], [%1], 16;\n" :: "r"(dst), "l"(src) : "memory");
        }
        asm volatile("cp.async.commit_group;\ncp.async.wait_group 0;\n" ::: "memory");
        __syncthreads();
    }
    uint32_t qf[12][4];
#pragma unroll
    for (int ck = 0; ck < 12; ck++) {
        uint32_t addr = sb + (warp * 16 + a_row_off) * KPITCH + ck * 32 + a_kch * 16;
        LDMATRIX_X4(qf[ck][0], qf[ck][1], qf[ck][2], qf[ck][3], addr);
    }
    __syncthreads();

    float oacc[8][4];
#pragma unroll
    for (int t = 0; t < 8; t++)
#pragma unroll
        for (int r = 0; r < 4; r++) oacc[t][r] = 0.f;
    float m0 = -1e30f, m1 = -1e30f, l0 = 0.f, l1 = 0.f;

    auto load_tile = [&](int kt, int st) {
        const int kt0 = kt * 64;
        uint32_t ks = sb + st * FSTAGE;
        uint32_t vh = ks + KS_BYTES;
        uint32_t vl = vh + VS_BYTES;
        const __nv_bfloat16* ksrc = kp + ((size_t)(bh * SEQ + kt0)) * 192;
#pragma unroll
        for (int i = 0; i < 12; i++) {
            int c = i * 128 + tid;
            int row = c / 24, ch = c % 24;
            uint32_t dst = ks + row * KPITCH + ch * 16;
            const __nv_bfloat16* src = ksrc + (size_t)row * 192 + ch * 8;
            asm volatile("cp.async.cg.shared.global [%0], [%1], 16;\n" :: "r"(dst), "l"(src) : "memory");
        }
#pragma unroll
        for (int i = 0; i < 4; i++) {
            int c = i * 128 + tid;
            int row = c >> 3, ch = c & 7;
            size_t so = ((size_t)(bh * DHEAD + row)) * SEQ + kt0 + ch * 8;
            uint32_t dsh = vh + row * VPITCH + ch * 16;
            uint32_t dsl = vl + row * VPITCH + ch * 16;
            asm volatile("cp.async.cg.shared.global [%0], [%1], 16;\n" :: "r"(dsh), "l"(vthi + so) : "memory");
            asm volatile("cp.async.cg.shared.global [%0], [%1], 16;\n" :: "r"(dsl), "l"(vtlo + so) : "memory");
        }
    };

    load_tile(0, 0);
    asm volatile("cp.async.commit_group;\n" ::: "memory");
    if (qt >= 1) load_tile(1, 1);
    asm volatile("cp.async.commit_group;\n" ::: "memory");

    for (int kt = 0; kt <= qt; kt++) {
        asm volatile("cp.async.wait_group 1;\n" ::: "memory");
        __syncthreads();
        const int st = kt & 1;
        uint32_t ks = sb + st * FSTAGE;
        uint32_t vh = ks + KS_BYTES;
        uint32_t vl = vh + VS_BYTES;

        float sacc[8][4];
#pragma unroll
        for (int t = 0; t < 8; t++)
#pragma unroll
            for (int r = 0; r < 4; r++) sacc[t][r] = 0.f;
#pragma unroll
        for (int ck = 0; ck < 12; ck++) {
            uint32_t bfr[4][4];
#pragma unroll
            for (int nj = 0; nj < 4; nj++) {
                uint32_t addr = ks + (nj * 16 + b_row_off) * KPITCH + ck * 32 + b_kch * 16;
                LDMATRIX_X4(bfr[nj][0], bfr[nj][1], bfr[nj][2], bfr[nj][3], addr);
            }
#pragma unroll
            for (int ni = 0; ni < 8; ni++)
                MMA_BF16(sacc[ni], qf[ck][0], qf[ck][1], qf[ck][2], qf[ck][3],
                         bfr[ni >> 1][(ni & 1) * 2 + 0], bfr[ni >> 1][(ni & 1) * 2 + 1]);
        }

        if (kt == qt) {
            int rq0 = warp * 16 + gr;
            int rq1 = rq0 + 8;
#pragma unroll
            for (int t = 0; t < 8; t++) {
                int c0 = 8 * t + 2 * tc;
                if (c0 > rq0)     sacc[t][0] = -1e30f;
                if (c0 + 1 > rq0) sacc[t][1] = -1e30f;
                if (c0 > rq1)     sacc[t][2] = -1e30f;
                if (c0 + 1 > rq1) sacc[t][3] = -1e30f;
            }
        }

        float mx0 = -1e30f, mx1 = -1e30f;
#pragma unroll
        for (int t = 0; t < 8; t++) {
            mx0 = fmaxf(mx0, fmaxf(sacc[t][0], sacc[t][1]));
            mx1 = fmaxf(mx1, fmaxf(sacc[t][2], sacc[t][3]));
        }
        mx0 = fmaxf(mx0, __shfl_xor_sync(0xffffffffu, mx0, 1));
        mx0 = fmaxf(mx0, __shfl_xor_sync(0xffffffffu, mx0, 2));
        mx1 = fmaxf(mx1, __shfl_xor_sync(0xffffffffu, mx1, 1));
        mx1 = fmaxf(mx1, __shfl_xor_sync(0xffffffffu, mx1, 2));
        float mn0 = fmaxf(m0, mx0), mn1 = fmaxf(m1, mx1);
        float cr0 = fast_exp2(m0 - mn0), cr1 = fast_exp2(m1 - mn1);
        m0 = mn0; m1 = mn1;
        l0 *= cr0; l1 *= cr1;
#pragma unroll
        for (int t = 0; t < 8; t++) {
            oacc[t][0] *= cr0; oacc[t][1] *= cr0;
            oacc[t][2] *= cr1; oacc[t][3] *= cr1;
        }
        uint32_t phi[8][2], plo[8][2];
        float rs0 = 0.f, rs1 = 0.f;
#pragma unroll
        for (int t = 0; t < 8; t++) {
            float p0 = fast_exp2(sacc[t][0] - m0);
            float p1 = fast_exp2(sacc[t][1] - m0);
            float p2 = fast_exp2(sacc[t][2] - m1);
            float p3 = fast_exp2(sacc[t][3] - m1);
            rs0 += p0 + p1; rs1 += p2 + p3;
            uint32_t h01 = pack_bf16x2(p0, p1);
            uint32_t h23 = pack_bf16x2(p2, p3);
            phi[t][0] = h01; phi[t][1] = h23;
            plo[t][0] = pack_bf16x2(p0 - bf16lo_f(h01), p1 - bf16hi_f(h01));
            plo[t][1] = pack_bf16x2(p2 - bf16lo_f(h23), p3 - bf16hi_f(h23));
        }
        rs0 += __shfl_xor_sync(0xffffffffu, rs0, 1);
        rs0 += __shfl_xor_sync(0xffffffffu, rs0, 2);
        rs1 += __shfl_xor_sync(0xffffffffu, rs1, 1);
        rs1 += __shfl_xor_sync(0xffffffffu, rs1, 2);
        l0 += rs0; l1 += rs1;

#pragma unroll
        for (int ck = 0; ck < 4; ck++) {
            uint32_t aph[4] = { phi[2 * ck][0], phi[2 * ck][1],
                                phi[2 * ck + 1][0], phi[2 * ck + 1][1] };
            uint32_t apl[4] = { plo[2 * ck][0], plo[2 * ck][1],
                                plo[2 * ck + 1][0], plo[2 * ck + 1][1] };
            uint32_t vhf[4][4], vlf[4][4];
#pragma unroll
            for (int dt = 0; dt < 4; dt++) {
                uint32_t ah = vh + (dt * 16 + b_row_off) * VPITCH + ck * 32 + b_kch * 16;
                uint32_t al = vl + (dt * 16 + b_row_off) * VPITCH + ck * 32 + b_kch * 16;
                LDMATRIX_X4(vhf[dt][0], vhf[dt][1], vhf[dt][2], vhf[dt][3], ah);
                LDMATRIX_X4(vlf[dt][0], vlf[dt][1], vlf[dt][2], vlf[dt][3], al);
            }
#pragma unroll
            for (int ni = 0; ni < 8; ni++) {
                uint32_t bh0 = vhf[ni >> 1][(ni & 1) * 2 + 0];
                uint32_t bh1 = vhf[ni >> 1][(ni & 1) * 2 + 1];
                uint32_t bl0 = vlf[ni >> 1][(ni & 1) * 2 + 0];
                uint32_t bl1 = vlf[ni >> 1][(ni & 1) * 2 + 1];
                MMA_BF16(oacc[ni], aph[0], aph[1], aph[2], aph[3], bh0, bh1);
                MMA_BF16(oacc[ni], apl[0], apl[1], apl[2], apl[3], bh0, bh1);
                MMA_BF16(oacc[ni], aph[0], aph[1], aph[2], aph[3], bl0, bl1);
            }
        }

        __syncthreads();
        if (kt + 2 <= qt) load_tile(kt + 2, st);
        asm volatile("cp.async.commit_group;\n" ::: "memory");
    }

    // ---- epilogue: write fp16 (hi,lo) interleaved directly into aP (K2 layout)
    const float inv0 = 1.f / l0, inv1 = 1.f / l1;
    const int qr0 = q0 + warp * 16 + gr;
    const int qr1 = qr0 + 8;
#pragma unroll
    for (int t = 0; t < 8; t++) {
        int col = h * DHEAD + 8 * t + 2 * tc;
        float c0 = oacc[t][0] * inv0, c1 = oacc[t][1] * inv0;
        float d0 = oacc[t][2] * inv1, d1 = oacc[t][3] * inv1;

        __half ch0 = __float2half_rn(c0);
        __half ch1 = __float2half_rn(c1);
        __half cl0 = __float2half_rn(c0 - __half2float(ch0));
        __half cl1 = __float2half_rn(c1 - __half2float(ch1));
        __half2* p0 = (__half2*)(aP + ((size_t)(b * SEQ + qr0)) * K2 + 2 * col);
        p0[0] = __half2(ch0, cl0);
        p0[1] = __half2(ch1, cl1);

        __half dh0 = __float2half_rn(d0);
        __half dh1 = __float2half_rn(d1);
        __half dl0 = __float2half_rn(d0 - __half2float(dh0));
        __half dl1 = __float2half_rn(d1 - __half2float(dh1));
        __half2* p1 = (__half2*)(aP + ((size_t)(b * SEQ + qr1)) * K2 + 2 * col);
        p1[0] = __half2(dh0, dl0);
        p1[1] = __half2(dh1, dl1);
    }
}

// ---------------------------------------------------------------------------
extern "C" void kernel_launch(void* const* d_in, const int* in_sizes, int n_in,
                              void* d_out, int out_size)
{
    const float* x     = (const float*)d_in[0];
    const float* W_qkv = (const float*)d_in[1];
    const float* W_o   = (const float*)d_in[2];
    float* out = (float*)d_out;

    float *vf;
    __half *aP, *w1P, *w2P;
    __nv_bfloat16 *qp, *kp, *vthi, *vtlo;
    cudaGetSymbolAddress((void**)&vf, g_vf);
    cudaGetSymbolAddress((void**)&aP, g_aP);
    cudaGetSymbolAddress((void**)&w1P, g_w1P);
    cudaGetSymbolAddress((void**)&w2P, g_w2P);
    cudaGetSymbolAddress((void**)&qp, g_qp);
    cudaGetSymbolAddress((void**)&kp, g_kp);
    cudaGetSymbolAddress((void**)&vthi, g_vthi);
    cudaGetSymbolAddress((void**)&vtlo, g_vtlo);

    cudaFuncSetAttribute(flash_mma_kernel,
                         cudaFuncAttributeMaxDynamicSharedMemorySize, FSMEM);
    cudaFuncSetAttribute(mma_gemm_kernel,
                         cudaFuncAttributeMaxDynamicSharedMemorySize, GSMEM);
    cudaFuncSetAttribute(mma_gemm_qkv_kernel,
                         cudaFuncAttributeMaxDynamicSharedMemorySize, GSMEM);

    // conversions
    {
        dim3 g(QKV_COLS / 32, DMODEL / 32);
        conv_weight_kernel<<<g, dim3(32, 8)>>>(W_qkv, w1P, QKV_COLS);
    }
    {
        dim3 g(DMODEL / 32, DMODEL / 32);
        conv_weight_kernel<<<g, dim3(32, 8)>>>(W_o, w2P, DMODEL);
    }
    conv_act_kernel<<<(MROWS * DMODEL / 2) / 256, 256>>>(x, aP);

    // 1) QKV GEMM with fused Q'/K'/V epilogue
    {
        dim3 grid(QKV_COLS / 128, MROWS / 128);
        mma_gemm_qkv_kernel<<<grid, 128, GSMEM>>>(aP, w1P, qp, kp, vf,
                                                  QKV_COLS, K2);
    }
    // V transpose/split
    {
        dim3 g(SEQ / 32, 2, BATCH * NHEAD);
        vt_conv_kernel<<<g, dim3(32, 8)>>>(vf, vthi, vtlo);
    }
    // 2) flash attention (writes fp16 aP for out-proj)
    {
        dim3 grid(SEQ / 64, NHEAD, BATCH);
        flash_mma_kernel<<<grid, 128, FSMEM>>>(qp, kp, vthi, vtlo, aP);
    }
    // 3) out = attn_out @ W_o
    {
        dim3 grid(DMODEL / 128, MROWS / 128);
        mma_gemm_kernel<<<grid, 128, GSMEM>>>(aP, w2P, out, DMODEL, K2);
    }
}

// round 7
// speedup vs baseline: 4.4435x; 1.1112x over previous
#include <cuda_runtime.h>
#include <cuda_bf16.h>
#include <cuda_fp16.h>
#include <math.h>
#include <stdint.h>

// Problem constants
#define BATCH 2
#define SEQ   2048
#define DMODEL 1024
#define NHEAD 16
#define DHEAD 64
#define MROWS (BATCH * SEQ)           // 4096
#define QKV_COLS (3 * DMODEL)         // 3072
#define K2 (2 * DMODEL)               // 2048 = interleaved K' for fp16 2-term
#define QSCALE 0.18033688f            // 0.125 * log2(e)

// ---------------------------------------------------------------------------
// Scratch (static device globals; allocations are forbidden)
// ---------------------------------------------------------------------------
__device__ float g_vf[(size_t)MROWS * DMODEL];             // 17 MB (V fp32)
__device__ __half g_aP[(size_t)MROWS * K2];                // 17 MB (A' for both GEMMs)
__device__ __half g_w1P[(size_t)QKV_COLS * K2];            // 12.6 MB
__device__ __half g_w2P[(size_t)DMODEL * K2];              // 4.2 MB
// Attention operands (fp16 2-term)
__device__ __half g_qp[(size_t)BATCH * NHEAD * SEQ * 128];     // 16.8 MB
__device__ __half g_kp[(size_t)BATCH * NHEAD * SEQ * 128];     // 16.8 MB
__device__ __half g_vthi[(size_t)BATCH * NHEAD * DHEAD * SEQ]; // 8.4 MB
__device__ __half g_vtlo[(size_t)BATCH * NHEAD * DHEAD * SEQ]; // 8.4 MB

__device__ __forceinline__ uint32_t smem_u32(const void* p) {
    uint32_t a;
    asm("{ .reg .u64 t; cvta.to.shared.u64 t, %1; cvt.u32.u64 %0, t; }" : "=r"(a) : "l"(p));
    return a;
}
__device__ __forceinline__ float fast_exp2(float x) {
    float y; asm("ex2.approx.ftz.f32 %0, %1;" : "=f"(y) : "f"(x)); return y;
}
// pack fp16x2: low half = lo, high half = hi
__device__ __forceinline__ uint32_t pack_f16x2(float lo, float hi) {
    uint32_t r; asm("cvt.rn.f16x2.f32 %0, %1, %2;" : "=r"(r) : "f"(hi), "f"(lo)); return r;
}

#define LDMATRIX_X4(r0, r1, r2, r3, addr) \
    asm volatile("ldmatrix.sync.aligned.m8n8.x4.shared.b16 {%0,%1,%2,%3}, [%4];" \
        : "=r"(r0), "=r"(r1), "=r"(r2), "=r"(r3) : "r"(addr))

#define MMA_F16(acc, a0, a1, a2, a3, b0, b1) \
    asm volatile( \
        "mma.sync.aligned.m16n8k16.row.col.f32.f16.f16.f32 " \
        "{%0,%1,%2,%3}, {%4,%5,%6,%7}, {%8,%9}, {%0,%1,%2,%3};" \
        : "+f"((acc)[0]), "+f"((acc)[1]), "+f"((acc)[2]), "+f"((acc)[3]) \
        : "r"(a0), "r"(a1), "r"(a2), "r"(a3), "r"(b0), "r"(b1))

// ---------------------------------------------------------------------------
// Conversion: fp32 activations (M x 1024) -> fp16 (hi,lo) interleaved (M x 2048)
// ---------------------------------------------------------------------------
__global__ void conv_act_kernel(const float* __restrict__ in,
                                __half* __restrict__ out)
{
    size_t j = (size_t)blockIdx.x * blockDim.x + threadIdx.x;
    float2 v = *(const float2*)(in + 2 * j);
    __half h0 = __float2half_rn(v.x);
    __half h1 = __float2half_rn(v.y);
    __half l0 = __float2half_rn(v.x - __half2float(h0));
    __half l1 = __float2half_rn(v.y - __half2float(h1));
    __half2* o = (__half2*)(out + 4 * j);
    o[0] = __half2(h0, l0);
    o[1] = __half2(h1, l1);
}

// ---------------------------------------------------------------------------
// Conversion: W (K x N fp32, row-major) -> B' (N x 2K fp16): (hi, hi)
// ---------------------------------------------------------------------------
__global__ void conv_weight_kernel(const float* __restrict__ W,
                                   __half* __restrict__ out,
                                   int N)
{
    __shared__ float t[32][33];
    const int tid = threadIdx.y * 32 + threadIdx.x;
    const int tx = threadIdx.x, ty = threadIdx.y;
#pragma unroll
    for (int i = 0; i < 4; i++) {
        int k = blockIdx.y * 32 + ty + 8 * i;
        int n = blockIdx.x * 32 + tx;
        t[ty + 8 * i][tx] = W[(size_t)k * N + n];
    }
    __syncthreads();
    const int w = tid >> 5, l = tid & 31;
#pragma unroll
    for (int r = 0; r < 4; r++) {
        int nl = w * 4 + r;
        int n = blockIdx.x * 32 + nl;
        __half hi = __float2half_rn(t[l][nl]);
        __half2* o = (__half2*)(out + (size_t)n * K2 + (size_t)(blockIdx.y * 32 + l) * 2);
        o[0] = __half2(hi, hi);
    }
}

// ---------------------------------------------------------------------------
// Conversion: V (fp32 [b,t,1024]) -> transposed split Vt[b,h,d,t] hi/lo fp16.
// ---------------------------------------------------------------------------
__global__ void vt_conv_kernel(const float* __restrict__ vf,
                               __half* __restrict__ vthi,
                               __half* __restrict__ vtlo)
{
    __shared__ float sm[32][33];
    const int tx = threadIdx.x, ty = threadIdx.y;
    const int t0 = blockIdx.x * 32;
    const int dblk = blockIdx.y;
    const int bh = blockIdx.z;
    const int b = bh >> 4, h = bh & 15;
#pragma unroll
    for (int i = 0; i < 4; i++) {
        int tl = ty + 8 * i;
        sm[tl][tx] = vf[((size_t)(b * SEQ + t0 + tl)) * DMODEL +
                        h * DHEAD + dblk * 32 + tx];
    }
    __syncthreads();
#pragma unroll
    for (int i = 0; i < 4; i++) {
        int dl = ty + 8 * i;
        float v = sm[tx][dl];
        __half hi = __float2half_rn(v);
        __half lo = __float2half_rn(v - __half2float(hi));
        size_t o = ((size_t)(bh * DHEAD + dblk * 32 + dl)) * SEQ + t0 + tx;
        vthi[o] = hi;
        vtlo[o] = lo;
    }
}

// ---------------------------------------------------------------------------
// GEMM mainloop (fp16 2-term, CTA 128x128, 4 warps 64x64, BK=64,
// 3-stage cp.async, one sync per iter).
// ---------------------------------------------------------------------------
#define GBK 64
#define ROWB 144                     // padded row bytes (64 fp16 = 128B data)
#define STILE (128 * ROWB)           // 18432 B
#define GSTAGE (2 * STILE)           // 36864 B
#define GSMEM (3 * GSTAGE)           // 110592 B

#define GEMM_PROLOGUE_AND_LOOP()                                               \
    const int tid = threadIdx.x;                                               \
    const int warp = tid >> 5;                                                 \
    const int lane = tid & 31;                                                 \
    const int bm = blockIdx.y * 128;                                           \
    const int bn = blockIdx.x * 128;                                           \
    const int wm0 = (warp >> 1) * 64;                                          \
    const int wn0 = (warp & 1) * 64;                                           \
    const int a_row_off = (lane & 7) + ((lane >> 3) & 1) * 8;                  \
    const int a_kch = (lane >> 4);                                             \
    const int b_row_off = (lane & 7) + ((lane >> 4) & 1) * 8;                  \
    const int b_kch = (lane >> 3) & 1;                                         \
    const uint32_t sbase = smem_u32(gsm);                                      \
    float acc[4][8][4];                                                        \
    _Pragma("unroll")                                                          \
    for (int mi = 0; mi < 4; mi++)                                             \
        _Pragma("unroll")                                                      \
        for (int ni = 0; ni < 8; ni++)                                         \
            _Pragma("unroll")                                                  \
            for (int r = 0; r < 4; r++) acc[mi][ni][r] = 0.f;                  \
    const int NIT = K / GBK;                                                   \
    auto load_stage = [&](int st, int k0) {                                    \
        uint32_t base = sbase + st * GSTAGE;                                   \
        _Pragma("unroll")                                                      \
        for (int i = 0; i < 8; i++) {                                          \
            int c = tid + i * 128;                                             \
            int row = c >> 3, ch = c & 7;                                      \
            uint32_t dA = base + row * ROWB + ch * 16;                         \
            uint32_t dB = dA + STILE;                                          \
            const __half* pA = A + (size_t)(bm + row) * K + k0 + ch * 8;       \
            const __half* pB = B + (size_t)(bn + row) * K + k0 + ch * 8;       \
            asm volatile("cp.async.cg.shared.global [%0], [%1], 16;\n" :: "r"(dA), "l"(pA) : "memory"); \
            asm volatile("cp.async.cg.shared.global [%0], [%1], 16;\n" :: "r"(dB), "l"(pB) : "memory"); \
        }                                                                      \
    };                                                                         \
    load_stage(0, 0);                                                          \
    asm volatile("cp.async.commit_group;\n" ::: "memory");                     \
    load_stage(1, GBK);                                                        \
    asm volatile("cp.async.commit_group;\n" ::: "memory");                     \
    int st = 0;                                                                \
    for (int it = 0; it < NIT; it++) {                                         \
        asm volatile("cp.async.wait_group 1;\n" ::: "memory");                 \
        __syncthreads();                                                       \
        if (it + 2 < NIT) {                                                    \
            int st2 = st + 2 >= 3 ? st - 1 : st + 2;                           \
            load_stage(st2, (it + 2) * GBK);                                   \
        }                                                                      \
        asm volatile("cp.async.commit_group;\n" ::: "memory");                 \
        uint32_t sA = sbase + st * GSTAGE;                                     \
        uint32_t sB = sA + STILE;                                              \
        _Pragma("unroll")                                                      \
        for (int ks = 0; ks < 4; ks++) {                                       \
            uint32_t af[4][4];                                                 \
            _Pragma("unroll")                                                  \
            for (int mi = 0; mi < 4; mi++) {                                   \
                uint32_t addr = sA + (wm0 + mi * 16 + a_row_off) * ROWB +      \
                                (ks * 2 + a_kch) * 16;                         \
                LDMATRIX_X4(af[mi][0], af[mi][1], af[mi][2], af[mi][3], addr); \
            }                                                                  \
            uint32_t bfr[4][4];                                                \
            _Pragma("unroll")                                                  \
            for (int nj = 0; nj < 4; nj++) {                                   \
                uint32_t addr = sB + (wn0 + nj * 16 + b_row_off) * ROWB +      \
                                (ks * 2 + b_kch) * 16;                         \
                LDMATRIX_X4(bfr[nj][0], bfr[nj][1], bfr[nj][2], bfr[nj][3], addr); \
            }                                                                  \
            _Pragma("unroll")                                                  \
            for (int mi = 0; mi < 4; mi++)                                     \
                _Pragma("unroll")                                              \
                for (int ni = 0; ni < 8; ni++)                                 \
                    MMA_F16(acc[mi][ni], af[mi][0], af[mi][1], af[mi][2], af[mi][3], \
                            bfr[ni >> 1][(ni & 1) * 2 + 0], bfr[ni >> 1][(ni & 1) * 2 + 1]); \
        }                                                                      \
        st = (st + 1 == 3) ? 0 : st + 1;                                       \
    }

// ---------------------------------------------------------------------------
// GEMM #2 (out-projection): plain fp32 epilogue.
// ---------------------------------------------------------------------------
__global__ void __launch_bounds__(128, 2) mma_gemm_kernel(
    const __half* __restrict__ A, const __half* __restrict__ B,
    float* __restrict__ C, int N, int K)
{
    extern __shared__ char gsm[];
    GEMM_PROLOGUE_AND_LOOP()

    const int gr = lane >> 2;
    const int tc = (lane & 3) * 2;
#pragma unroll
    for (int mi = 0; mi < 4; mi++) {
#pragma unroll
        for (int ni = 0; ni < 8; ni++) {
            size_t r0 = (size_t)(bm + wm0 + mi * 16 + gr);
            int col = bn + wn0 + ni * 8 + tc;
            *(float2*)&C[r0 * N + col] = make_float2(acc[mi][ni][0], acc[mi][ni][1]);
            *(float2*)&C[(r0 + 8) * N + col] = make_float2(acc[mi][ni][2], acc[mi][ni][3]);
        }
    }
}

// ---------------------------------------------------------------------------
// GEMM #1 (QKV): fused epilogue writes Q'/K' fp16 layouts + V fp32.
// bn in [0,1024) -> Q, [1024,2048) -> K, [2048,3072) -> V.
// Q'[b,h,t,2d..2d+1] = (hi,lo) of QSCALE*q;  K' = (hi,hi) of k.
// ---------------------------------------------------------------------------
__global__ void __launch_bounds__(128, 2) mma_gemm_qkv_kernel(
    const __half* __restrict__ A, const __half* __restrict__ B,
    __half* __restrict__ qp, __half* __restrict__ kp,
    float* __restrict__ vf, int N, int K)
{
    extern __shared__ char gsm[];
    GEMM_PROLOGUE_AND_LOOP()

    const int gr = lane >> 2;
    const int tc = (lane & 3) * 2;
    const int sec = bn >> 10;                 // 0=Q, 1=K, 2=V
    const int colbase = (bn & 1023) + wn0;

#pragma unroll
    for (int mi = 0; mi < 4; mi++) {
#pragma unroll
        for (int rr = 0; rr < 2; rr++) {
            const int row = bm + wm0 + mi * 16 + gr + rr * 8;
            const int b = row >> 11;
            const int t = row & (SEQ - 1);
#pragma unroll
            for (int ni = 0; ni < 8; ni++) {
                const int col = colbase + ni * 8 + tc;    // within section
                float v0 = acc[mi][ni][rr * 2 + 0];
                float v1 = acc[mi][ni][rr * 2 + 1];
                if (sec == 2) {
                    *(float2*)&vf[(size_t)(b * SEQ + t) * DMODEL + col] =
                        make_float2(v0, v1);
                } else {
                    const int h = col >> 6;
                    const int d = col & 63;
                    size_t base = ((size_t)((b * NHEAD + h) * SEQ + t)) * 128 + 2 * d;
                    __half2* p = (__half2*)(qp + base);
                    if (sec == 0) {
                        v0 *= QSCALE; v1 *= QSCALE;
                    } else {
                        p = (__half2*)(kp + base);
                    }
                    __half h0 = __float2half_rn(v0);
                    __half h1 = __float2half_rn(v1);
                    if (sec == 0) {
                        __half l0 = __float2half_rn(v0 - __half2float(h0));
                        __half l1 = __float2half_rn(v1 - __half2float(h1));
                        p[0] = __half2(h0, l0);
                        p[1] = __half2(h1, l1);
                    } else {
                        p[0] = __half2(h0, h0);
                        p[1] = __half2(h1, h1);
                    }
                }
            }
        }
    }
}

// ---------------------------------------------------------------------------
// Tensor-core flash attention (FA2), causal, all fp16 2-term.
// S = Q'(hi,lo) . K'(hi,hi)^T, K'=128.  PV = P_f16.Vhi + P_f16.Vlo.
// Epilogue writes fp16 (hi,lo) K2-layout A-operand for the out-projection.
// ---------------------------------------------------------------------------
#define KPITCH 272                  // 128 fp16 = 256B data + 16 pad
#define VPITCH 144                  // 64 fp16 = 128B data + 16 pad
#define KS_BYTES (64 * KPITCH)      // 17408
#define VS_BYTES (64 * VPITCH)      // 9216
#define FSTAGE (KS_BYTES + 2 * VS_BYTES)  // 35840
#define FSMEM (2 * FSTAGE)          // 71680

__global__ void __launch_bounds__(128, 3) flash_mma_kernel(
    const __half* __restrict__ qp, const __half* __restrict__ kp,
    const __half* __restrict__ vthi, const __half* __restrict__ vtlo,
    __half* __restrict__ aP)
{
    extern __shared__ char fsm[];
    const int tid = threadIdx.x;
    const int warp = tid >> 5;
    const int lane = tid & 31;
    const int qt = gridDim.x - 1 - blockIdx.x;
    const int h = blockIdx.y;
    const int b = blockIdx.z;
    const int bh = b * NHEAD + h;
    const int q0 = qt * 64;

    const uint32_t sb = smem_u32(fsm);
    const int gr = lane >> 2;
    const int tc = lane & 3;
    const int a_row_off = (lane & 7) + ((lane >> 3) & 1) * 8;
    const int a_kch = lane >> 4;
    const int b_row_off = (lane & 7) + ((lane >> 4) & 1) * 8;
    const int b_kch = (lane >> 3) & 1;

    // ---- stage Q' tile into stage-0 K area, extract A fragments
    {
        const __half* qsrc = qp + ((size_t)(bh * SEQ + q0)) * 128;
#pragma unroll
        for (int i = 0; i < 8; i++) {
            int c = i * 128 + tid;
            int row = c >> 4, ch = c & 15;
            uint32_t dst = sb + row * KPITCH + ch * 16;
            const __half* src = qsrc + (size_t)row * 128 + ch * 8;
            asm volatile("cp.async.cg.shared.global [%0], [%1], 16;\n" :: "r"(dst), "l"(src) : "memory");
        }
        asm volatile("cp.async.commit_group;\ncp.async.wait_group 0;\n" ::: "memory");
        __syncthreads();
    }
    uint32_t qf[8][4];
#pragma unroll
    for (int ck = 0; ck < 8; ck++) {
        uint32_t addr = sb + (warp * 16 + a_row_off) * KPITCH + ck * 32 + a_kch * 16;
        LDMATRIX_X4(qf[ck][0], qf[ck][1], qf[ck][2], qf[ck][3], addr);
    }
    __syncthreads();

    float oacc[8][4];
#pragma unroll
    for (int t = 0; t < 8; t++)
#pragma unroll
        for (int r = 0; r < 4; r++) oacc[t][r] = 0.f;
    float m0 = -1e30f, m1 = -1e30f, l0 = 0.f, l1 = 0.f;

    auto load_tile = [&](int kt, int st) {
        const int kt0 = kt * 64;
        uint32_t ks = sb + st * FSTAGE;
        uint32_t vh = ks + KS_BYTES;
        uint32_t vl = vh + VS_BYTES;
        const __half* ksrc = kp + ((size_t)(bh * SEQ + kt0)) * 128;
#pragma unroll
        for (int i = 0; i < 8; i++) {
            int c = i * 128 + tid;
            int row = c >> 4, ch = c & 15;
            uint32_t dst = ks + row * KPITCH + ch * 16;
            const __half* src = ksrc + (size_t)row * 128 + ch * 8;
            asm volatile("cp.async.cg.shared.global [%0], [%1], 16;\n" :: "r"(dst), "l"(src) : "memory");
        }
#pragma unroll
        for (int i = 0; i < 4; i++) {
            int c = i * 128 + tid;
            int row = c >> 3, ch = c & 7;
            size_t so = ((size_t)(bh * DHEAD + row)) * SEQ + kt0 + ch * 8;
            uint32_t dsh = vh + row * VPITCH + ch * 16;
            uint32_t dsl = vl + row * VPITCH + ch * 16;
            asm volatile("cp.async.cg.shared.global [%0], [%1], 16;\n" :: "r"(dsh), "l"(vthi + so) : "memory");
            asm volatile("cp.async.cg.shared.global [%0], [%1], 16;\n" :: "r"(dsl), "l"(vtlo + so) : "memory");
        }
    };

    load_tile(0, 0);
    asm volatile("cp.async.commit_group;\n" ::: "memory");
    if (qt >= 1) load_tile(1, 1);
    asm volatile("cp.async.commit_group;\n" ::: "memory");

    for (int kt = 0; kt <= qt; kt++) {
        asm volatile("cp.async.wait_group 1;\n" ::: "memory");
        __syncthreads();
        const int st = kt & 1;
        uint32_t ks = sb + st * FSTAGE;
        uint32_t vh = ks + KS_BYTES;
        uint32_t vl = vh + VS_BYTES;

        // ---- S = Q'.K'^T (8 chunks, K'=128)
        float sacc[8][4];
#pragma unroll
        for (int t = 0; t < 8; t++)
#pragma unroll
            for (int r = 0; r < 4; r++) sacc[t][r] = 0.f;
#pragma unroll
        for (int ck = 0; ck < 8; ck++) {
            uint32_t bfr[4][4];
#pragma unroll
            for (int nj = 0; nj < 4; nj++) {
                uint32_t addr = ks + (nj * 16 + b_row_off) * KPITCH + ck * 32 + b_kch * 16;
                LDMATRIX_X4(bfr[nj][0], bfr[nj][1], bfr[nj][2], bfr[nj][3], addr);
            }
#pragma unroll
            for (int ni = 0; ni < 8; ni++)
                MMA_F16(sacc[ni], qf[ck][0], qf[ck][1], qf[ck][2], qf[ck][3],
                        bfr[ni >> 1][(ni & 1) * 2 + 0], bfr[ni >> 1][(ni & 1) * 2 + 1]);
        }

        // ---- causal mask on diagonal tile
        if (kt == qt) {
            int rq0 = warp * 16 + gr;
            int rq1 = rq0 + 8;
#pragma unroll
            for (int t = 0; t < 8; t++) {
                int c0 = 8 * t + 2 * tc;
                if (c0 > rq0)     sacc[t][0] = -1e30f;
                if (c0 + 1 > rq0) sacc[t][1] = -1e30f;
                if (c0 > rq1)     sacc[t][2] = -1e30f;
                if (c0 + 1 > rq1) sacc[t][3] = -1e30f;
            }
        }

        // ---- online softmax (base-2, quad reductions)
        float mx0 = -1e30f, mx1 = -1e30f;
#pragma unroll
        for (int t = 0; t < 8; t++) {
            mx0 = fmaxf(mx0, fmaxf(sacc[t][0], sacc[t][1]));
            mx1 = fmaxf(mx1, fmaxf(sacc[t][2], sacc[t][3]));
        }
        mx0 = fmaxf(mx0, __shfl_xor_sync(0xffffffffu, mx0, 1));
        mx0 = fmaxf(mx0, __shfl_xor_sync(0xffffffffu, mx0, 2));
        mx1 = fmaxf(mx1, __shfl_xor_sync(0xffffffffu, mx1, 1));
        mx1 = fmaxf(mx1, __shfl_xor_sync(0xffffffffu, mx1, 2));
        float mn0 = fmaxf(m0, mx0), mn1 = fmaxf(m1, mx1);
        float cr0 = fast_exp2(m0 - mn0), cr1 = fast_exp2(m1 - mn1);
        m0 = mn0; m1 = mn1;
        l0 *= cr0; l1 *= cr1;
#pragma unroll
        for (int t = 0; t < 8; t++) {
            oacc[t][0] *= cr0; oacc[t][1] *= cr0;
            oacc[t][2] *= cr1; oacc[t][3] *= cr1;
        }
        uint32_t phi[8][2];
        float rs0 = 0.f, rs1 = 0.f;
#pragma unroll
        for (int t = 0; t < 8; t++) {
            float p0 = fast_exp2(sacc[t][0] - m0);
            float p1 = fast_exp2(sacc[t][1] - m0);
            float p2 = fast_exp2(sacc[t][2] - m1);
            float p3 = fast_exp2(sacc[t][3] - m1);
            rs0 += p0 + p1; rs1 += p2 + p3;
            phi[t][0] = pack_f16x2(p0, p1);
            phi[t][1] = pack_f16x2(p2, p3);
        }
        rs0 += __shfl_xor_sync(0xffffffffu, rs0, 1);
        rs0 += __shfl_xor_sync(0xffffffffu, rs0, 2);
        rs1 += __shfl_xor_sync(0xffffffffu, rs1, 1);
        rs1 += __shfl_xor_sync(0xffffffffu, rs1, 2);
        l0 += rs0; l1 += rs1;

        // ---- PV: O += P.Vhi + P.Vlo
#pragma unroll
        for (int ck = 0; ck < 4; ck++) {
            uint32_t aph[4] = { phi[2 * ck][0], phi[2 * ck][1],
                                phi[2 * ck + 1][0], phi[2 * ck + 1][1] };
            uint32_t vhf[4][4], vlf[4][4];
#pragma unroll
            for (int dt = 0; dt < 4; dt++) {
                uint32_t ah = vh + (dt * 16 + b_row_off) * VPITCH + ck * 32 + b_kch * 16;
                uint32_t al = vl + (dt * 16 + b_row_off) * VPITCH + ck * 32 + b_kch * 16;
                LDMATRIX_X4(vhf[dt][0], vhf[dt][1], vhf[dt][2], vhf[dt][3], ah);
                LDMATRIX_X4(vlf[dt][0], vlf[dt][1], vlf[dt][2], vlf[dt][3], al);
            }
#pragma unroll
            for (int ni = 0; ni < 8; ni++) {
                MMA_F16(oacc[ni], aph[0], aph[1], aph[2], aph[3],
                        vhf[ni >> 1][(ni & 1) * 2 + 0], vhf[ni >> 1][(ni & 1) * 2 + 1]);
                MMA_F16(oacc[ni], aph[0], aph[1], aph[2], aph[3],
                        vlf[ni >> 1][(ni & 1) * 2 + 0], vlf[ni >> 1][(ni & 1) * 2 + 1]);
            }
        }

        __syncthreads();
        if (kt + 2 <= qt) load_tile(kt + 2, st);
        asm volatile("cp.async.commit_group;\n" ::: "memory");
    }

    // ---- epilogue: write fp16 (hi,lo) interleaved directly into aP (K2 layout)
    const float inv0 = 1.f / l0, inv1 = 1.f / l1;
    const int qr0 = q0 + warp * 16 + gr;
    const int qr1 = qr0 + 8;
#pragma unroll
    for (int t = 0; t < 8; t++) {
        int col = h * DHEAD + 8 * t + 2 * tc;
        float c0 = oacc[t][0] * inv0, c1 = oacc[t][1] * inv0;
        float d0 = oacc[t][2] * inv1, d1 = oacc[t][3] * inv1;

        __half ch0 = __float2half_rn(c0);
        __half ch1 = __float2half_rn(c1);
        __half cl0 = __float2half_rn(c0 - __half2float(ch0));
        __half cl1 = __float2half_rn(c1 - __half2float(ch1));
        __half2* p0 = (__half2*)(aP + ((size_t)(b * SEQ + qr0)) * K2 + 2 * col);
        p0[0] = __half2(ch0, cl0);
        p0[1] = __half2(ch1, cl1);

        __half dh0 = __float2half_rn(d0);
        __half dh1 = __float2half_rn(d1);
        __half dl0 = __float2half_rn(d0 - __half2float(dh0));
        __half dl1 = __float2half_rn(d1 - __half2float(dh1));
        __half2* p1 = (__half2*)(aP + ((size_t)(b * SEQ + qr1)) * K2 + 2 * col);
        p1[0] = __half2(dh0, dl0);
        p1[1] = __half2(dh1, dl1);
    }
}

// ---------------------------------------------------------------------------
extern "C" void kernel_launch(void* const* d_in, const int* in_sizes, int n_in,
                              void* d_out, int out_size)
{
    const float* x     = (const float*)d_in[0];
    const float* W_qkv = (const float*)d_in[1];
    const float* W_o   = (const float*)d_in[2];
    float* out = (float*)d_out;

    float *vf;
    __half *aP, *w1P, *w2P, *qp, *kp, *vthi, *vtlo;
    cudaGetSymbolAddress((void**)&vf, g_vf);
    cudaGetSymbolAddress((void**)&aP, g_aP);
    cudaGetSymbolAddress((void**)&w1P, g_w1P);
    cudaGetSymbolAddress((void**)&w2P, g_w2P);
    cudaGetSymbolAddress((void**)&qp, g_qp);
    cudaGetSymbolAddress((void**)&kp, g_kp);
    cudaGetSymbolAddress((void**)&vthi, g_vthi);
    cudaGetSymbolAddress((void**)&vtlo, g_vtlo);

    cudaFuncSetAttribute(flash_mma_kernel,
                         cudaFuncAttributeMaxDynamicSharedMemorySize, FSMEM);
    cudaFuncSetAttribute(mma_gemm_kernel,
                         cudaFuncAttributeMaxDynamicSharedMemorySize, GSMEM);
    cudaFuncSetAttribute(mma_gemm_qkv_kernel,
                         cudaFuncAttributeMaxDynamicSharedMemorySize, GSMEM);

    // conversions
    {
        dim3 g(QKV_COLS / 32, DMODEL / 32);
        conv_weight_kernel<<<g, dim3(32, 8)>>>(W_qkv, w1P, QKV_COLS);
    }
    {
        dim3 g(DMODEL / 32, DMODEL / 32);
        conv_weight_kernel<<<g, dim3(32, 8)>>>(W_o, w2P, DMODEL);
    }
    conv_act_kernel<<<(MROWS * DMODEL / 2) / 256, 256>>>(x, aP);

    // 1) QKV GEMM with fused Q'/K'/V epilogue
    {
        dim3 grid(QKV_COLS / 128, MROWS / 128);
        mma_gemm_qkv_kernel<<<grid, 128, GSMEM>>>(aP, w1P, qp, kp, vf,
                                                  QKV_COLS, K2);
    }
    // V transpose/split
    {
        dim3 g(SEQ / 32, 2, BATCH * NHEAD);
        vt_conv_kernel<<<g, dim3(32, 8)>>>(vf, vthi, vtlo);
    }
    // 2) flash attention (writes fp16 aP for out-proj)
    {
        dim3 grid(SEQ / 64, NHEAD, BATCH);
        flash_mma_kernel<<<grid, 128, FSMEM>>>(qp, kp, vthi, vtlo, aP);
    }
    // 3) out = attn_out @ W_o
    {
        dim3 grid(DMODEL / 128, MROWS / 128);
        mma_gemm_kernel<<<grid, 128, GSMEM>>>(aP, w2P, out, DMODEL, K2);
    }
}

// round 8
// speedup vs baseline: 6.1931x; 1.3937x over previous
#include <cuda_runtime.h>
#include <cuda_bf16.h>
#include <cuda_fp16.h>
#include <math.h>
#include <stdint.h>

// Problem constants
#define BATCH 2
#define SEQ   2048
#define DMODEL 1024
#define NHEAD 16
#define DHEAD 64
#define MROWS (BATCH * SEQ)           // 4096
#define QKV_COLS (3 * DMODEL)         // 3072
#define QSCALE 0.18033688f            // 0.125 * log2(e)

// ---------------------------------------------------------------------------
// Scratch (static device globals; allocations are forbidden)
// ---------------------------------------------------------------------------
__device__ float g_vf[(size_t)MROWS * DMODEL];             // 17 MB (V fp32)
__device__ __half g_aP[(size_t)MROWS * DMODEL];            // 8.4 MB (A fp16, both GEMMs)
__device__ __half g_w1P[(size_t)QKV_COLS * DMODEL];        // 6.3 MB (W_qkv^T fp16)
__device__ __half g_w2P[(size_t)DMODEL * DMODEL];          // 2.1 MB (W_o^T fp16)
// Attention operands (fp16 2-term)
__device__ __half g_qp[(size_t)BATCH * NHEAD * SEQ * 128];     // 16.8 MB
__device__ __half g_kp[(size_t)BATCH * NHEAD * SEQ * 128];     // 16.8 MB
__device__ __half g_vthi[(size_t)BATCH * NHEAD * DHEAD * SEQ]; // 8.4 MB
__device__ __half g_vtlo[(size_t)BATCH * NHEAD * DHEAD * SEQ]; // 8.4 MB

__device__ __forceinline__ uint32_t smem_u32(const void* p) {
    uint32_t a;
    asm("{ .reg .u64 t; cvta.to.shared.u64 t, %1; cvt.u32.u64 %0, t; }" : "=r"(a) : "l"(p));
    return a;
}
__device__ __forceinline__ float fast_exp2(float x) {
    float y; asm("ex2.approx.ftz.f32 %0, %1;" : "=f"(y) : "f"(x)); return y;
}
// pack fp16x2: low half = lo, high half = hi
__device__ __forceinline__ uint32_t pack_f16x2(float lo, float hi) {
    uint32_t r; asm("cvt.rn.f16x2.f32 %0, %1, %2;" : "=r"(r) : "f"(hi), "f"(lo)); return r;
}

#define LDMATRIX_X4(r0, r1, r2, r3, addr) \
    asm volatile("ldmatrix.sync.aligned.m8n8.x4.shared.b16 {%0,%1,%2,%3}, [%4];" \
        : "=r"(r0), "=r"(r1), "=r"(r2), "=r"(r3) : "r"(addr))

#define MMA_F16(acc, a0, a1, a2, a3, b0, b1) \
    asm volatile( \
        "mma.sync.aligned.m16n8k16.row.col.f32.f16.f16.f32 " \
        "{%0,%1,%2,%3}, {%4,%5,%6,%7}, {%8,%9}, {%0,%1,%2,%3};" \
        : "+f"((acc)[0]), "+f"((acc)[1]), "+f"((acc)[2]), "+f"((acc)[3]) \
        : "r"(a0), "r"(a1), "r"(a2), "r"(a3), "r"(b0), "r"(b1))

// ---------------------------------------------------------------------------
// Conversion: fp32 activations (M x 1024) -> fp16 (M x 1024)
// ---------------------------------------------------------------------------
__global__ void conv_act_kernel(const float* __restrict__ in,
                                __half* __restrict__ out)
{
    size_t j = (size_t)blockIdx.x * blockDim.x + threadIdx.x;
    float4 v = *(const float4*)(in + 4 * j);
    __half2* o = (__half2*)(out + 4 * j);
    o[0] = __half2(__float2half_rn(v.x), __float2half_rn(v.y));
    o[1] = __half2(__float2half_rn(v.z), __float2half_rn(v.w));
}

// ---------------------------------------------------------------------------
// Conversion: W (K x N fp32, row-major) -> B' (N x K fp16) transpose-cast
// ---------------------------------------------------------------------------
__global__ void conv_weight_kernel(const float* __restrict__ W,
                                   __half* __restrict__ out,
                                   int N)
{
    __shared__ float t[32][33];
    const int tx = threadIdx.x, ty = threadIdx.y;
#pragma unroll
    for (int i = 0; i < 4; i++) {
        int k = blockIdx.y * 32 + ty + 8 * i;
        int n = blockIdx.x * 32 + tx;
        t[ty + 8 * i][tx] = W[(size_t)k * N + n];
    }
    __syncthreads();
#pragma unroll
    for (int i = 0; i < 4; i++) {
        int nl = ty + 8 * i;
        int n = blockIdx.x * 32 + nl;
        out[(size_t)n * DMODEL + blockIdx.y * 32 + tx] = __float2half_rn(t[tx][nl]);
    }
}

// ---------------------------------------------------------------------------
// Conversion: V (fp32 [b,t,1024]) -> transposed split Vt[b,h,d,t] hi/lo fp16.
// ---------------------------------------------------------------------------
__global__ void vt_conv_kernel(const float* __restrict__ vf,
                               __half* __restrict__ vthi,
                               __half* __restrict__ vtlo)
{
    __shared__ float sm[32][33];
    const int tx = threadIdx.x, ty = threadIdx.y;
    const int t0 = blockIdx.x * 32;
    const int dblk = blockIdx.y;
    const int bh = blockIdx.z;
    const int b = bh >> 4, h = bh & 15;
#pragma unroll
    for (int i = 0; i < 4; i++) {
        int tl = ty + 8 * i;
        sm[tl][tx] = vf[((size_t)(b * SEQ + t0 + tl)) * DMODEL +
                        h * DHEAD + dblk * 32 + tx];
    }
    __syncthreads();
#pragma unroll
    for (int i = 0; i < 4; i++) {
        int dl = ty + 8 * i;
        float v = sm[tx][dl];
        __half hi = __float2half_rn(v);
        __half lo = __float2half_rn(v - __half2float(hi));
        size_t o = ((size_t)(bh * DHEAD + dblk * 32 + dl)) * SEQ + t0 + tx;
        vthi[o] = hi;
        vtlo[o] = lo;
    }
}

// ---------------------------------------------------------------------------
// GEMM mainloop (fp16 1-term, CTA 128x128, 4 warps 64x64, BK=64,
// 3-stage cp.async, one sync per iter).
// ---------------------------------------------------------------------------
#define GBK 64
#define ROWB 144                     // padded row bytes (64 fp16 = 128B data)
#define STILE (128 * ROWB)           // 18432 B
#define GSTAGE (2 * STILE)           // 36864 B
#define GSMEM (3 * GSTAGE)           // 110592 B

#define GEMM_PROLOGUE_AND_LOOP()                                               \
    const int tid = threadIdx.x;                                               \
    const int warp = tid >> 5;                                                 \
    const int lane = tid & 31;                                                 \
    const int bm = blockIdx.y * 128;                                           \
    const int bn = blockIdx.x * 128;                                           \
    const int wm0 = (warp >> 1) * 64;                                          \
    const int wn0 = (warp & 1) * 64;                                           \
    const int a_row_off = (lane & 7) + ((lane >> 3) & 1) * 8;                  \
    const int a_kch = (lane >> 4);                                             \
    const int b_row_off = (lane & 7) + ((lane >> 4) & 1) * 8;                  \
    const int b_kch = (lane >> 3) & 1;                                         \
    const uint32_t sbase = smem_u32(gsm);                                      \
    float acc[4][8][4];                                                        \
    _Pragma("unroll")                                                          \
    for (int mi = 0; mi < 4; mi++)                                             \
        _Pragma("unroll")                                                      \
        for (int ni = 0; ni < 8; ni++)                                         \
            _Pragma("unroll")                                                  \
            for (int r = 0; r < 4; r++) acc[mi][ni][r] = 0.f;                  \
    const int NIT = K / GBK;                                                   \
    auto load_stage = [&](int st, int k0) {                                    \
        uint32_t base = sbase + st * GSTAGE;                                   \
        _Pragma("unroll")                                                      \
        for (int i = 0; i < 8; i++) {                                          \
            int c = tid + i * 128;                                             \
            int row = c >> 3, ch = c & 7;                                      \
            uint32_t dA = base + row * ROWB + ch * 16;                         \
            uint32_t dB = dA + STILE;                                          \
            const __half* pA = A + (size_t)(bm + row) * K + k0 + ch * 8;       \
            const __half* pB = B + (size_t)(bn + row) * K + k0 + ch * 8;       \
            asm volatile("cp.async.cg.shared.global [%0], [%1], 16;\n" :: "r"(dA), "l"(pA) : "memory"); \
            asm volatile("cp.async.cg.shared.global [%0], [%1], 16;\n" :: "r"(dB), "l"(pB) : "memory"); \
        }                                                                      \
    };                                                                         \
    load_stage(0, 0);                                                          \
    asm volatile("cp.async.commit_group;\n" ::: "memory");                     \
    load_stage(1, GBK);                                                        \
    asm volatile("cp.async.commit_group;\n" ::: "memory");                     \
    int st = 0;                                                                \
    for (int it = 0; it < NIT; it++) {                                         \
        asm volatile("cp.async.wait_group 1;\n" ::: "memory");                 \
        __syncthreads();                                                       \
        if (it + 2 < NIT) {                                                    \
            int st2 = st + 2 >= 3 ? st - 1 : st + 2;                           \
            load_stage(st2, (it + 2) * GBK);                                   \
        }                                                                      \
        asm volatile("cp.async.commit_group;\n" ::: "memory");                 \
        uint32_t sA = sbase + st * GSTAGE;                                     \
        uint32_t sB = sA + STILE;                                              \
        _Pragma("unroll")                                                      \
        for (int ks = 0; ks < 4; ks++) {                                       \
            uint32_t af[4][4];                                                 \
            _Pragma("unroll")                                                  \
            for (int mi = 0; mi < 4; mi++) {                                   \
                uint32_t addr = sA + (wm0 + mi * 16 + a_row_off) * ROWB +      \
                                (ks * 2 + a_kch) * 16;                         \
                LDMATRIX_X4(af[mi][0], af[mi][1], af[mi][2], af[mi][3], addr); \
            }                                                                  \
            uint32_t bfr[4][4];                                                \
            _Pragma("unroll")                                                  \
            for (int nj = 0; nj < 4; nj++) {                                   \
                uint32_t addr = sB + (wn0 + nj * 16 + b_row_off) * ROWB +      \
                                (ks * 2 + b_kch) * 16;                         \
                LDMATRIX_X4(bfr[nj][0], bfr[nj][1], bfr[nj][2], bfr[nj][3], addr); \
            }                                                                  \
            _Pragma("unroll")                                                  \
            for (int mi = 0; mi < 4; mi++)                                     \
                _Pragma("unroll")                                              \
                for (int ni = 0; ni < 8; ni++)                                 \
                    MMA_F16(acc[mi][ni], af[mi][0], af[mi][1], af[mi][2], af[mi][3], \
                            bfr[ni >> 1][(ni & 1) * 2 + 0], bfr[ni >> 1][(ni & 1) * 2 + 1]); \
        }                                                                      \
        st = (st + 1 == 3) ? 0 : st + 1;                                       \
    }

// ---------------------------------------------------------------------------
// GEMM #2 (out-projection): plain fp32 epilogue.
// ---------------------------------------------------------------------------
__global__ void __launch_bounds__(128, 2) mma_gemm_kernel(
    const __half* __restrict__ A, const __half* __restrict__ B,
    float* __restrict__ C, int N, int K)
{
    extern __shared__ char gsm[];
    GEMM_PROLOGUE_AND_LOOP()

    const int gr = lane >> 2;
    const int tc = (lane & 3) * 2;
#pragma unroll
    for (int mi = 0; mi < 4; mi++) {
#pragma unroll
        for (int ni = 0; ni < 8; ni++) {
            size_t r0 = (size_t)(bm + wm0 + mi * 16 + gr);
            int col = bn + wn0 + ni * 8 + tc;
            *(float2*)&C[r0 * N + col] = make_float2(acc[mi][ni][0], acc[mi][ni][1]);
            *(float2*)&C[(r0 + 8) * N + col] = make_float2(acc[mi][ni][2], acc[mi][ni][3]);
        }
    }
}

// ---------------------------------------------------------------------------
// GEMM #1 (QKV): fused epilogue writes Q'/K' fp16 layouts + V fp32.
// bn in [0,1024) -> Q, [1024,2048) -> K, [2048,3072) -> V.
// Q'[b,h,t,2d..2d+1] = (hi,lo) of QSCALE*q;  K' = (hi,hi) of k.
// ---------------------------------------------------------------------------
__global__ void __launch_bounds__(128, 2) mma_gemm_qkv_kernel(
    const __half* __restrict__ A, const __half* __restrict__ B,
    __half* __restrict__ qp, __half* __restrict__ kp,
    float* __restrict__ vf, int N, int K)
{
    extern __shared__ char gsm[];
    GEMM_PROLOGUE_AND_LOOP()

    const int gr = lane >> 2;
    const int tc = (lane & 3) * 2;
    const int sec = bn >> 10;                 // 0=Q, 1=K, 2=V
    const int colbase = (bn & 1023) + wn0;

#pragma unroll
    for (int mi = 0; mi < 4; mi++) {
#pragma unroll
        for (int rr = 0; rr < 2; rr++) {
            const int row = bm + wm0 + mi * 16 + gr + rr * 8;
            const int b = row >> 11;
            const int t = row & (SEQ - 1);
#pragma unroll
            for (int ni = 0; ni < 8; ni++) {
                const int col = colbase + ni * 8 + tc;    // within section
                float v0 = acc[mi][ni][rr * 2 + 0];
                float v1 = acc[mi][ni][rr * 2 + 1];
                if (sec == 2) {
                    *(float2*)&vf[(size_t)(b * SEQ + t) * DMODEL + col] =
                        make_float2(v0, v1);
                } else {
                    const int h = col >> 6;
                    const int d = col & 63;
                    size_t base = ((size_t)((b * NHEAD + h) * SEQ + t)) * 128 + 2 * d;
                    __half2* p = (__half2*)(qp + base);
                    if (sec == 0) {
                        v0 *= QSCALE; v1 *= QSCALE;
                    } else {
                        p = (__half2*)(kp + base);
                    }
                    __half h0 = __float2half_rn(v0);
                    __half h1 = __float2half_rn(v1);
                    if (sec == 0) {
                        __half l0 = __float2half_rn(v0 - __half2float(h0));
                        __half l1 = __float2half_rn(v1 - __half2float(h1));
                        p[0] = __half2(h0, l0);
                        p[1] = __half2(h1, l1);
                    } else {
                        p[0] = __half2(h0, h0);
                        p[1] = __half2(h1, h1);
                    }
                }
            }
        }
    }
}

// ---------------------------------------------------------------------------
// Tensor-core flash attention (FA2), causal, fp16 2-term.
// S = Q'(hi,lo) . K'(hi,hi)^T, K'=128.  PV = P_f16.Vhi + P_f16.Vlo.
// Epilogue writes plain fp16 output row for GEMM #2 A-operand.
// ---------------------------------------------------------------------------
#define KPITCH 272                  // 128 fp16 = 256B data + 16 pad
#define VPITCH 144                  // 64 fp16 = 128B data + 16 pad
#define KS_BYTES (64 * KPITCH)      // 17408
#define VS_BYTES (64 * VPITCH)      // 9216
#define FSTAGE (KS_BYTES + 2 * VS_BYTES)  // 35840
#define FSMEM (2 * FSTAGE)          // 71680

__global__ void __launch_bounds__(128, 3) flash_mma_kernel(
    const __half* __restrict__ qp, const __half* __restrict__ kp,
    const __half* __restrict__ vthi, const __half* __restrict__ vtlo,
    __half* __restrict__ aP)
{
    extern __shared__ char fsm[];
    const int tid = threadIdx.x;
    const int warp = tid >> 5;
    const int lane = tid & 31;
    const int qt = gridDim.x - 1 - blockIdx.x;
    const int h = blockIdx.y;
    const int b = blockIdx.z;
    const int bh = b * NHEAD + h;
    const int q0 = qt * 64;

    const uint32_t sb = smem_u32(fsm);
    const int gr = lane >> 2;
    const int tc = lane & 3;
    const int a_row_off = (lane & 7) + ((lane >> 3) & 1) * 8;
    const int a_kch = lane >> 4;
    const int b_row_off = (lane & 7) + ((lane >> 4) & 1) * 8;
    const int b_kch = (lane >> 3) & 1;

    // ---- stage Q' tile into stage-0 K area, extract A fragments
    {
        const __half* qsrc = qp + ((size_t)(bh * SEQ + q0)) * 128;
#pragma unroll
        for (int i = 0; i < 8; i++) {
            int c = i * 128 + tid;
            int row = c >> 4, ch = c & 15;
            uint32_t dst = sb + row * KPITCH + ch * 16;
            const __half* src = qsrc + (size_t)row * 128 + ch * 8;
            asm volatile("cp.async.cg.shared.global [%0], [%1], 16;\n" :: "r"(dst), "l"(src) : "memory");
        }
        asm volatile("cp.async.commit_group;\ncp.async.wait_group 0;\n" ::: "memory");
        __syncthreads();
    }
    uint32_t qf[8][4];
#pragma unroll
    for (int ck = 0; ck < 8; ck++) {
        uint32_t addr = sb + (warp * 16 + a_row_off) * KPITCH + ck * 32 + a_kch * 16;
        LDMATRIX_X4(qf[ck][0], qf[ck][1], qf[ck][2], qf[ck][3], addr);
    }
    __syncthreads();

    float oacc[8][4];
#pragma unroll
    for (int t = 0; t < 8; t++)
#pragma unroll
        for (int r = 0; r < 4; r++) oacc[t][r] = 0.f;
    float m0 = -1e30f, m1 = -1e30f, l0 = 0.f, l1 = 0.f;

    auto load_tile = [&](int kt, int st) {
        const int kt0 = kt * 64;
        uint32_t ks = sb + st * FSTAGE;
        uint32_t vh = ks + KS_BYTES;
        uint32_t vl = vh + VS_BYTES;
        const __half* ksrc = kp + ((size_t)(bh * SEQ + kt0)) * 128;
#pragma unroll
        for (int i = 0; i < 8; i++) {
            int c = i * 128 + tid;
            int row = c >> 4, ch = c & 15;
            uint32_t dst = ks + row * KPITCH + ch * 16;
            const __half* src = ksrc + (size_t)row * 128 + ch * 8;
            asm volatile("cp.async.cg.shared.global [%0], [%1], 16;\n" :: "r"(dst), "l"(src) : "memory");
        }
#pragma unroll
        for (int i = 0; i < 4; i++) {
            int c = i * 128 + tid;
            int row = c >> 3, ch = c & 7;
            size_t so = ((size_t)(bh * DHEAD + row)) * SEQ + kt0 + ch * 8;
            uint32_t dsh = vh + row * VPITCH + ch * 16;
            uint32_t dsl = vl + row * VPITCH + ch * 16;
            asm volatile("cp.async.cg.shared.global [%0], [%1], 16;\n" :: "r"(dsh), "l"(vthi + so) : "memory");
            asm volatile("cp.async.cg.shared.global [%0], [%1], 16;\n" :: "r"(dsl), "l"(vtlo + so) : "memory");
        }
    };

    load_tile(0, 0);
    asm volatile("cp.async.commit_group;\n" ::: "memory");
    if (qt >= 1) load_tile(1, 1);
    asm volatile("cp.async.commit_group;\n" ::: "memory");

    for (int kt = 0; kt <= qt; kt++) {
        asm volatile("cp.async.wait_group 1;\n" ::: "memory");
        __syncthreads();
        const int st = kt & 1;
        uint32_t ks = sb + st * FSTAGE;
        uint32_t vh = ks + KS_BYTES;
        uint32_t vl = vh + VS_BYTES;

        // ---- S = Q'.K'^T (8 chunks, K'=128)
        float sacc[8][4];
#pragma unroll
        for (int t = 0; t < 8; t++)
#pragma unroll
            for (int r = 0; r < 4; r++) sacc[t][r] = 0.f;
#pragma unroll
        for (int ck = 0; ck < 8; ck++) {
            uint32_t bfr[4][4];
#pragma unroll
            for (int nj = 0; nj < 4; nj++) {
                uint32_t addr = ks + (nj * 16 + b_row_off) * KPITCH + ck * 32 + b_kch * 16;
                LDMATRIX_X4(bfr[nj][0], bfr[nj][1], bfr[nj][2], bfr[nj][3], addr);
            }
#pragma unroll
            for (int ni = 0; ni < 8; ni++)
                MMA_F16(sacc[ni], qf[ck][0], qf[ck][1], qf[ck][2], qf[ck][3],
                        bfr[ni >> 1][(ni & 1) * 2 + 0], bfr[ni >> 1][(ni & 1) * 2 + 1]);
        }

        // ---- causal mask on diagonal tile
        if (kt == qt) {
            int rq0 = warp * 16 + gr;
            int rq1 = rq0 + 8;
#pragma unroll
            for (int t = 0; t < 8; t++) {
                int c0 = 8 * t + 2 * tc;
                if (c0 > rq0)     sacc[t][0] = -1e30f;
                if (c0 + 1 > rq0) sacc[t][1] = -1e30f;
                if (c0 > rq1)     sacc[t][2] = -1e30f;
                if (c0 + 1 > rq1) sacc[t][3] = -1e30f;
            }
        }

        // ---- online softmax (base-2, quad reductions)
        float mx0 = -1e30f, mx1 = -1e30f;
#pragma unroll
        for (int t = 0; t < 8; t++) {
            mx0 = fmaxf(mx0, fmaxf(sacc[t][0], sacc[t][1]));
            mx1 = fmaxf(mx1, fmaxf(sacc[t][2], sacc[t][3]));
        }
        mx0 = fmaxf(mx0, __shfl_xor_sync(0xffffffffu, mx0, 1));
        mx0 = fmaxf(mx0, __shfl_xor_sync(0xffffffffu, mx0, 2));
        mx1 = fmaxf(mx1, __shfl_xor_sync(0xffffffffu, mx1, 1));
        mx1 = fmaxf(mx1, __shfl_xor_sync(0xffffffffu, mx1, 2));
        float mn0 = fmaxf(m0, mx0), mn1 = fmaxf(m1, mx1);
        float cr0 = fast_exp2(m0 - mn0), cr1 = fast_exp2(m1 - mn1);
        m0 = mn0; m1 = mn1;
        l0 *= cr0; l1 *= cr1;
#pragma unroll
        for (int t = 0; t < 8; t++) {
            oacc[t][0] *= cr0; oacc[t][1] *= cr0;
            oacc[t][2] *= cr1; oacc[t][3] *= cr1;
        }
        uint32_t phi[8][2];
        float rs0 = 0.f, rs1 = 0.f;
#pragma unroll
        for (int t = 0; t < 8; t++) {
            float p0 = fast_exp2(sacc[t][0] - m0);
            float p1 = fast_exp2(sacc[t][1] - m0);
            float p2 = fast_exp2(sacc[t][2] - m1);
            float p3 = fast_exp2(sacc[t][3] - m1);
            rs0 += p0 + p1; rs1 += p2 + p3;
            phi[t][0] = pack_f16x2(p0, p1);
            phi[t][1] = pack_f16x2(p2, p3);
        }
        rs0 += __shfl_xor_sync(0xffffffffu, rs0, 1);
        rs0 += __shfl_xor_sync(0xffffffffu, rs0, 2);
        rs1 += __shfl_xor_sync(0xffffffffu, rs1, 1);
        rs1 += __shfl_xor_sync(0xffffffffu, rs1, 2);
        l0 += rs0; l1 += rs1;

        // ---- PV: O += P.Vhi + P.Vlo
#pragma unroll
        for (int ck = 0; ck < 4; ck++) {
            uint32_t aph[4] = { phi[2 * ck][0], phi[2 * ck][1],
                                phi[2 * ck + 1][0], phi[2 * ck + 1][1] };
            uint32_t vhf[4][4], vlf[4][4];
#pragma unroll
            for (int dt = 0; dt < 4; dt++) {
                uint32_t ah = vh + (dt * 16 + b_row_off) * VPITCH + ck * 32 + b_kch * 16;
                uint32_t al = vl + (dt * 16 + b_row_off) * VPITCH + ck * 32 + b_kch * 16;
                LDMATRIX_X4(vhf[dt][0], vhf[dt][1], vhf[dt][2], vhf[dt][3], ah);
                LDMATRIX_X4(vlf[dt][0], vlf[dt][1], vlf[dt][2], vlf[dt][3], al);
            }
#pragma unroll
            for (int ni = 0; ni < 8; ni++) {
                MMA_F16(oacc[ni], aph[0], aph[1], aph[2], aph[3],
                        vhf[ni >> 1][(ni & 1) * 2 + 0], vhf[ni >> 1][(ni & 1) * 2 + 1]);
                MMA_F16(oacc[ni], aph[0], aph[1], aph[2], aph[3],
                        vlf[ni >> 1][(ni & 1) * 2 + 0], vlf[ni >> 1][(ni & 1) * 2 + 1]);
            }
        }

        __syncthreads();
        if (kt + 2 <= qt) load_tile(kt + 2, st);
        asm volatile("cp.async.commit_group;\n" ::: "memory");
    }

    // ---- epilogue: write plain fp16 attention output into aP [M x 1024]
    const float inv0 = 1.f / l0, inv1 = 1.f / l1;
    const int qr0 = q0 + warp * 16 + gr;
    const int qr1 = qr0 + 8;
#pragma unroll
    for (int t = 0; t < 8; t++) {
        int col = h * DHEAD + 8 * t + 2 * tc;
        *(__half2*)(aP + ((size_t)(b * SEQ + qr0)) * DMODEL + col) =
            __half2(__float2half_rn(oacc[t][0] * inv0), __float2half_rn(oacc[t][1] * inv0));
        *(__half2*)(aP + ((size_t)(b * SEQ + qr1)) * DMODEL + col) =
            __half2(__float2half_rn(oacc[t][2] * inv1), __float2half_rn(oacc[t][3] * inv1));
    }
}

// ---------------------------------------------------------------------------
extern "C" void kernel_launch(void* const* d_in, const int* in_sizes, int n_in,
                              void* d_out, int out_size)
{
    const float* x     = (const float*)d_in[0];
    const float* W_qkv = (const float*)d_in[1];
    const float* W_o   = (const float*)d_in[2];
    float* out = (float*)d_out;

    float *vf;
    __half *aP, *w1P, *w2P, *qp, *kp, *vthi, *vtlo;
    cudaGetSymbolAddress((void**)&vf, g_vf);
    cudaGetSymbolAddress((void**)&aP, g_aP);
    cudaGetSymbolAddress((void**)&w1P, g_w1P);
    cudaGetSymbolAddress((void**)&w2P, g_w2P);
    cudaGetSymbolAddress((void**)&qp, g_qp);
    cudaGetSymbolAddress((void**)&kp, g_kp);
    cudaGetSymbolAddress((void**)&vthi, g_vthi);
    cudaGetSymbolAddress((void**)&vtlo, g_vtlo);

    cudaFuncSetAttribute(flash_mma_kernel,
                         cudaFuncAttributeMaxDynamicSharedMemorySize, FSMEM);
    cudaFuncSetAttribute(mma_gemm_kernel,
                         cudaFuncAttributeMaxDynamicSharedMemorySize, GSMEM);
    cudaFuncSetAttribute(mma_gemm_qkv_kernel,
                         cudaFuncAttributeMaxDynamicSharedMemorySize, GSMEM);

    // conversions
    {
        dim3 g(QKV_COLS / 32, DMODEL / 32);
        conv_weight_kernel<<<g, dim3(32, 8)>>>(W_qkv, w1P, QKV_COLS);
    }
    {
        dim3 g(DMODEL / 32, DMODEL / 32);
        conv_weight_kernel<<<g, dim3(32, 8)>>>(W_o, w2P, DMODEL);
    }
    conv_act_kernel<<<(MROWS * DMODEL / 4) / 256, 256>>>(x, aP);

    // 1) QKV GEMM with fused Q'/K'/V epilogue   (M=4096, N=3072, K=1024 fp16)
    {
        dim3 grid(QKV_COLS / 128, MROWS / 128);
        mma_gemm_qkv_kernel<<<grid, 128, GSMEM>>>(aP, w1P, qp, kp, vf,
                                                  QKV_COLS, DMODEL);
    }
    // V transpose/split
    {
        dim3 g(SEQ / 32, 2, BATCH * NHEAD);
        vt_conv_kernel<<<g, dim3(32, 8)>>>(vf, vthi, vtlo);
    }
    // 2) flash attention (writes fp16 aP for out-proj)
    {
        dim3 grid(SEQ / 64, NHEAD, BATCH);
        flash_mma_kernel<<<grid, 128, FSMEM>>>(qp, kp, vthi, vtlo, aP);
    }
    // 3) out = attn_out @ W_o   (M=4096, N=1024, K=1024 fp16)
    {
        dim3 grid(DMODEL / 128, MROWS / 128);
        mma_gemm_kernel<<<grid, 128, GSMEM>>>(aP, w2P, out, DMODEL, DMODEL);
    }
}

// round 9
// speedup vs baseline: 7.8725x; 1.2712x over previous
#include <cuda_runtime.h>
#include <cuda_bf16.h>
#include <cuda_fp16.h>
#include <math.h>
#include <stdint.h>

// Problem constants
#define BATCH 2
#define SEQ   2048
#define DMODEL 1024
#define NHEAD 16
#define DHEAD 64
#define MROWS (BATCH * SEQ)           // 4096
#define QKV_COLS (3 * DMODEL)         // 3072
#define QSCALE 0.18033688f            // 0.125 * log2(e)

// ---------------------------------------------------------------------------
// Scratch (static device globals; allocations are forbidden)
// ---------------------------------------------------------------------------
__device__ __half g_vh[(size_t)MROWS * DMODEL];            // 8.4 MB (V fp16 row-major)
__device__ __half g_aP[(size_t)MROWS * DMODEL];            // 8.4 MB (A fp16, both GEMMs)
__device__ __half g_w1P[(size_t)QKV_COLS * DMODEL];        // 6.3 MB (W_qkv^T fp16)
__device__ __half g_w2P[(size_t)DMODEL * DMODEL];          // 2.1 MB (W_o^T fp16)
// Attention operands (plain fp16)
__device__ __half g_qp[(size_t)BATCH * NHEAD * SEQ * DHEAD];  // 8.4 MB
__device__ __half g_kp[(size_t)BATCH * NHEAD * SEQ * DHEAD];  // 8.4 MB
__device__ __half g_vt[(size_t)BATCH * NHEAD * DHEAD * SEQ];  // 8.4 MB

__device__ __forceinline__ uint32_t smem_u32(const void* p) {
    uint32_t a;
    asm("{ .reg .u64 t; cvta.to.shared.u64 t, %1; cvt.u32.u64 %0, t; }" : "=r"(a) : "l"(p));
    return a;
}
__device__ __forceinline__ float fast_exp2(float x) {
    float y; asm("ex2.approx.ftz.f32 %0, %1;" : "=f"(y) : "f"(x)); return y;
}
// pack fp16x2: low half = lo, high half = hi
__device__ __forceinline__ uint32_t pack_f16x2(float lo, float hi) {
    uint32_t r; asm("cvt.rn.f16x2.f32 %0, %1, %2;" : "=r"(r) : "f"(hi), "f"(lo)); return r;
}

#define LDMATRIX_X4(r0, r1, r2, r3, addr) \
    asm volatile("ldmatrix.sync.aligned.m8n8.x4.shared.b16 {%0,%1,%2,%3}, [%4];" \
        : "=r"(r0), "=r"(r1), "=r"(r2), "=r"(r3) : "r"(addr))

#define MMA_F16(acc, a0, a1, a2, a3, b0, b1) \
    asm volatile( \
        "mma.sync.aligned.m16n8k16.row.col.f32.f16.f16.f32 " \
        "{%0,%1,%2,%3}, {%4,%5,%6,%7}, {%8,%9}, {%0,%1,%2,%3};" \
        : "+f"((acc)[0]), "+f"((acc)[1]), "+f"((acc)[2]), "+f"((acc)[3]) \
        : "r"(a0), "r"(a1), "r"(a2), "r"(a3), "r"(b0), "r"(b1))

// ---------------------------------------------------------------------------
// Conversion: fp32 activations (M x 1024) -> fp16 (M x 1024)
// ---------------------------------------------------------------------------
__global__ void conv_act_kernel(const float* __restrict__ in,
                                __half* __restrict__ out)
{
    size_t j = (size_t)blockIdx.x * blockDim.x + threadIdx.x;
    float4 v = *(const float4*)(in + 4 * j);
    __half2* o = (__half2*)(out + 4 * j);
    o[0] = __half2(__float2half_rn(v.x), __float2half_rn(v.y));
    o[1] = __half2(__float2half_rn(v.z), __float2half_rn(v.w));
}

// ---------------------------------------------------------------------------
// Conversion: W (K x N fp32, row-major) -> B' (N x K fp16) transpose-cast
// ---------------------------------------------------------------------------
__global__ void conv_weight_kernel(const float* __restrict__ W,
                                   __half* __restrict__ out,
                                   int N)
{
    __shared__ float t[32][33];
    const int tx = threadIdx.x, ty = threadIdx.y;
#pragma unroll
    for (int i = 0; i < 4; i++) {
        int k = blockIdx.y * 32 + ty + 8 * i;
        int n = blockIdx.x * 32 + tx;
        t[ty + 8 * i][tx] = W[(size_t)k * N + n];
    }
    __syncthreads();
#pragma unroll
    for (int i = 0; i < 4; i++) {
        int nl = ty + 8 * i;
        int n = blockIdx.x * 32 + nl;
        out[(size_t)n * DMODEL + blockIdx.y * 32 + tx] = __float2half_rn(t[tx][nl]);
    }
}

// ---------------------------------------------------------------------------
// Conversion: V (fp16 [b,t,1024]) -> transposed Vt[b,h,d,t] fp16.
// ---------------------------------------------------------------------------
__global__ void vt_conv_kernel(const __half* __restrict__ vh,
                               __half* __restrict__ vt)
{
    __shared__ __half sm[32][33];
    const int tx = threadIdx.x, ty = threadIdx.y;
    const int t0 = blockIdx.x * 32;
    const int dblk = blockIdx.y;
    const int bh = blockIdx.z;
    const int b = bh >> 4, h = bh & 15;
#pragma unroll
    for (int i = 0; i < 4; i++) {
        int tl = ty + 8 * i;
        sm[tl][tx] = vh[((size_t)(b * SEQ + t0 + tl)) * DMODEL +
                        h * DHEAD + dblk * 32 + tx];
    }
    __syncthreads();
#pragma unroll
    for (int i = 0; i < 4; i++) {
        int dl = ty + 8 * i;
        size_t o = ((size_t)(bh * DHEAD + dblk * 32 + dl)) * SEQ + t0 + tx;
        vt[o] = sm[tx][dl];
    }
}

// ---------------------------------------------------------------------------
// GEMM mainloop (fp16, CTA 128x128, 4 warps 64x64, BK=64,
// 3-stage cp.async, one sync per iter).
// ---------------------------------------------------------------------------
#define GBK 64
#define ROWB 144                     // padded row bytes (64 fp16 = 128B data)
#define STILE (128 * ROWB)           // 18432 B
#define GSTAGE (2 * STILE)           // 36864 B
#define GSMEM (3 * GSTAGE)           // 110592 B

#define GEMM_PROLOGUE_AND_LOOP()                                               \
    const int tid = threadIdx.x;                                               \
    const int warp = tid >> 5;                                                 \
    const int lane = tid & 31;                                                 \
    const int bm = blockIdx.y * 128;                                           \
    const int bn = blockIdx.x * 128;                                           \
    const int wm0 = (warp >> 1) * 64;                                          \
    const int wn0 = (warp & 1) * 64;                                           \
    const int a_row_off = (lane & 7) + ((lane >> 3) & 1) * 8;                  \
    const int a_kch = (lane >> 4);                                             \
    const int b_row_off = (lane & 7) + ((lane >> 4) & 1) * 8;                  \
    const int b_kch = (lane >> 3) & 1;                                         \
    const uint32_t sbase = smem_u32(gsm);                                      \
    float acc[4][8][4];                                                        \
    _Pragma("unroll")                                                          \
    for (int mi = 0; mi < 4; mi++)                                             \
        _Pragma("unroll")                                                      \
        for (int ni = 0; ni < 8; ni++)                                         \
            _Pragma("unroll")                                                  \
            for (int r = 0; r < 4; r++) acc[mi][ni][r] = 0.f;                  \
    const int NIT = K / GBK;                                                   \
    auto load_stage = [&](int st, int k0) {                                    \
        uint32_t base = sbase + st * GSTAGE;                                   \
        _Pragma("unroll")                                                      \
        for (int i = 0; i < 8; i++) {                                          \
            int c = tid + i * 128;                                             \
            int row = c >> 3, ch = c & 7;                                      \
            uint32_t dA = base + row * ROWB + ch * 16;                         \
            uint32_t dB = dA + STILE;                                          \
            const __half* pA = A + (size_t)(bm + row) * K + k0 + ch * 8;       \
            const __half* pB = B + (size_t)(bn + row) * K + k0 + ch * 8;       \
            asm volatile("cp.async.cg.shared.global [%0], [%1], 16;\n" :: "r"(dA), "l"(pA) : "memory"); \
            asm volatile("cp.async.cg.shared.global [%0], [%1], 16;\n" :: "r"(dB), "l"(pB) : "memory"); \
        }                                                                      \
    };                                                                         \
    load_stage(0, 0);                                                          \
    asm volatile("cp.async.commit_group;\n" ::: "memory");                     \
    load_stage(1, GBK);                                                        \
    asm volatile("cp.async.commit_group;\n" ::: "memory");                     \
    int st = 0;                                                                \
    for (int it = 0; it < NIT; it++) {                                         \
        asm volatile("cp.async.wait_group 1;\n" ::: "memory");                 \
        __syncthreads();                                                       \
        if (it + 2 < NIT) {                                                    \
            int st2 = st + 2 >= 3 ? st - 1 : st + 2;                           \
            load_stage(st2, (it + 2) * GBK);                                   \
        }                                                                      \
        asm volatile("cp.async.commit_group;\n" ::: "memory");                 \
        uint32_t sA = sbase + st * GSTAGE;                                     \
        uint32_t sB = sA + STILE;                                              \
        _Pragma("unroll")                                                      \
        for (int ks = 0; ks < 4; ks++) {                                       \
            uint32_t af[4][4];                                                 \
            _Pragma("unroll")                                                  \
            for (int mi = 0; mi < 4; mi++) {                                   \
                uint32_t addr = sA + (wm0 + mi * 16 + a_row_off) * ROWB +      \
                                (ks * 2 + a_kch) * 16;                         \
                LDMATRIX_X4(af[mi][0], af[mi][1], af[mi][2], af[mi][3], addr); \
            }                                                                  \
            uint32_t bfr[4][4];                                                \
            _Pragma("unroll")                                                  \
            for (int nj = 0; nj < 4; nj++) {                                   \
                uint32_t addr = sB + (wn0 + nj * 16 + b_row_off) * ROWB +      \
                                (ks * 2 + b_kch) * 16;                         \
                LDMATRIX_X4(bfr[nj][0], bfr[nj][1], bfr[nj][2], bfr[nj][3], addr); \
            }                                                                  \
            _Pragma("unroll")                                                  \
            for (int mi = 0; mi < 4; mi++)                                     \
                _Pragma("unroll")                                              \
                for (int ni = 0; ni < 8; ni++)                                 \
                    MMA_F16(acc[mi][ni], af[mi][0], af[mi][1], af[mi][2], af[mi][3], \
                            bfr[ni >> 1][(ni & 1) * 2 + 0], bfr[ni >> 1][(ni & 1) * 2 + 1]); \
        }                                                                      \
        st = (st + 1 == 3) ? 0 : st + 1;                                       \
    }

// ---------------------------------------------------------------------------
// GEMM #2 (out-projection): plain fp32 epilogue.
// ---------------------------------------------------------------------------
__global__ void __launch_bounds__(128, 2) mma_gemm_kernel(
    const __half* __restrict__ A, const __half* __restrict__ B,
    float* __restrict__ C, int N, int K)
{
    extern __shared__ char gsm[];
    GEMM_PROLOGUE_AND_LOOP()

    const int gr = lane >> 2;
    const int tc = (lane & 3) * 2;
#pragma unroll
    for (int mi = 0; mi < 4; mi++) {
#pragma unroll
        for (int ni = 0; ni < 8; ni++) {
            size_t r0 = (size_t)(bm + wm0 + mi * 16 + gr);
            int col = bn + wn0 + ni * 8 + tc;
            *(float2*)&C[r0 * N + col] = make_float2(acc[mi][ni][0], acc[mi][ni][1]);
            *(float2*)&C[(r0 + 8) * N + col] = make_float2(acc[mi][ni][2], acc[mi][ni][3]);
        }
    }
}

// ---------------------------------------------------------------------------
// GEMM #1 (QKV): fused epilogue writes fp16 Q (scaled) / K [b,h,t,64] + V fp16.
// bn in [0,1024) -> Q, [1024,2048) -> K, [2048,3072) -> V.
// ---------------------------------------------------------------------------
__global__ void __launch_bounds__(128, 2) mma_gemm_qkv_kernel(
    const __half* __restrict__ A, const __half* __restrict__ B,
    __half* __restrict__ qp, __half* __restrict__ kp,
    __half* __restrict__ vh_out, int N, int K)
{
    extern __shared__ char gsm[];
    GEMM_PROLOGUE_AND_LOOP()

    const int gr = lane >> 2;
    const int tc = (lane & 3) * 2;
    const int sec = bn >> 10;                 // 0=Q, 1=K, 2=V
    const int colbase = (bn & 1023) + wn0;

#pragma unroll
    for (int mi = 0; mi < 4; mi++) {
#pragma unroll
        for (int rr = 0; rr < 2; rr++) {
            const int row = bm + wm0 + mi * 16 + gr + rr * 8;
            const int b = row >> 11;
            const int t = row & (SEQ - 1);
#pragma unroll
            for (int ni = 0; ni < 8; ni++) {
                const int col = colbase + ni * 8 + tc;    // within section
                float v0 = acc[mi][ni][rr * 2 + 0];
                float v1 = acc[mi][ni][rr * 2 + 1];
                if (sec == 2) {
                    *(__half2*)&vh_out[(size_t)(b * SEQ + t) * DMODEL + col] =
                        __half2(__float2half_rn(v0), __float2half_rn(v1));
                } else {
                    const int h = col >> 6;
                    const int d = col & 63;
                    size_t base = ((size_t)((b * NHEAD + h) * SEQ + t)) * DHEAD + d;
                    if (sec == 0) { v0 *= QSCALE; v1 *= QSCALE; }
                    __half2 val = __half2(__float2half_rn(v0), __float2half_rn(v1));
                    *(__half2*)((sec == 0 ? qp : kp) + base) = val;
                }
            }
        }
    }
}

// ---------------------------------------------------------------------------
// Tensor-core flash attention (FA2), causal, plain fp16.
// CTA: 128 queries x 1 head; 8 warps (each m16 x 64-key tile), 256 threads.
// K-tiles of 64 keys, double-buffered K+Vt smem via cp.async.
// Epilogue writes plain fp16 output row for GEMM #2 A-operand.
// ---------------------------------------------------------------------------
#define KPITCH 144                  // 64 fp16 = 128B data + 16 pad
#define KS_BYTES (64 * KPITCH)      // 9216
#define FSTAGE (2 * KS_BYTES)       // 18432 (K + Vt)
#define FSMEM (2 * FSTAGE)          // 36864

__global__ void __launch_bounds__(256, 2) flash_mma_kernel(
    const __half* __restrict__ qp, const __half* __restrict__ kp,
    const __half* __restrict__ vt,
    __half* __restrict__ aP)
{
    extern __shared__ char fsm[];
    const int tid = threadIdx.x;
    const int warp = tid >> 5;
    const int lane = tid & 31;
    const int qt = gridDim.x - 1 - blockIdx.x;      // heavy tiles first
    const int h = blockIdx.y;
    const int b = blockIdx.z;
    const int bh = b * NHEAD + h;
    const int q0 = qt * 128;

    const uint32_t sb = smem_u32(fsm);
    const int gr = lane >> 2;
    const int tc = lane & 3;
    const int a_row_off = (lane & 7) + ((lane >> 3) & 1) * 8;
    const int a_kch = lane >> 4;
    const int b_row_off = (lane & 7) + ((lane >> 4) & 1) * 8;
    const int b_kch = (lane >> 3) & 1;

    // ---- stage Q tile (128 x 64 fp16) into smem, extract A fragments
    {
        const __half* qsrc = qp + ((size_t)(bh * SEQ + q0)) * DHEAD;
#pragma unroll
        for (int i = 0; i < 4; i++) {
            int c = i * 256 + tid;               // 0..1023 (16B chunks)
            int row = c >> 3, ch = c & 7;
            uint32_t dst = sb + row * KPITCH + ch * 16;
            const __half* src = qsrc + (size_t)row * DHEAD + ch * 8;
            asm volatile("cp.async.cg.shared.global [%0], [%1], 16;\n" :: "r"(dst), "l"(src) : "memory");
        }
        asm volatile("cp.async.commit_group;\ncp.async.wait_group 0;\n" ::: "memory");
        __syncthreads();
    }
    uint32_t qf[4][4];
#pragma unroll
    for (int ck = 0; ck < 4; ck++) {
        uint32_t addr = sb + (warp * 16 + a_row_off) * KPITCH + ck * 32 + a_kch * 16;
        LDMATRIX_X4(qf[ck][0], qf[ck][1], qf[ck][2], qf[ck][3], addr);
    }
    __syncthreads();

    float oacc[8][4];
#pragma unroll
    for (int t = 0; t < 8; t++)
#pragma unroll
        for (int r = 0; r < 4; r++) oacc[t][r] = 0.f;
    float m0 = -1e30f, m1 = -1e30f, l0 = 0.f, l1 = 0.f;

    const int nkt = 2 * qt + 2;                 // k-tiles (64 keys each)

    auto load_tile = [&](int kt, int st) {
        const int kt0 = kt * 64;
        uint32_t ks = sb + st * FSTAGE;
        uint32_t vs = ks + KS_BYTES;
        const __half* ksrc = kp + ((size_t)(bh * SEQ + kt0)) * DHEAD;
#pragma unroll
        for (int i = 0; i < 2; i++) {
            int c = i * 256 + tid;               // 0..511
            int row = c >> 3, ch = c & 7;
            uint32_t dst = ks + row * KPITCH + ch * 16;
            const __half* src = ksrc + (size_t)row * DHEAD + ch * 8;
            asm volatile("cp.async.cg.shared.global [%0], [%1], 16;\n" :: "r"(dst), "l"(src) : "memory");
        }
#pragma unroll
        for (int i = 0; i < 2; i++) {
            int c = i * 256 + tid;
            int row = c >> 3, ch = c & 7;        // row = d
            size_t so = ((size_t)(bh * DHEAD + row)) * SEQ + kt0 + ch * 8;
            uint32_t dst = vs + row * KPITCH + ch * 16;
            asm volatile("cp.async.cg.shared.global [%0], [%1], 16;\n" :: "r"(dst), "l"(vt + so) : "memory");
        }
    };

    load_tile(0, 0);
    asm volatile("cp.async.commit_group;\n" ::: "memory");
    load_tile(1, 1);
    asm volatile("cp.async.commit_group;\n" ::: "memory");

    for (int kt = 0; kt < nkt; kt++) {
        asm volatile("cp.async.wait_group 1;\n" ::: "memory");
        __syncthreads();
        const int st = kt & 1;
        uint32_t ks = sb + st * FSTAGE;
        uint32_t vs = ks + KS_BYTES;

        // ---- S = Q.K^T  (4 k16 chunks over DHEAD=64)
        float sacc[8][4];
#pragma unroll
        for (int t = 0; t < 8; t++)
#pragma unroll
            for (int r = 0; r < 4; r++) sacc[t][r] = 0.f;
#pragma unroll
        for (int ck = 0; ck < 4; ck++) {
            uint32_t bfr[4][4];
#pragma unroll
            for (int nj = 0; nj < 4; nj++) {
                uint32_t addr = ks + (nj * 16 + b_row_off) * KPITCH + ck * 32 + b_kch * 16;
                LDMATRIX_X4(bfr[nj][0], bfr[nj][1], bfr[nj][2], bfr[nj][3], addr);
            }
#pragma unroll
            for (int ni = 0; ni < 8; ni++)
                MMA_F16(sacc[ni], qf[ck][0], qf[ck][1], qf[ck][2], qf[ck][3],
                        bfr[ni >> 1][(ni & 1) * 2 + 0], bfr[ni >> 1][(ni & 1) * 2 + 1]);
        }

        // ---- causal mask on the two diagonal-spanning k-tiles
        if (kt >= nkt - 2) {
            const int kt0 = kt * 64;
            int rq0 = q0 + warp * 16 + gr;
            int rq1 = rq0 + 8;
#pragma unroll
            for (int t = 0; t < 8; t++) {
                int c0 = kt0 + 8 * t + 2 * tc;
                if (c0 > rq0)     sacc[t][0] = -1e30f;
                if (c0 + 1 > rq0) sacc[t][1] = -1e30f;
                if (c0 > rq1)     sacc[t][2] = -1e30f;
                if (c0 + 1 > rq1) sacc[t][3] = -1e30f;
            }
        }

        // ---- online softmax (base-2, quad reductions)
        float mx0 = -1e30f, mx1 = -1e30f;
#pragma unroll
        for (int t = 0; t < 8; t++) {
            mx0 = fmaxf(mx0, fmaxf(sacc[t][0], sacc[t][1]));
            mx1 = fmaxf(mx1, fmaxf(sacc[t][2], sacc[t][3]));
        }
        mx0 = fmaxf(mx0, __shfl_xor_sync(0xffffffffu, mx0, 1));
        mx0 = fmaxf(mx0, __shfl_xor_sync(0xffffffffu, mx0, 2));
        mx1 = fmaxf(mx1, __shfl_xor_sync(0xffffffffu, mx1, 1));
        mx1 = fmaxf(mx1, __shfl_xor_sync(0xffffffffu, mx1, 2));
        float mn0 = fmaxf(m0, mx0), mn1 = fmaxf(m1, mx1);
        float cr0 = fast_exp2(m0 - mn0), cr1 = fast_exp2(m1 - mn1);
        m0 = mn0; m1 = mn1;
        l0 *= cr0; l1 *= cr1;
#pragma unroll
        for (int t = 0; t < 8; t++) {
            oacc[t][0] *= cr0; oacc[t][1] *= cr0;
            oacc[t][2] *= cr1; oacc[t][3] *= cr1;
        }
        uint32_t phi[8][2];
        float rs0 = 0.f, rs1 = 0.f;
#pragma unroll
        for (int t = 0; t < 8; t++) {
            float p0 = fast_exp2(sacc[t][0] - m0);
            float p1 = fast_exp2(sacc[t][1] - m0);
            float p2 = fast_exp2(sacc[t][2] - m1);
            float p3 = fast_exp2(sacc[t][3] - m1);
            rs0 += p0 + p1; rs1 += p2 + p3;
            phi[t][0] = pack_f16x2(p0, p1);
            phi[t][1] = pack_f16x2(p2, p3);
        }
        rs0 += __shfl_xor_sync(0xffffffffu, rs0, 1);
        rs0 += __shfl_xor_sync(0xffffffffu, rs0, 2);
        rs1 += __shfl_xor_sync(0xffffffffu, rs1, 1);
        rs1 += __shfl_xor_sync(0xffffffffu, rs1, 2);
        l0 += rs0; l1 += rs1;

        // ---- PV: O += P.Vt  (4 key-chunks of 16)
#pragma unroll
        for (int ck = 0; ck < 4; ck++) {
            uint32_t aph[4] = { phi[2 * ck][0], phi[2 * ck][1],
                                phi[2 * ck + 1][0], phi[2 * ck + 1][1] };
            uint32_t vfr[4][4];
#pragma unroll
            for (int dt = 0; dt < 4; dt++) {
                uint32_t addr = vs + (dt * 16 + b_row_off) * KPITCH + ck * 32 + b_kch * 16;
                LDMATRIX_X4(vfr[dt][0], vfr[dt][1], vfr[dt][2], vfr[dt][3], addr);
            }
#pragma unroll
            for (int ni = 0; ni < 8; ni++)
                MMA_F16(oacc[ni], aph[0], aph[1], aph[2], aph[3],
                        vfr[ni >> 1][(ni & 1) * 2 + 0], vfr[ni >> 1][(ni & 1) * 2 + 1]);
        }

        __syncthreads();
        if (kt + 2 < nkt) load_tile(kt + 2, st);
        asm volatile("cp.async.commit_group;\n" ::: "memory");
    }

    // ---- epilogue: write plain fp16 attention output into aP [M x 1024]
    const float inv0 = 1.f / l0, inv1 = 1.f / l1;
    const int qr0 = q0 + warp * 16 + gr;
    const int qr1 = qr0 + 8;
#pragma unroll
    for (int t = 0; t < 8; t++) {
        int col = h * DHEAD + 8 * t + 2 * tc;
        *(__half2*)(aP + ((size_t)(b * SEQ + qr0)) * DMODEL + col) =
            __half2(__float2half_rn(oacc[t][0] * inv0), __float2half_rn(oacc[t][1] * inv0));
        *(__half2*)(aP + ((size_t)(b * SEQ + qr1)) * DMODEL + col) =
            __half2(__float2half_rn(oacc[t][2] * inv1), __float2half_rn(oacc[t][3] * inv1));
    }
}

// ---------------------------------------------------------------------------
extern "C" void kernel_launch(void* const* d_in, const int* in_sizes, int n_in,
                              void* d_out, int out_size)
{
    const float* x     = (const float*)d_in[0];
    const float* W_qkv = (const float*)d_in[1];
    const float* W_o   = (const float*)d_in[2];
    float* out = (float*)d_out;

    __half *vh, *aP, *w1P, *w2P, *qp, *kp, *vt;
    cudaGetSymbolAddress((void**)&vh, g_vh);
    cudaGetSymbolAddress((void**)&aP, g_aP);
    cudaGetSymbolAddress((void**)&w1P, g_w1P);
    cudaGetSymbolAddress((void**)&w2P, g_w2P);
    cudaGetSymbolAddress((void**)&qp, g_qp);
    cudaGetSymbolAddress((void**)&kp, g_kp);
    cudaGetSymbolAddress((void**)&vt, g_vt);

    cudaFuncSetAttribute(flash_mma_kernel,
                         cudaFuncAttributeMaxDynamicSharedMemorySize, FSMEM);
    cudaFuncSetAttribute(mma_gemm_kernel,
                         cudaFuncAttributeMaxDynamicSharedMemorySize, GSMEM);
    cudaFuncSetAttribute(mma_gemm_qkv_kernel,
                         cudaFuncAttributeMaxDynamicSharedMemorySize, GSMEM);

    // conversions
    {
        dim3 g(QKV_COLS / 32, DMODEL / 32);
        conv_weight_kernel<<<g, dim3(32, 8)>>>(W_qkv, w1P, QKV_COLS);
    }
    {
        dim3 g(DMODEL / 32, DMODEL / 32);
        conv_weight_kernel<<<g, dim3(32, 8)>>>(W_o, w2P, DMODEL);
    }
    conv_act_kernel<<<(MROWS * DMODEL / 4) / 256, 256>>>(x, aP);

    // 1) QKV GEMM with fused Q/K/V fp16 epilogue   (M=4096, N=3072, K=1024)
    {
        dim3 grid(QKV_COLS / 128, MROWS / 128);
        mma_gemm_qkv_kernel<<<grid, 128, GSMEM>>>(aP, w1P, qp, kp, vh,
                                                  QKV_COLS, DMODEL);
    }
    // V transpose (fp16 -> fp16)
    {
        dim3 g(SEQ / 32, 2, BATCH * NHEAD);
        vt_conv_kernel<<<g, dim3(32, 8)>>>(vh, vt);
    }
    // 2) flash attention (q-tile 128, writes fp16 aP for out-proj)
    {
        dim3 grid(SEQ / 128, NHEAD, BATCH);
        flash_mma_kernel<<<grid, 256, FSMEM>>>(qp, kp, vt, aP);
    }
    // 3) out = attn_out @ W_o   (M=4096, N=1024, K=1024)
    {
        dim3 grid(DMODEL / 128, MROWS / 128);
        mma_gemm_kernel<<<grid, 128, GSMEM>>>(aP, w2P, out, DMODEL, DMODEL);
    }
}

// round 10
// speedup vs baseline: 8.1990x; 1.0415x over previous
#include <cuda_runtime.h>
#include <cuda_bf16.h>
#include <cuda_fp16.h>
#include <math.h>
#include <stdint.h>

// Problem constants
#define BATCH 2
#define SEQ   2048
#define DMODEL 1024
#define NHEAD 16
#define DHEAD 64
#define MROWS (BATCH * SEQ)           // 4096
#define QKV_COLS (3 * DMODEL)         // 3072
#define QSCALE 0.18033688f            // 0.125 * log2(e)

// ---------------------------------------------------------------------------
// Scratch (static device globals; allocations are forbidden)
// ---------------------------------------------------------------------------
__device__ __half g_aP[(size_t)MROWS * DMODEL];            // 8.4 MB (A fp16, both GEMMs)
__device__ __half g_w1P[(size_t)QKV_COLS * DMODEL];        // 6.3 MB (W_qkv^T fp16)
__device__ __half g_w2P[(size_t)DMODEL * DMODEL];          // 2.1 MB (W_o^T fp16)
// Attention operands (plain fp16, all [b,h,t,64])
__device__ __half g_qp[(size_t)BATCH * NHEAD * SEQ * DHEAD];  // 8.4 MB
__device__ __half g_kp[(size_t)BATCH * NHEAD * SEQ * DHEAD];  // 8.4 MB
__device__ __half g_vp[(size_t)BATCH * NHEAD * SEQ * DHEAD];  // 8.4 MB

__device__ __forceinline__ uint32_t smem_u32(const void* p) {
    uint32_t a;
    asm("{ .reg .u64 t; cvta.to.shared.u64 t, %1; cvt.u32.u64 %0, t; }" : "=r"(a) : "l"(p));
    return a;
}
__device__ __forceinline__ float fast_exp2(float x) {
    float y; asm("ex2.approx.ftz.f32 %0, %1;" : "=f"(y) : "f"(x)); return y;
}
// pack fp16x2: low half = lo, high half = hi
__device__ __forceinline__ uint32_t pack_f16x2(float lo, float hi) {
    uint32_t r; asm("cvt.rn.f16x2.f32 %0, %1, %2;" : "=r"(r) : "f"(hi), "f"(lo)); return r;
}

#define LDMATRIX_X4(r0, r1, r2, r3, addr) \
    asm volatile("ldmatrix.sync.aligned.m8n8.x4.shared.b16 {%0,%1,%2,%3}, [%4];" \
        : "=r"(r0), "=r"(r1), "=r"(r2), "=r"(r3) : "r"(addr))

#define LDMATRIX_X4_TRANS(r0, r1, r2, r3, addr) \
    asm volatile("ldmatrix.sync.aligned.m8n8.x4.trans.shared.b16 {%0,%1,%2,%3}, [%4];" \
        : "=r"(r0), "=r"(r1), "=r"(r2), "=r"(r3) : "r"(addr))

#define MMA_F16(acc, a0, a1, a2, a3, b0, b1) \
    asm volatile( \
        "mma.sync.aligned.m16n8k16.row.col.f32.f16.f16.f32 " \
        "{%0,%1,%2,%3}, {%4,%5,%6,%7}, {%8,%9}, {%0,%1,%2,%3};" \
        : "+f"((acc)[0]), "+f"((acc)[1]), "+f"((acc)[2]), "+f"((acc)[3]) \
        : "r"(a0), "r"(a1), "r"(a2), "r"(a3), "r"(b0), "r"(b1))

// ---------------------------------------------------------------------------
// Merged conversion kernel (single launch):
//   section 0: x fp32 -> aP fp16                  (4096 blocks)
//   section 1: W_qkv (1024x3072) -> w1P (3072x1024) transpose-cast (3072 blocks)
//   section 2: W_o   (1024x1024) -> w2P (1024x1024) transpose-cast (1024 blocks)
// All blocks are 256 threads.
// ---------------------------------------------------------------------------
__global__ void __launch_bounds__(256) conv_all_kernel(
    const float* __restrict__ x, const float* __restrict__ Wq,
    const float* __restrict__ Wo,
    __half* __restrict__ aP, __half* __restrict__ w1P, __half* __restrict__ w2P)
{
    const int bid = blockIdx.x;
    const int tid = threadIdx.x;

    if (bid < 4096) {
        // activations: 4 floats per thread
        size_t j = (size_t)bid * 256 + tid;
        float4 v = *(const float4*)(x + 4 * j);
        __half2* o = (__half2*)(aP + 4 * j);
        o[0] = __half2(__float2half_rn(v.x), __float2half_rn(v.y));
        o[1] = __half2(__float2half_rn(v.z), __float2half_rn(v.w));
        return;
    }

    // weight transpose-cast
    __shared__ float t[32][33];
    const int tx = tid & 31, ty = tid >> 5;
    const float* W;
    __half* out;
    int N, bx, by;
    if (bid < 4096 + 3072) {
        int idx = bid - 4096;
        W = Wq; out = w1P; N = QKV_COLS;
        bx = idx % (QKV_COLS / 32); by = idx / (QKV_COLS / 32);
    } else {
        int idx = bid - 4096 - 3072;
        W = Wo; out = w2P; N = DMODEL;
        bx = idx % (DMODEL / 32); by = idx / (DMODEL / 32);
    }
#pragma unroll
    for (int i = 0; i < 4; i++) {
        int k = by * 32 + ty + 8 * i;
        int n = bx * 32 + tx;
        t[ty + 8 * i][tx] = W[(size_t)k * N + n];
    }
    __syncthreads();
#pragma unroll
    for (int i = 0; i < 4; i++) {
        int nl = ty + 8 * i;
        int n = bx * 32 + nl;
        out[(size_t)n * DMODEL + by * 32 + tx] = __float2half_rn(t[tx][nl]);
    }
}

// ---------------------------------------------------------------------------
// GEMM mainloop (fp16, CTA 128x128, 4 warps 64x64, BK=64,
// 3-stage cp.async, one sync per iter).
// ---------------------------------------------------------------------------
#define GBK 64
#define ROWB 144                     // padded row bytes (64 fp16 = 128B data)
#define STILE (128 * ROWB)           // 18432 B
#define GSTAGE (2 * STILE)           // 36864 B
#define GSMEM (3 * GSTAGE)           // 110592 B

#define GEMM_PROLOGUE_AND_LOOP()                                               \
    const int tid = threadIdx.x;                                               \
    const int warp = tid >> 5;                                                 \
    const int lane = tid & 31;                                                 \
    const int bm = blockIdx.y * 128;                                           \
    const int bn = blockIdx.x * 128;                                           \
    const int wm0 = (warp >> 1) * 64;                                          \
    const int wn0 = (warp & 1) * 64;                                           \
    const int a_row_off = (lane & 7) + ((lane >> 3) & 1) * 8;                  \
    const int a_kch = (lane >> 4);                                             \
    const int b_row_off = (lane & 7) + ((lane >> 4) & 1) * 8;                  \
    const int b_kch = (lane >> 3) & 1;                                         \
    const uint32_t sbase = smem_u32(gsm);                                      \
    float acc[4][8][4];                                                        \
    _Pragma("unroll")                                                          \
    for (int mi = 0; mi < 4; mi++)                                             \
        _Pragma("unroll")                                                      \
        for (int ni = 0; ni < 8; ni++)                                         \
            _Pragma("unroll")                                                  \
            for (int r = 0; r < 4; r++) acc[mi][ni][r] = 0.f;                  \
    const int NIT = K / GBK;                                                   \
    auto load_stage = [&](int st, int k0) {                                    \
        uint32_t base = sbase + st * GSTAGE;                                   \
        _Pragma("unroll")                                                      \
        for (int i = 0; i < 8; i++) {                                          \
            int c = tid + i * 128;                                             \
            int row = c >> 3, ch = c & 7;                                      \
            uint32_t dA = base + row * ROWB + ch * 16;                         \
            uint32_t dB = dA + STILE;                                          \
            const __half* pA = A + (size_t)(bm + row) * K + k0 + ch * 8;       \
            const __half* pB = B + (size_t)(bn + row) * K + k0 + ch * 8;       \
            asm volatile("cp.async.cg.shared.global [%0], [%1], 16;\n" :: "r"(dA), "l"(pA) : "memory"); \
            asm volatile("cp.async.cg.shared.global [%0], [%1], 16;\n" :: "r"(dB), "l"(pB) : "memory"); \
        }                                                                      \
    };                                                                         \
    load_stage(0, 0);                                                          \
    asm volatile("cp.async.commit_group;\n" ::: "memory");                     \
    load_stage(1, GBK);                                                        \
    asm volatile("cp.async.commit_group;\n" ::: "memory");                     \
    int st = 0;                                                                \
    for (int it = 0; it < NIT; it++) {                                         \
        asm volatile("cp.async.wait_group 1;\n" ::: "memory");                 \
        __syncthreads();                                                       \
        if (it + 2 < NIT) {                                                    \
            int st2 = st + 2 >= 3 ? st - 1 : st + 2;                           \
            load_stage(st2, (it + 2) * GBK);                                   \
        }                                                                      \
        asm volatile("cp.async.commit_group;\n" ::: "memory");                 \
        uint32_t sA = sbase + st * GSTAGE;                                     \
        uint32_t sB = sA + STILE;                                              \
        _Pragma("unroll")                                                      \
        for (int ks = 0; ks < 4; ks++) {                                       \
            uint32_t af[4][4];                                                 \
            _Pragma("unroll")                                                  \
            for (int mi = 0; mi < 4; mi++) {                                   \
                uint32_t addr = sA + (wm0 + mi * 16 + a_row_off) * ROWB +      \
                                (ks * 2 + a_kch) * 16;                         \
                LDMATRIX_X4(af[mi][0], af[mi][1], af[mi][2], af[mi][3], addr); \
            }                                                                  \
            uint32_t bfr[4][4];                                                \
            _Pragma("unroll")                                                  \
            for (int nj = 0; nj < 4; nj++) {                                   \
                uint32_t addr = sB + (wn0 + nj * 16 + b_row_off) * ROWB +      \
                                (ks * 2 + b_kch) * 16;                         \
                LDMATRIX_X4(bfr[nj][0], bfr[nj][1], bfr[nj][2], bfr[nj][3], addr); \
            }                                                                  \
            _Pragma("unroll")                                                  \
            for (int mi = 0; mi < 4; mi++)                                     \
                _Pragma("unroll")                                              \
                for (int ni = 0; ni < 8; ni++)                                 \
                    MMA_F16(acc[mi][ni], af[mi][0], af[mi][1], af[mi][2], af[mi][3], \
                            bfr[ni >> 1][(ni & 1) * 2 + 0], bfr[ni >> 1][(ni & 1) * 2 + 1]); \
        }                                                                      \
        st = (st + 1 == 3) ? 0 : st + 1;                                       \
    }

// ---------------------------------------------------------------------------
// GEMM #2 (out-projection): plain fp32 epilogue.
// ---------------------------------------------------------------------------
__global__ void __launch_bounds__(128, 2) mma_gemm_kernel(
    const __half* __restrict__ A, const __half* __restrict__ B,
    float* __restrict__ C, int N, int K)
{
    extern __shared__ char gsm[];
    GEMM_PROLOGUE_AND_LOOP()

    const int gr = lane >> 2;
    const int tc = (lane & 3) * 2;
#pragma unroll
    for (int mi = 0; mi < 4; mi++) {
#pragma unroll
        for (int ni = 0; ni < 8; ni++) {
            size_t r0 = (size_t)(bm + wm0 + mi * 16 + gr);
            int col = bn + wn0 + ni * 8 + tc;
            *(float2*)&C[r0 * N + col] = make_float2(acc[mi][ni][0], acc[mi][ni][1]);
            *(float2*)&C[(r0 + 8) * N + col] = make_float2(acc[mi][ni][2], acc[mi][ni][3]);
        }
    }
}

// ---------------------------------------------------------------------------
// GEMM #1 (QKV): fused epilogue writes fp16 Q (scaled) / K / V, all [b,h,t,64].
// bn in [0,1024) -> Q, [1024,2048) -> K, [2048,3072) -> V.
// ---------------------------------------------------------------------------
__global__ void __launch_bounds__(128, 2) mma_gemm_qkv_kernel(
    const __half* __restrict__ A, const __half* __restrict__ B,
    __half* __restrict__ qp, __half* __restrict__ kp,
    __half* __restrict__ vp, int N, int K)
{
    extern __shared__ char gsm[];
    GEMM_PROLOGUE_AND_LOOP()

    const int gr = lane >> 2;
    const int tc = (lane & 3) * 2;
    const int sec = bn >> 10;                 // 0=Q, 1=K, 2=V
    const int colbase = (bn & 1023) + wn0;
    __half* const dst = (sec == 0) ? qp : ((sec == 1) ? kp : vp);

#pragma unroll
    for (int mi = 0; mi < 4; mi++) {
#pragma unroll
        for (int rr = 0; rr < 2; rr++) {
            const int row = bm + wm0 + mi * 16 + gr + rr * 8;
            const int b = row >> 11;
            const int t = row & (SEQ - 1);
#pragma unroll
            for (int ni = 0; ni < 8; ni++) {
                const int col = colbase + ni * 8 + tc;    // within section
                float v0 = acc[mi][ni][rr * 2 + 0];
                float v1 = acc[mi][ni][rr * 2 + 1];
                if (sec == 0) { v0 *= QSCALE; v1 *= QSCALE; }
                const int h = col >> 6;
                const int d = col & 63;
                size_t base = ((size_t)((b * NHEAD + h) * SEQ + t)) * DHEAD + d;
                *(__half2*)(dst + base) =
                    __half2(__float2half_rn(v0), __float2half_rn(v1));
            }
        }
    }
}

// ---------------------------------------------------------------------------
// Tensor-core flash attention (FA2), causal, plain fp16.
// CTA: 128 queries x 1 head; 8 warps (each m16 x 64-key tile), 256 threads.
// K and V both [b,h,t,64]; V's B-fragments via ldmatrix.trans (no Vt buffer).
// Epilogue writes plain fp16 output row for GEMM #2 A-operand.
// ---------------------------------------------------------------------------
#define KPITCH 144                  // 64 fp16 = 128B data + 16 pad
#define KS_BYTES (64 * KPITCH)      // 9216
#define FSTAGE (2 * KS_BYTES)       // 18432 (K + V)
#define FSMEM (2 * FSTAGE)          // 36864

__global__ void __launch_bounds__(256, 2) flash_mma_kernel(
    const __half* __restrict__ qp, const __half* __restrict__ kp,
    const __half* __restrict__ vp,
    __half* __restrict__ aP)
{
    extern __shared__ char fsm[];
    const int tid = threadIdx.x;
    const int warp = tid >> 5;
    const int lane = tid & 31;
    const int qt = gridDim.x - 1 - blockIdx.x;      // heavy tiles first
    const int h = blockIdx.y;
    const int b = blockIdx.z;
    const int bh = b * NHEAD + h;
    const int q0 = qt * 128;

    const uint32_t sb = smem_u32(fsm);
    const int gr = lane >> 2;
    const int tc = lane & 3;
    const int a_row_off = (lane & 7) + ((lane >> 3) & 1) * 8;
    const int a_kch = lane >> 4;
    const int b_row_off = (lane & 7) + ((lane >> 4) & 1) * 8;
    const int b_kch = (lane >> 3) & 1;
    // trans-ldmatrix addressing for V (row-major [key][d] tile)
    const int v_row_off = lane & 15;            // key within k16 chunk
    const int v_coff = (lane >> 4) * 16;        // d-half byte offset

    // ---- stage Q tile (128 x 64 fp16) into smem, extract A fragments
    {
        const __half* qsrc = qp + ((size_t)(bh * SEQ + q0)) * DHEAD;
#pragma unroll
        for (int i = 0; i < 4; i++) {
            int c = i * 256 + tid;               // 0..1023 (16B chunks)
            int row = c >> 3, ch = c & 7;
            uint32_t dst = sb + row * KPITCH + ch * 16;
            const __half* src = qsrc + (size_t)row * DHEAD + ch * 8;
            asm volatile("cp.async.cg.shared.global [%0], [%1], 16;\n" :: "r"(dst), "l"(src) : "memory");
        }
        asm volatile("cp.async.commit_group;\ncp.async.wait_group 0;\n" ::: "memory");
        __syncthreads();
    }
    uint32_t qf[4][4];
#pragma unroll
    for (int ck = 0; ck < 4; ck++) {
        uint32_t addr = sb + (warp * 16 + a_row_off) * KPITCH + ck * 32 + a_kch * 16;
        LDMATRIX_X4(qf[ck][0], qf[ck][1], qf[ck][2], qf[ck][3], addr);
    }
    __syncthreads();

    float oacc[8][4];
#pragma unroll
    for (int t = 0; t < 8; t++)
#pragma unroll
        for (int r = 0; r < 4; r++) oacc[t][r] = 0.f;
    float m0 = -1e30f, m1 = -1e30f, l0 = 0.f, l1 = 0.f;

    const int nkt = 2 * qt + 2;                 // k-tiles (64 keys each)

    auto load_tile = [&](int kt, int st) {
        const int kt0 = kt * 64;
        uint32_t ks = sb + st * FSTAGE;
        uint32_t vs = ks + KS_BYTES;
        const __half* ksrc = kp + ((size_t)(bh * SEQ + kt0)) * DHEAD;
        const __half* vsrc = vp + ((size_t)(bh * SEQ + kt0)) * DHEAD;
#pragma unroll
        for (int i = 0; i < 2; i++) {
            int c = i * 256 + tid;               // 0..511
            int row = c >> 3, ch = c & 7;
            uint32_t dk = ks + row * KPITCH + ch * 16;
            uint32_t dv = vs + row * KPITCH + ch * 16;
            const __half* sk = ksrc + (size_t)row * DHEAD + ch * 8;
            const __half* sv = vsrc + (size_t)row * DHEAD + ch * 8;
            asm volatile("cp.async.cg.shared.global [%0], [%1], 16;\n" :: "r"(dk), "l"(sk) : "memory");
            asm volatile("cp.async.cg.shared.global [%0], [%1], 16;\n" :: "r"(dv), "l"(sv) : "memory");
        }
    };

    load_tile(0, 0);
    asm volatile("cp.async.commit_group;\n" ::: "memory");
    load_tile(1, 1);
    asm volatile("cp.async.commit_group;\n" ::: "memory");

    for (int kt = 0; kt < nkt; kt++) {
        asm volatile("cp.async.wait_group 1;\n" ::: "memory");
        __syncthreads();
        const int st = kt & 1;
        uint32_t ks = sb + st * FSTAGE;
        uint32_t vs = ks + KS_BYTES;

        // ---- S = Q.K^T  (4 k16 chunks over DHEAD=64)
        float sacc[8][4];
#pragma unroll
        for (int t = 0; t < 8; t++)
#pragma unroll
            for (int r = 0; r < 4; r++) sacc[t][r] = 0.f;
#pragma unroll
        for (int ck = 0; ck < 4; ck++) {
            uint32_t bfr[4][4];
#pragma unroll
            for (int nj = 0; nj < 4; nj++) {
                uint32_t addr = ks + (nj * 16 + b_row_off) * KPITCH + ck * 32 + b_kch * 16;
                LDMATRIX_X4(bfr[nj][0], bfr[nj][1], bfr[nj][2], bfr[nj][3], addr);
            }
#pragma unroll
            for (int ni = 0; ni < 8; ni++)
                MMA_F16(sacc[ni], qf[ck][0], qf[ck][1], qf[ck][2], qf[ck][3],
                        bfr[ni >> 1][(ni & 1) * 2 + 0], bfr[ni >> 1][(ni & 1) * 2 + 1]);
        }

        // ---- causal mask on the two diagonal-spanning k-tiles
        if (kt >= nkt - 2) {
            const int kt0 = kt * 64;
            int rq0 = q0 + warp * 16 + gr;
            int rq1 = rq0 + 8;
#pragma unroll
            for (int t = 0; t < 8; t++) {
                int c0 = kt0 + 8 * t + 2 * tc;
                if (c0 > rq0)     sacc[t][0] = -1e30f;
                if (c0 + 1 > rq0) sacc[t][1] = -1e30f;
                if (c0 > rq1)     sacc[t][2] = -1e30f;
                if (c0 + 1 > rq1) sacc[t][3] = -1e30f;
            }
        }

        // ---- online softmax (base-2, quad reductions)
        float mx0 = -1e30f, mx1 = -1e30f;
#pragma unroll
        for (int t = 0; t < 8; t++) {
            mx0 = fmaxf(mx0, fmaxf(sacc[t][0], sacc[t][1]));
            mx1 = fmaxf(mx1, fmaxf(sacc[t][2], sacc[t][3]));
        }
        mx0 = fmaxf(mx0, __shfl_xor_sync(0xffffffffu, mx0, 1));
        mx0 = fmaxf(mx0, __shfl_xor_sync(0xffffffffu, mx0, 2));
        mx1 = fmaxf(mx1, __shfl_xor_sync(0xffffffffu, mx1, 1));
        mx1 = fmaxf(mx1, __shfl_xor_sync(0xffffffffu, mx1, 2));
        float mn0 = fmaxf(m0, mx0), mn1 = fmaxf(m1, mx1);
        float cr0 = fast_exp2(m0 - mn0), cr1 = fast_exp2(m1 - mn1);
        m0 = mn0; m1 = mn1;
        l0 *= cr0; l1 *= cr1;
#pragma unroll
        for (int t = 0; t < 8; t++) {
            oacc[t][0] *= cr0; oacc[t][1] *= cr0;
            oacc[t][2] *= cr1; oacc[t][3] *= cr1;
        }
        uint32_t phi[8][2];
        float rs0 = 0.f, rs1 = 0.f;
#pragma unroll
        for (int t = 0; t < 8; t++) {
            float p0 = fast_exp2(sacc[t][0] - m0);
            float p1 = fast_exp2(sacc[t][1] - m0);
            float p2 = fast_exp2(sacc[t][2] - m1);
            float p3 = fast_exp2(sacc[t][3] - m1);
            rs0 += p0 + p1; rs1 += p2 + p3;
            phi[t][0] = pack_f16x2(p0, p1);
            phi[t][1] = pack_f16x2(p2, p3);
        }
        rs0 += __shfl_xor_sync(0xffffffffu, rs0, 1);
        rs0 += __shfl_xor_sync(0xffffffffu, rs0, 2);
        rs1 += __shfl_xor_sync(0xffffffffu, rs1, 1);
        rs1 += __shfl_xor_sync(0xffffffffu, rs1, 2);
        l0 += rs0; l1 += rs1;

        // ---- PV: O += P.V  (V row-major [key][d]; B-frags via ldmatrix.trans)
#pragma unroll
        for (int ck = 0; ck < 4; ck++) {
            uint32_t aph[4] = { phi[2 * ck][0], phi[2 * ck][1],
                                phi[2 * ck + 1][0], phi[2 * ck + 1][1] };
            uint32_t vfr[4][4];
#pragma unroll
            for (int dt = 0; dt < 4; dt++) {
                uint32_t addr = vs + (ck * 16 + v_row_off) * KPITCH + dt * 32 + v_coff;
                LDMATRIX_X4_TRANS(vfr[dt][0], vfr[dt][1], vfr[dt][2], vfr[dt][3], addr);
            }
#pragma unroll
            for (int ni = 0; ni < 8; ni++)
                MMA_F16(oacc[ni], aph[0], aph[1], aph[2], aph[3],
                        vfr[ni >> 1][(ni & 1) * 2 + 0], vfr[ni >> 1][(ni & 1) * 2 + 1]);
        }

        __syncthreads();
        if (kt + 2 < nkt) load_tile(kt + 2, st);
        asm volatile("cp.async.commit_group;\n" ::: "memory");
    }

    // ---- epilogue: write plain fp16 attention output into aP [M x 1024]
    const float inv0 = 1.f / l0, inv1 = 1.f / l1;
    const int qr0 = q0 + warp * 16 + gr;
    const int qr1 = qr0 + 8;
#pragma unroll
    for (int t = 0; t < 8; t++) {
        int col = h * DHEAD + 8 * t + 2 * tc;
        *(__half2*)(aP + ((size_t)(b * SEQ + qr0)) * DMODEL + col) =
            __half2(__float2half_rn(oacc[t][0] * inv0), __float2half_rn(oacc[t][1] * inv0));
        *(__half2*)(aP + ((size_t)(b * SEQ + qr1)) * DMODEL + col) =
            __half2(__float2half_rn(oacc[t][2] * inv1), __float2half_rn(oacc[t][3] * inv1));
    }
}

// ---------------------------------------------------------------------------
extern "C" void kernel_launch(void* const* d_in, const int* in_sizes, int n_in,
                              void* d_out, int out_size)
{
    const float* x     = (const float*)d_in[0];
    const float* W_qkv = (const float*)d_in[1];
    const float* W_o   = (const float*)d_in[2];
    float* out = (float*)d_out;

    __half *aP, *w1P, *w2P, *qp, *kp, *vp;
    cudaGetSymbolAddress((void**)&aP, g_aP);
    cudaGetSymbolAddress((void**)&w1P, g_w1P);
    cudaGetSymbolAddress((void**)&w2P, g_w2P);
    cudaGetSymbolAddress((void**)&qp, g_qp);
    cudaGetSymbolAddress((void**)&kp, g_kp);
    cudaGetSymbolAddress((void**)&vp, g_vp);

    cudaFuncSetAttribute(flash_mma_kernel,
                         cudaFuncAttributeMaxDynamicSharedMemorySize, FSMEM);
    cudaFuncSetAttribute(mma_gemm_kernel,
                         cudaFuncAttributeMaxDynamicSharedMemorySize, GSMEM);
    cudaFuncSetAttribute(mma_gemm_qkv_kernel,
                         cudaFuncAttributeMaxDynamicSharedMemorySize, GSMEM);

    // all conversions in one launch
    conv_all_kernel<<<4096 + 3072 + 1024, 256>>>(x, W_qkv, W_o, aP, w1P, w2P);

    // 1) QKV GEMM with fused Q/K/V fp16 epilogue   (M=4096, N=3072, K=1024)
    {
        dim3 grid(QKV_COLS / 128, MROWS / 128);
        mma_gemm_qkv_kernel<<<grid, 128, GSMEM>>>(aP, w1P, qp, kp, vp,
                                                  QKV_COLS, DMODEL);
    }
    // 2) flash attention (q-tile 128, writes fp16 aP for out-proj)
    {
        dim3 grid(SEQ / 128, NHEAD, BATCH);
        flash_mma_kernel<<<grid, 256, FSMEM>>>(qp, kp, vp, aP);
    }
    // 3) out = attn_out @ W_o   (M=4096, N=1024, K=1024)
    {
        dim3 grid(DMODEL / 128, MROWS / 128);
        mma_gemm_kernel<<<grid, 128, GSMEM>>>(aP, w2P, out, DMODEL, DMODEL);
    }
}

// round 11
// speedup vs baseline: 8.2314x; 1.0040x over previous
#include <cuda_runtime.h>
#include <cuda_bf16.h>
#include <cuda_fp16.h>
#include <math.h>
#include <stdint.h>

// Problem constants
#define BATCH 2
#define SEQ   2048
#define DMODEL 1024
#define NHEAD 16
#define DHEAD 64
#define MROWS (BATCH * SEQ)           // 4096
#define QKV_COLS (3 * DMODEL)         // 3072
#define QSCALE 0.18033688f            // 0.125 * log2(e)

// ---------------------------------------------------------------------------
// Scratch (static device globals; allocations are forbidden)
// ---------------------------------------------------------------------------
__device__ __half g_aP[(size_t)MROWS * DMODEL];            // 8.4 MB (A fp16, both GEMMs)
__device__ __half g_w1P[(size_t)QKV_COLS * DMODEL];        // 6.3 MB (W_qkv^T fp16)
__device__ __half g_w2P[(size_t)DMODEL * DMODEL];          // 2.1 MB (W_o^T fp16)
// Attention operands (plain fp16, all [b,h,t,64])
__device__ __half g_qp[(size_t)BATCH * NHEAD * SEQ * DHEAD];  // 8.4 MB
__device__ __half g_kp[(size_t)BATCH * NHEAD * SEQ * DHEAD];  // 8.4 MB
__device__ __half g_vp[(size_t)BATCH * NHEAD * SEQ * DHEAD];  // 8.4 MB

__device__ __forceinline__ uint32_t smem_u32(const void* p) {
    uint32_t a;
    asm("{ .reg .u64 t; cvta.to.shared.u64 t, %1; cvt.u32.u64 %0, t; }" : "=r"(a) : "l"(p));
    return a;
}
__device__ __forceinline__ float fast_exp2(float x) {
    float y; asm("ex2.approx.ftz.f32 %0, %1;" : "=f"(y) : "f"(x)); return y;
}
// pack fp16x2: low half = lo, high half = hi
__device__ __forceinline__ uint32_t pack_f16x2(float lo, float hi) {
    uint32_t r; asm("cvt.rn.f16x2.f32 %0, %1, %2;" : "=r"(r) : "f"(hi), "f"(lo)); return r;
}

#define LDMATRIX_X4(r0, r1, r2, r3, addr) \
    asm volatile("ldmatrix.sync.aligned.m8n8.x4.shared.b16 {%0,%1,%2,%3}, [%4];" \
        : "=r"(r0), "=r"(r1), "=r"(r2), "=r"(r3) : "r"(addr))

#define LDMATRIX_X4_TRANS(r0, r1, r2, r3, addr) \
    asm volatile("ldmatrix.sync.aligned.m8n8.x4.trans.shared.b16 {%0,%1,%2,%3}, [%4];" \
        : "=r"(r0), "=r"(r1), "=r"(r2), "=r"(r3) : "r"(addr))

#define MMA_F16(acc, a0, a1, a2, a3, b0, b1) \
    asm volatile( \
        "mma.sync.aligned.m16n8k16.row.col.f32.f16.f16.f32 " \
        "{%0,%1,%2,%3}, {%4,%5,%6,%7}, {%8,%9}, {%0,%1,%2,%3};" \
        : "+f"((acc)[0]), "+f"((acc)[1]), "+f"((acc)[2]), "+f"((acc)[3]) \
        : "r"(a0), "r"(a1), "r"(a2), "r"(a3), "r"(b0), "r"(b1))

// ---------------------------------------------------------------------------
// Merged conversion kernel (single launch):
//   section 0: x fp32 -> aP fp16                  (4096 blocks)
//   section 1: W_qkv -> w1P transpose-cast        (3072 blocks)
//   section 2: W_o   -> w2P transpose-cast        (1024 blocks)
// ---------------------------------------------------------------------------
__global__ void __launch_bounds__(256) conv_all_kernel(
    const float* __restrict__ x, const float* __restrict__ Wq,
    const float* __restrict__ Wo,
    __half* __restrict__ aP, __half* __restrict__ w1P, __half* __restrict__ w2P)
{
    const int bid = blockIdx.x;
    const int tid = threadIdx.x;

    if (bid < 4096) {
        size_t j = (size_t)bid * 256 + tid;
        float4 v = *(const float4*)(x + 4 * j);
        __half2* o = (__half2*)(aP + 4 * j);
        o[0] = __half2(__float2half_rn(v.x), __float2half_rn(v.y));
        o[1] = __half2(__float2half_rn(v.z), __float2half_rn(v.w));
        return;
    }

    __shared__ float t[32][33];
    const int tx = tid & 31, ty = tid >> 5;
    const float* W;
    __half* out;
    int N, bx, by;
    if (bid < 4096 + 3072) {
        int idx = bid - 4096;
        W = Wq; out = w1P; N = QKV_COLS;
        bx = idx % (QKV_COLS / 32); by = idx / (QKV_COLS / 32);
    } else {
        int idx = bid - 4096 - 3072;
        W = Wo; out = w2P; N = DMODEL;
        bx = idx % (DMODEL / 32); by = idx / (DMODEL / 32);
    }
#pragma unroll
    for (int i = 0; i < 4; i++) {
        int k = by * 32 + ty + 8 * i;
        int n = bx * 32 + tx;
        t[ty + 8 * i][tx] = W[(size_t)k * N + n];
    }
    __syncthreads();
#pragma unroll
    for (int i = 0; i < 4; i++) {
        int nl = ty + 8 * i;
        int n = bx * 32 + nl;
        out[(size_t)n * DMODEL + by * 32 + tx] = __float2half_rn(t[tx][nl]);
    }
}

// ---------------------------------------------------------------------------
// GEMM mainloop (fp16, CTA 128x128, 4 warps 64x64, BK=64,
// 3-stage cp.async, one sync per iter).
// ---------------------------------------------------------------------------
#define GBK 64
#define ROWB 144                     // padded row bytes (64 fp16 = 128B data)
#define STILE (128 * ROWB)           // 18432 B
#define GSTAGE (2 * STILE)           // 36864 B
#define GSMEM (3 * GSTAGE)           // 110592 B

#define GEMM_PROLOGUE_AND_LOOP()                                               \
    const int tid = threadIdx.x;                                               \
    const int warp = tid >> 5;                                                 \
    const int lane = tid & 31;                                                 \
    const int bm = blockIdx.y * 128;                                           \
    const int bn = blockIdx.x * 128;                                           \
    const int wm0 = (warp >> 1) * 64;                                          \
    const int wn0 = (warp & 1) * 64;                                           \
    const int a_row_off = (lane & 7) + ((lane >> 3) & 1) * 8;                  \
    const int a_kch = (lane >> 4);                                             \
    const int b_row_off = (lane & 7) + ((lane >> 4) & 1) * 8;                  \
    const int b_kch = (lane >> 3) & 1;                                         \
    const uint32_t sbase = smem_u32(gsm);                                      \
    float acc[4][8][4];                                                        \
    _Pragma("unroll")                                                          \
    for (int mi = 0; mi < 4; mi++)                                             \
        _Pragma("unroll")                                                      \
        for (int ni = 0; ni < 8; ni++)                                         \
            _Pragma("unroll")                                                  \
            for (int r = 0; r < 4; r++) acc[mi][ni][r] = 0.f;                  \
    const int NIT = K / GBK;                                                   \
    auto load_stage = [&](int st, int k0) {                                    \
        uint32_t base = sbase + st * GSTAGE;                                   \
        _Pragma("unroll")                                                      \
        for (int i = 0; i < 8; i++) {                                          \
            int c = tid + i * 128;                                             \
            int row = c >> 3, ch = c & 7;                                      \
            uint32_t dA = base + row * ROWB + ch * 16;                         \
            uint32_t dB = dA + STILE;                                          \
            const __half* pA = A + (size_t)(bm + row) * K + k0 + ch * 8;       \
            const __half* pB = B + (size_t)(bn + row) * K + k0 + ch * 8;       \
            asm volatile("cp.async.cg.shared.global [%0], [%1], 16;\n" :: "r"(dA), "l"(pA) : "memory"); \
            asm volatile("cp.async.cg.shared.global [%0], [%1], 16;\n" :: "r"(dB), "l"(pB) : "memory"); \
        }                                                                      \
    };                                                                         \
    load_stage(0, 0);                                                          \
    asm volatile("cp.async.commit_group;\n" ::: "memory");                     \
    load_stage(1, GBK);                                                        \
    asm volatile("cp.async.commit_group;\n" ::: "memory");                     \
    int st = 0;                                                                \
    for (int it = 0; it < NIT; it++) {                                         \
        asm volatile("cp.async.wait_group 1;\n" ::: "memory");                 \
        __syncthreads();                                                       \
        if (it + 2 < NIT) {                                                    \
            int st2 = st + 2 >= 3 ? st - 1 : st + 2;                           \
            load_stage(st2, (it + 2) * GBK);                                   \
        }                                                                      \
        asm volatile("cp.async.commit_group;\n" ::: "memory");                 \
        uint32_t sA = sbase + st * GSTAGE;                                     \
        uint32_t sB = sA + STILE;                                              \
        _Pragma("unroll")                                                      \
        for (int ks = 0; ks < 4; ks++) {                                       \
            uint32_t af[4][4];                                                 \
            _Pragma("unroll")                                                  \
            for (int mi = 0; mi < 4; mi++) {                                   \
                uint32_t addr = sA + (wm0 + mi * 16 + a_row_off) * ROWB +      \
                                (ks * 2 + a_kch) * 16;                         \
                LDMATRIX_X4(af[mi][0], af[mi][1], af[mi][2], af[mi][3], addr); \
            }                                                                  \
            uint32_t bfr[4][4];                                                \
            _Pragma("unroll")                                                  \
            for (int nj = 0; nj < 4; nj++) {                                   \
                uint32_t addr = sB + (wn0 + nj * 16 + b_row_off) * ROWB +      \
                                (ks * 2 + b_kch) * 16;                         \
                LDMATRIX_X4(bfr[nj][0], bfr[nj][1], bfr[nj][2], bfr[nj][3], addr); \
            }                                                                  \
            _Pragma("unroll")                                                  \
            for (int mi = 0; mi < 4; mi++)                                     \
                _Pragma("unroll")                                              \
                for (int ni = 0; ni < 8; ni++)                                 \
                    MMA_F16(acc[mi][ni], af[mi][0], af[mi][1], af[mi][2], af[mi][3], \
                            bfr[ni >> 1][(ni & 1) * 2 + 0], bfr[ni >> 1][(ni & 1) * 2 + 1]); \
        }                                                                      \
        st = (st + 1 == 3) ? 0 : st + 1;                                       \
    }

// ---------------------------------------------------------------------------
// GEMM #2 (out-projection): plain fp32 epilogue.
// ---------------------------------------------------------------------------
__global__ void __launch_bounds__(128, 2) mma_gemm_kernel(
    const __half* __restrict__ A, const __half* __restrict__ B,
    float* __restrict__ C, int N, int K)
{
    extern __shared__ char gsm[];
    GEMM_PROLOGUE_AND_LOOP()

    const int gr = lane >> 2;
    const int tc = (lane & 3) * 2;
#pragma unroll
    for (int mi = 0; mi < 4; mi++) {
#pragma unroll
        for (int ni = 0; ni < 8; ni++) {
            size_t r0 = (size_t)(bm + wm0 + mi * 16 + gr);
            int col = bn + wn0 + ni * 8 + tc;
            *(float2*)&C[r0 * N + col] = make_float2(acc[mi][ni][0], acc[mi][ni][1]);
            *(float2*)&C[(r0 + 8) * N + col] = make_float2(acc[mi][ni][2], acc[mi][ni][3]);
        }
    }
}

// ---------------------------------------------------------------------------
// GEMM #1 (QKV): fused epilogue writes fp16 Q (scaled) / K / V, all [b,h,t,64].
// bn in [0,1024) -> Q, [1024,2048) -> K, [2048,3072) -> V.
// ---------------------------------------------------------------------------
__global__ void __launch_bounds__(128, 2) mma_gemm_qkv_kernel(
    const __half* __restrict__ A, const __half* __restrict__ B,
    __half* __restrict__ qp, __half* __restrict__ kp,
    __half* __restrict__ vp, int N, int K)
{
    extern __shared__ char gsm[];
    GEMM_PROLOGUE_AND_LOOP()

    const int gr = lane >> 2;
    const int tc = (lane & 3) * 2;
    const int sec = bn >> 10;                 // 0=Q, 1=K, 2=V
    const int colbase = (bn & 1023) + wn0;
    __half* const dst = (sec == 0) ? qp : ((sec == 1) ? kp : vp);

#pragma unroll
    for (int mi = 0; mi < 4; mi++) {
#pragma unroll
        for (int rr = 0; rr < 2; rr++) {
            const int row = bm + wm0 + mi * 16 + gr + rr * 8;
            const int b = row >> 11;
            const int t = row & (SEQ - 1);
#pragma unroll
            for (int ni = 0; ni < 8; ni++) {
                const int col = colbase + ni * 8 + tc;    // within section
                float v0 = acc[mi][ni][rr * 2 + 0];
                float v1 = acc[mi][ni][rr * 2 + 1];
                if (sec == 0) { v0 *= QSCALE; v1 *= QSCALE; }
                const int h = col >> 6;
                const int d = col & 63;
                size_t base = ((size_t)((b * NHEAD + h) * SEQ + t)) * DHEAD + d;
                *(__half2*)(dst + base) =
                    __half2(__float2half_rn(v0), __float2half_rn(v1));
            }
        }
    }
}

// ---------------------------------------------------------------------------
// Tensor-core flash attention (FA2), causal, plain fp16.
// CTA: 128 queries x 1 head; 8 warps (each m16 x 64-key tile), 256 threads.
// Q has its own smem region; prologue overlaps Q + K/V tile 0 + tile 1 loads.
// Fully-masked diagonal warps skip compute (bit-identical; their P was 0).
// ---------------------------------------------------------------------------
#define KPITCH 144                  // 64 fp16 = 128B data + 16 pad
#define KS_BYTES (64 * KPITCH)      // 9216
#define FSTAGE (2 * KS_BYTES)       // 18432 (K + V)
#define QS_BYTES (128 * KPITCH)     // 18432 (Q region)
#define FSMEM (2 * FSTAGE + QS_BYTES)  // 55296

__global__ void __launch_bounds__(256, 2) flash_mma_kernel(
    const __half* __restrict__ qp, const __half* __restrict__ kp,
    const __half* __restrict__ vp,
    __half* __restrict__ aP)
{
    extern __shared__ char fsm[];
    const int tid = threadIdx.x;
    const int warp = tid >> 5;
    const int lane = tid & 31;
    const int qt = gridDim.x - 1 - blockIdx.x;      // heavy tiles first
    const int h = blockIdx.y;
    const int b = blockIdx.z;
    const int bh = b * NHEAD + h;
    const int q0 = qt * 128;

    const uint32_t sb = smem_u32(fsm);
    const uint32_t qb = sb + 2 * FSTAGE;            // Q region
    const int gr = lane >> 2;
    const int tc = lane & 3;
    const int a_row_off = (lane & 7) + ((lane >> 3) & 1) * 8;
    const int a_kch = lane >> 4;
    const int b_row_off = (lane & 7) + ((lane >> 4) & 1) * 8;
    const int b_kch = (lane >> 3) & 1;
    // trans-ldmatrix addressing for V (row-major [key][d] tile)
    const int v_row_off = lane & 15;            // key within k16 chunk
    const int v_coff = (lane >> 4) * 16;        // d-half byte offset

    const int nkt = 2 * qt + 2;                 // k-tiles (64 keys each)

    auto load_tile = [&](int kt, int st) {
        const int kt0 = kt * 64;
        uint32_t ks = sb + st * FSTAGE;
        uint32_t vs = ks + KS_BYTES;
        const __half* ksrc = kp + ((size_t)(bh * SEQ + kt0)) * DHEAD;
        const __half* vsrc = vp + ((size_t)(bh * SEQ + kt0)) * DHEAD;
#pragma unroll
        for (int i = 0; i < 2; i++) {
            int c = i * 256 + tid;               // 0..511
            int row = c >> 3, ch = c & 7;
            uint32_t dk = ks + row * KPITCH + ch * 16;
            uint32_t dv = vs + row * KPITCH + ch * 16;
            const __half* sk = ksrc + (size_t)row * DHEAD + ch * 8;
            const __half* sv = vsrc + (size_t)row * DHEAD + ch * 8;
            asm volatile("cp.async.cg.shared.global [%0], [%1], 16;\n" :: "r"(dk), "l"(sk) : "memory");
            asm volatile("cp.async.cg.shared.global [%0], [%1], 16;\n" :: "r"(dv), "l"(sv) : "memory");
        }
    };

    // ---- overlapped prologue: Q + K/V tile 0 + K/V tile 1, then one wait
    {
        const __half* qsrc = qp + ((size_t)(bh * SEQ + q0)) * DHEAD;
#pragma unroll
        for (int i = 0; i < 4; i++) {
            int c = i * 256 + tid;               // 0..1023 (16B chunks)
            int row = c >> 3, ch = c & 7;
            uint32_t dst = qb + row * KPITCH + ch * 16;
            const __half* src = qsrc + (size_t)row * DHEAD + ch * 8;
            asm volatile("cp.async.cg.shared.global [%0], [%1], 16;\n" :: "r"(dst), "l"(src) : "memory");
        }
        asm volatile("cp.async.commit_group;\n" ::: "memory");
    }
    load_tile(0, 0);
    asm volatile("cp.async.commit_group;\n" ::: "memory");
    load_tile(1, 1);
    asm volatile("cp.async.commit_group;\n" ::: "memory");

    // Q group done when <=2 groups pending
    asm volatile("cp.async.wait_group 2;\n" ::: "memory");
    __syncthreads();

    uint32_t qf[4][4];
#pragma unroll
    for (int ck = 0; ck < 4; ck++) {
        uint32_t addr = qb + (warp * 16 + a_row_off) * KPITCH + ck * 32 + a_kch * 16;
        LDMATRIX_X4(qf[ck][0], qf[ck][1], qf[ck][2], qf[ck][3], addr);
    }

    float oacc[8][4];
#pragma unroll
    for (int t = 0; t < 8; t++)
#pragma unroll
        for (int r = 0; r < 4; r++) oacc[t][r] = 0.f;
    float m0 = -1e30f, m1 = -1e30f, l0 = 0.f, l1 = 0.f;

    for (int kt = 0; kt < nkt; kt++) {
        asm volatile("cp.async.wait_group 1;\n" ::: "memory");
        __syncthreads();
        const int st = kt & 1;
        uint32_t ks = sb + st * FSTAGE;
        uint32_t vs = ks + KS_BYTES;

        // warps 0-3 on the last k-tile are fully above the diagonal:
        // their P is exactly 0 there, so skip the compute entirely.
        const bool active = !(kt == nkt - 1 && warp < 4);
        if (active) {
            // ---- S = Q.K^T  (4 k16 chunks over DHEAD=64)
            float sacc[8][4];
#pragma unroll
            for (int t = 0; t < 8; t++)
#pragma unroll
                for (int r = 0; r < 4; r++) sacc[t][r] = 0.f;
#pragma unroll
            for (int ck = 0; ck < 4; ck++) {
                uint32_t bfr[4][4];
#pragma unroll
                for (int nj = 0; nj < 4; nj++) {
                    uint32_t addr = ks + (nj * 16 + b_row_off) * KPITCH + ck * 32 + b_kch * 16;
                    LDMATRIX_X4(bfr[nj][0], bfr[nj][1], bfr[nj][2], bfr[nj][3], addr);
                }
#pragma unroll
                for (int ni = 0; ni < 8; ni++)
                    MMA_F16(sacc[ni], qf[ck][0], qf[ck][1], qf[ck][2], qf[ck][3],
                            bfr[ni >> 1][(ni & 1) * 2 + 0], bfr[ni >> 1][(ni & 1) * 2 + 1]);
            }

            // ---- causal mask on the two diagonal-spanning k-tiles
            if (kt >= nkt - 2) {
                const int kt0 = kt * 64;
                int rq0 = q0 + warp * 16 + gr;
                int rq1 = rq0 + 8;
#pragma unroll
                for (int t = 0; t < 8; t++) {
                    int c0 = kt0 + 8 * t + 2 * tc;
                    if (c0 > rq0)     sacc[t][0] = -1e30f;
                    if (c0 + 1 > rq0) sacc[t][1] = -1e30f;
                    if (c0 > rq1)     sacc[t][2] = -1e30f;
                    if (c0 + 1 > rq1) sacc[t][3] = -1e30f;
                }
            }

            // ---- online softmax (base-2, quad reductions)
            float mx0 = -1e30f, mx1 = -1e30f;
#pragma unroll
            for (int t = 0; t < 8; t++) {
                mx0 = fmaxf(mx0, fmaxf(sacc[t][0], sacc[t][1]));
                mx1 = fmaxf(mx1, fmaxf(sacc[t][2], sacc[t][3]));
            }
            mx0 = fmaxf(mx0, __shfl_xor_sync(0xffffffffu, mx0, 1));
            mx0 = fmaxf(mx0, __shfl_xor_sync(0xffffffffu, mx0, 2));
            mx1 = fmaxf(mx1, __shfl_xor_sync(0xffffffffu, mx1, 1));
            mx1 = fmaxf(mx1, __shfl_xor_sync(0xffffffffu, mx1, 2));
            float mn0 = fmaxf(m0, mx0), mn1 = fmaxf(m1, mx1);
            float cr0 = fast_exp2(m0 - mn0), cr1 = fast_exp2(m1 - mn1);
            m0 = mn0; m1 = mn1;
            l0 *= cr0; l1 *= cr1;
#pragma unroll
            for (int t = 0; t < 8; t++) {
                oacc[t][0] *= cr0; oacc[t][1] *= cr0;
                oacc[t][2] *= cr1; oacc[t][3] *= cr1;
            }
            uint32_t phi[8][2];
            float rs0 = 0.f, rs1 = 0.f;
#pragma unroll
            for (int t = 0; t < 8; t++) {
                float p0 = fast_exp2(sacc[t][0] - m0);
                float p1 = fast_exp2(sacc[t][1] - m0);
                float p2 = fast_exp2(sacc[t][2] - m1);
                float p3 = fast_exp2(sacc[t][3] - m1);
                rs0 += p0 + p1; rs1 += p2 + p3;
                phi[t][0] = pack_f16x2(p0, p1);
                phi[t][1] = pack_f16x2(p2, p3);
            }
            rs0 += __shfl_xor_sync(0xffffffffu, rs0, 1);
            rs0 += __shfl_xor_sync(0xffffffffu, rs0, 2);
            rs1 += __shfl_xor_sync(0xffffffffu, rs1, 1);
            rs1 += __shfl_xor_sync(0xffffffffu, rs1, 2);
            l0 += rs0; l1 += rs1;

            // ---- PV: O += P.V  (V row-major; B-frags via ldmatrix.trans)
#pragma unroll
            for (int ck = 0; ck < 4; ck++) {
                uint32_t aph[4] = { phi[2 * ck][0], phi[2 * ck][1],
                                    phi[2 * ck + 1][0], phi[2 * ck + 1][1] };
                uint32_t vfr[4][4];
#pragma unroll
                for (int dt = 0; dt < 4; dt++) {
                    uint32_t addr = vs + (ck * 16 + v_row_off) * KPITCH + dt * 32 + v_coff;
                    LDMATRIX_X4_TRANS(vfr[dt][0], vfr[dt][1], vfr[dt][2], vfr[dt][3], addr);
                }
#pragma unroll
                for (int ni = 0; ni < 8; ni++)
                    MMA_F16(oacc[ni], aph[0], aph[1], aph[2], aph[3],
                            vfr[ni >> 1][(ni & 1) * 2 + 0], vfr[ni >> 1][(ni & 1) * 2 + 1]);
            }
        }

        __syncthreads();
        if (kt + 2 < nkt) load_tile(kt + 2, st);
        asm volatile("cp.async.commit_group;\n" ::: "memory");
    }

    // ---- epilogue: write plain fp16 attention output into aP [M x 1024]
    const float inv0 = 1.f / l0, inv1 = 1.f / l1;
    const int qr0 = q0 + warp * 16 + gr;
    const int qr1 = qr0 + 8;
#pragma unroll
    for (int t = 0; t < 8; t++) {
        int col = h * DHEAD + 8 * t + 2 * tc;
        *(__half2*)(aP + ((size_t)(b * SEQ + qr0)) * DMODEL + col) =
            __half2(__float2half_rn(oacc[t][0] * inv0), __float2half_rn(oacc[t][1] * inv0));
        *(__half2*)(aP + ((size_t)(b * SEQ + qr1)) * DMODEL + col) =
            __half2(__float2half_rn(oacc[t][2] * inv1), __float2half_rn(oacc[t][3] * inv1));
    }
}

// ---------------------------------------------------------------------------
extern "C" void kernel_launch(void* const* d_in, const int* in_sizes, int n_in,
                              void* d_out, int out_size)
{
    const float* x     = (const float*)d_in[0];
    const float* W_qkv = (const float*)d_in[1];
    const float* W_o   = (const float*)d_in[2];
    float* out = (float*)d_out;

    __half *aP, *w1P, *w2P, *qp, *kp, *vp;
    cudaGetSymbolAddress((void**)&aP, g_aP);
    cudaGetSymbolAddress((void**)&w1P, g_w1P);
    cudaGetSymbolAddress((void**)&w2P, g_w2P);
    cudaGetSymbolAddress((void**)&qp, g_qp);
    cudaGetSymbolAddress((void**)&kp, g_kp);
    cudaGetSymbolAddress((void**)&vp, g_vp);

    cudaFuncSetAttribute(flash_mma_kernel,
                         cudaFuncAttributeMaxDynamicSharedMemorySize, FSMEM);
    cudaFuncSetAttribute(mma_gemm_kernel,
                         cudaFuncAttributeMaxDynamicSharedMemorySize, GSMEM);
    cudaFuncSetAttribute(mma_gemm_qkv_kernel,
                         cudaFuncAttributeMaxDynamicSharedMemorySize, GSMEM);

    // all conversions in one launch
    conv_all_kernel<<<4096 + 3072 + 1024, 256>>>(x, W_qkv, W_o, aP, w1P, w2P);

    // 1) QKV GEMM with fused Q/K/V fp16 epilogue   (M=4096, N=3072, K=1024)
    {
        dim3 grid(QKV_COLS / 128, MROWS / 128);
        mma_gemm_qkv_kernel<<<grid, 128, GSMEM>>>(aP, w1P, qp, kp, vp,
                                                  QKV_COLS, DMODEL);
    }
    // 2) flash attention (q-tile 128, writes fp16 aP for out-proj)
    {
        dim3 grid(SEQ / 128, NHEAD, BATCH);
        flash_mma_kernel<<<grid, 256, FSMEM>>>(qp, kp, vp, aP);
    }
    // 3) out = attn_out @ W_o   (M=4096, N=1024, K=1024)
    {
        dim3 grid(DMODEL / 128, MROWS / 128);
        mma_gemm_kernel<<<grid, 128, GSMEM>>>(aP, w2P, out, DMODEL, DMODEL);
    }
}

// round 13
// speedup vs baseline: 8.4339x; 1.0246x over previous
#include <cuda_runtime.h>
#include <cuda_bf16.h>
#include <cuda_fp16.h>
#include <math.h>
#include <stdint.h>

// Problem constants
#define BATCH 2
#define SEQ   2048
#define DMODEL 1024
#define NHEAD 16
#define DHEAD 64
#define MROWS (BATCH * SEQ)           // 4096
#define QKV_COLS (3 * DMODEL)         // 3072
#define QSCALE 0.18033688f            // 0.125 * log2(e)

// ---------------------------------------------------------------------------
// Scratch (static device globals; allocations are forbidden)
// ---------------------------------------------------------------------------
__device__ __half g_aP[(size_t)MROWS * DMODEL];            // 8.4 MB (A fp16, both GEMMs)
__device__ __half g_w1P[(size_t)QKV_COLS * DMODEL];        // 6.3 MB (W_qkv^T fp16)
__device__ __half g_w2P[(size_t)DMODEL * DMODEL];          // 2.1 MB (W_o^T fp16)
// Attention operands (plain fp16, all [b,h,t,64])
__device__ __half g_qp[(size_t)BATCH * NHEAD * SEQ * DHEAD];  // 8.4 MB
__device__ __half g_kp[(size_t)BATCH * NHEAD * SEQ * DHEAD];  // 8.4 MB
__device__ __half g_vp[(size_t)BATCH * NHEAD * SEQ * DHEAD];  // 8.4 MB

__device__ __forceinline__ uint32_t smem_u32(const void* p) {
    uint32_t a;
    asm("{ .reg .u64 t; cvta.to.shared.u64 t, %1; cvt.u32.u64 %0, t; }" : "=r"(a) : "l"(p));
    return a;
}
__device__ __forceinline__ float fast_exp2(float x) {
    float y; asm("ex2.approx.ftz.f32 %0, %1;" : "=f"(y) : "f"(x)); return y;
}
// pack fp16x2: low half = lo, high half = hi
__device__ __forceinline__ uint32_t pack_f16x2(float lo, float hi) {
    uint32_t r; asm("cvt.rn.f16x2.f32 %0, %1, %2;" : "=r"(r) : "f"(hi), "f"(lo)); return r;
}

#define LDMATRIX_X4(r0, r1, r2, r3, addr) \
    asm volatile("ldmatrix.sync.aligned.m8n8.x4.shared.b16 {%0,%1,%2,%3}, [%4];" \
        : "=r"(r0), "=r"(r1), "=r"(r2), "=r"(r3) : "r"(addr))

#define LDMATRIX_X4_TRANS(r0, r1, r2, r3, addr) \
    asm volatile("ldmatrix.sync.aligned.m8n8.x4.trans.shared.b16 {%0,%1,%2,%3}, [%4];" \
        : "=r"(r0), "=r"(r1), "=r"(r2), "=r"(r3) : "r"(addr))

#define MMA_F16(acc, a0, a1, a2, a3, b0, b1) \
    asm volatile( \
        "mma.sync.aligned.m16n8k16.row.col.f32.f16.f16.f32 " \
        "{%0,%1,%2,%3}, {%4,%5,%6,%7}, {%8,%9}, {%0,%1,%2,%3};" \
        : "+f"((acc)[0]), "+f"((acc)[1]), "+f"((acc)[2]), "+f"((acc)[3]) \
        : "r"(a0), "r"(a1), "r"(a2), "r"(a3), "r"(b0), "r"(b1))

// ---------------------------------------------------------------------------
// Merged conversion kernel (single launch):
//   section 0: x fp32 -> aP fp16                  (4096 blocks)
//   section 1: W_qkv -> w1P transpose-cast        (3072 blocks)
//   section 2: W_o   -> w2P transpose-cast        (1024 blocks)
// ---------------------------------------------------------------------------
__global__ void __launch_bounds__(256) conv_all_kernel(
    const float* __restrict__ x, const float* __restrict__ Wq,
    const float* __restrict__ Wo,
    __half* __restrict__ aP, __half* __restrict__ w1P, __half* __restrict__ w2P)
{
    const int bid = blockIdx.x;
    const int tid = threadIdx.x;

    if (bid < 4096) {
        size_t j = (size_t)bid * 256 + tid;
        float4 v = *(const float4*)(x + 4 * j);
        __half2* o = (__half2*)(aP + 4 * j);
        o[0] = __half2(__float2half_rn(v.x), __float2half_rn(v.y));
        o[1] = __half2(__float2half_rn(v.z), __float2half_rn(v.w));
        return;
    }

    __shared__ float t[32][33];
    const int tx = tid & 31, ty = tid >> 5;
    const float* W;
    __half* out;
    int N, bx, by;
    if (bid < 4096 + 3072) {
        int idx = bid - 4096;
        W = Wq; out = w1P; N = QKV_COLS;
        bx = idx % (QKV_COLS / 32); by = idx / (QKV_COLS / 32);
    } else {
        int idx = bid - 4096 - 3072;
        W = Wo; out = w2P; N = DMODEL;
        bx = idx % (DMODEL / 32); by = idx / (DMODEL / 32);
    }
#pragma unroll
    for (int i = 0; i < 4; i++) {
        int k = by * 32 + ty + 8 * i;
        int n = bx * 32 + tx;
        t[ty + 8 * i][tx] = W[(size_t)k * N + n];
    }
    __syncthreads();
#pragma unroll
    for (int i = 0; i < 4; i++) {
        int nl = ty + 8 * i;
        int n = bx * 32 + nl;
        out[(size_t)n * DMODEL + by * 32 + tx] = __float2half_rn(t[tx][nl]);
    }
}

// ---------------------------------------------------------------------------
// GEMM mainloop (fp16, CTA 128x128, 4 warps 64x64, BK=32,
// 4-stage cp.async pipeline, one sync per iter).
// Tile = 128 rows x 32 fp16 = 128 x 4 chunks of 16B = 512 chunks per operand;
// 128 threads x 4 iterations, row = c>>2, ch = c&3 (coalesced within rows).
// ---------------------------------------------------------------------------
#define GBK 32
#define ROWB 80                      // padded row bytes (32 fp16 = 64B data)
#define STILE (128 * ROWB)           // 10240 B
#define GSTAGE (2 * STILE)           // 20480 B
#define GSMEM (4 * GSTAGE)           // 81920 B

#define GEMM_PROLOGUE_AND_LOOP()                                               \
    const int tid = threadIdx.x;                                               \
    const int warp = tid >> 5;                                                 \
    const int lane = tid & 31;                                                 \
    const int bm = blockIdx.y * 128;                                           \
    const int bn = blockIdx.x * 128;                                           \
    const int wm0 = (warp >> 1) * 64;                                          \
    const int wn0 = (warp & 1) * 64;                                           \
    const int a_row_off = (lane & 7) + ((lane >> 3) & 1) * 8;                  \
    const int a_kch = (lane >> 4);                                             \
    const int b_row_off = (lane & 7) + ((lane >> 4) & 1) * 8;                  \
    const int b_kch = (lane >> 3) & 1;                                         \
    const uint32_t sbase = smem_u32(gsm);                                      \
    float acc[4][8][4];                                                        \
    _Pragma("unroll")                                                          \
    for (int mi = 0; mi < 4; mi++)                                             \
        _Pragma("unroll")                                                      \
        for (int ni = 0; ni < 8; ni++)                                         \
            _Pragma("unroll")                                                  \
            for (int r = 0; r < 4; r++) acc[mi][ni][r] = 0.f;                  \
    const int NIT = K / GBK;                                                   \
    auto load_stage = [&](int st, int k0) {                                    \
        uint32_t base = sbase + st * GSTAGE;                                   \
        _Pragma("unroll")                                                      \
        for (int i = 0; i < 4; i++) {                                          \
            int c = tid + i * 128;               /* 0..511 */                  \
            int row = c >> 2, ch = c & 3;                                      \
            uint32_t dA = base + row * ROWB + ch * 16;                         \
            uint32_t dB = dA + STILE;                                          \
            const __half* pA = A + (size_t)(bm + row) * K + k0 + ch * 8;       \
            const __half* pB = B + (size_t)(bn + row) * K + k0 + ch * 8;       \
            asm volatile("cp.async.cg.shared.global [%0], [%1], 16;\n" :: "r"(dA), "l"(pA) : "memory"); \
            asm volatile("cp.async.cg.shared.global [%0], [%1], 16;\n" :: "r"(dB), "l"(pB) : "memory"); \
        }                                                                      \
    };                                                                         \
    load_stage(0, 0);                                                          \
    asm volatile("cp.async.commit_group;\n" ::: "memory");                     \
    load_stage(1, GBK);                                                        \
    asm volatile("cp.async.commit_group;\n" ::: "memory");                     \
    load_stage(2, 2 * GBK);                                                    \
    asm volatile("cp.async.commit_group;\n" ::: "memory");                     \
    int st = 0;                                                                \
    for (int it = 0; it < NIT; it++) {                                         \
        asm volatile("cp.async.wait_group 2;\n" ::: "memory");                 \
        __syncthreads();                                                       \
        if (it + 3 < NIT) load_stage((st + 3) & 3, (it + 3) * GBK);            \
        asm volatile("cp.async.commit_group;\n" ::: "memory");                 \
        uint32_t sA = sbase + st * GSTAGE;                                     \
        uint32_t sB = sA + STILE;                                              \
        _Pragma("unroll")                                                      \
        for (int ks = 0; ks < 2; ks++) {                                       \
            uint32_t af[4][4];                                                 \
            _Pragma("unroll")                                                  \
            for (int mi = 0; mi < 4; mi++) {                                   \
                uint32_t addr = sA + (wm0 + mi * 16 + a_row_off) * ROWB +      \
                                (ks * 2 + a_kch) * 16;                         \
                LDMATRIX_X4(af[mi][0], af[mi][1], af[mi][2], af[mi][3], addr); \
            }                                                                  \
            uint32_t bfr[4][4];                                                \
            _Pragma("unroll")                                                  \
            for (int nj = 0; nj < 4; nj++) {                                   \
                uint32_t addr = sB + (wn0 + nj * 16 + b_row_off) * ROWB +      \
                                (ks * 2 + b_kch) * 16;                         \
                LDMATRIX_X4(bfr[nj][0], bfr[nj][1], bfr[nj][2], bfr[nj][3], addr); \
            }                                                                  \
            _Pragma("unroll")                                                  \
            for (int mi = 0; mi < 4; mi++)                                     \
                _Pragma("unroll")                                              \
                for (int ni = 0; ni < 8; ni++)                                 \
                    MMA_F16(acc[mi][ni], af[mi][0], af[mi][1], af[mi][2], af[mi][3], \
                            bfr[ni >> 1][(ni & 1) * 2 + 0], bfr[ni >> 1][(ni & 1) * 2 + 1]); \
        }                                                                      \
        st = (st + 1) & 3;                                                     \
    }

// ---------------------------------------------------------------------------
// GEMM #2 (out-projection): plain fp32 epilogue.
// ---------------------------------------------------------------------------
__global__ void __launch_bounds__(128, 2) mma_gemm_kernel(
    const __half* __restrict__ A, const __half* __restrict__ B,
    float* __restrict__ C, int N, int K)
{
    extern __shared__ char gsm[];
    GEMM_PROLOGUE_AND_LOOP()

    const int gr = lane >> 2;
    const int tc = (lane & 3) * 2;
#pragma unroll
    for (int mi = 0; mi < 4; mi++) {
#pragma unroll
        for (int ni = 0; ni < 8; ni++) {
            size_t r0 = (size_t)(bm + wm0 + mi * 16 + gr);
            int col = bn + wn0 + ni * 8 + tc;
            *(float2*)&C[r0 * N + col] = make_float2(acc[mi][ni][0], acc[mi][ni][1]);
            *(float2*)&C[(r0 + 8) * N + col] = make_float2(acc[mi][ni][2], acc[mi][ni][3]);
        }
    }
}

// ---------------------------------------------------------------------------
// GEMM #1 (QKV): fused epilogue writes fp16 Q (scaled) / K / V, all [b,h,t,64].
// bn in [0,1024) -> Q, [1024,2048) -> K, [2048,3072) -> V.
// ---------------------------------------------------------------------------
__global__ void __launch_bounds__(128, 2) mma_gemm_qkv_kernel(
    const __half* __restrict__ A, const __half* __restrict__ B,
    __half* __restrict__ qp, __half* __restrict__ kp,
    __half* __restrict__ vp, int N, int K)
{
    extern __shared__ char gsm[];
    GEMM_PROLOGUE_AND_LOOP()

    const int gr = lane >> 2;
    const int tc = (lane & 3) * 2;
    const int sec = bn >> 10;                 // 0=Q, 1=K, 2=V
    const int colbase = (bn & 1023) + wn0;
    __half* const dst = (sec == 0) ? qp : ((sec == 1) ? kp : vp);

#pragma unroll
    for (int mi = 0; mi < 4; mi++) {
#pragma unroll
        for (int rr = 0; rr < 2; rr++) {
            const int row = bm + wm0 + mi * 16 + gr + rr * 8;
            const int b = row >> 11;
            const int t = row & (SEQ - 1);
#pragma unroll
            for (int ni = 0; ni < 8; ni++) {
                const int col = colbase + ni * 8 + tc;    // within section
                float v0 = acc[mi][ni][rr * 2 + 0];
                float v1 = acc[mi][ni][rr * 2 + 1];
                if (sec == 0) { v0 *= QSCALE; v1 *= QSCALE; }
                const int h = col >> 6;
                const int d = col & 63;
                size_t base = ((size_t)((b * NHEAD + h) * SEQ + t)) * DHEAD + d;
                *(__half2*)(dst + base) =
                    __half2(__float2half_rn(v0), __float2half_rn(v1));
            }
        }
    }
}

// ---------------------------------------------------------------------------
// Tensor-core flash attention (FA2), causal, plain fp16.
// CTA: 128 queries x 1 head; 8 warps (each m16 x 64-key tile), 256 threads.
// Q has its own smem region; prologue overlaps Q + K/V tile 0 + tile 1 loads.
// Fully-masked diagonal warps skip compute (bit-identical; their P was 0).
// ---------------------------------------------------------------------------
#define KPITCH 144                  // 64 fp16 = 128B data + 16 pad
#define KS_BYTES (64 * KPITCH)      // 9216
#define FSTAGE (2 * KS_BYTES)       // 18432 (K + V)
#define QS_BYTES (128 * KPITCH)     // 18432 (Q region)
#define FSMEM (2 * FSTAGE + QS_BYTES)  // 55296

__global__ void __launch_bounds__(256, 2) flash_mma_kernel(
    const __half* __restrict__ qp, const __half* __restrict__ kp,
    const __half* __restrict__ vp,
    __half* __restrict__ aP)
{
    extern __shared__ char fsm[];
    const int tid = threadIdx.x;
    const int warp = tid >> 5;
    const int lane = tid & 31;
    const int qt = gridDim.x - 1 - blockIdx.x;      // heavy tiles first
    const int h = blockIdx.y;
    const int b = blockIdx.z;
    const int bh = b * NHEAD + h;
    const int q0 = qt * 128;

    const uint32_t sb = smem_u32(fsm);
    const uint32_t qb = sb + 2 * FSTAGE;            // Q region
    const int gr = lane >> 2;
    const int tc = lane & 3;
    const int a_row_off = (lane & 7) + ((lane >> 3) & 1) * 8;
    const int a_kch = lane >> 4;
    const int b_row_off = (lane & 7) + ((lane >> 4) & 1) * 8;
    const int b_kch = (lane >> 3) & 1;
    // trans-ldmatrix addressing for V (row-major [key][d] tile)
    const int v_row_off = lane & 15;            // key within k16 chunk
    const int v_coff = (lane >> 4) * 16;        // d-half byte offset

    const int nkt = 2 * qt + 2;                 // k-tiles (64 keys each)

    auto load_tile = [&](int kt, int st) {
        const int kt0 = kt * 64;
        uint32_t ks = sb + st * FSTAGE;
        uint32_t vs = ks + KS_BYTES;
        const __half* ksrc = kp + ((size_t)(bh * SEQ + kt0)) * DHEAD;
        const __half* vsrc = vp + ((size_t)(bh * SEQ + kt0)) * DHEAD;
#pragma unroll
        for (int i = 0; i < 2; i++) {
            int c = i * 256 + tid;               // 0..511
            int row = c >> 3, ch = c & 7;
            uint32_t dk = ks + row * KPITCH + ch * 16;
            uint32_t dv = vs + row * KPITCH + ch * 16;
            const __half* sk = ksrc + (size_t)row * DHEAD + ch * 8;
            const __half* sv = vsrc + (size_t)row * DHEAD + ch * 8;
            asm volatile("cp.async.cg.shared.global [%0], [%1], 16;\n" :: "r"(dk), "l"(sk) : "memory");
            asm volatile("cp.async.cg.shared.global [%0], [%1], 16;\n" :: "r"(dv), "l"(sv) : "memory");
        }
    };

    // ---- overlapped prologue: Q + K/V tile 0 + K/V tile 1, then one wait
    {
        const __half* qsrc = qp + ((size_t)(bh * SEQ + q0)) * DHEAD;
#pragma unroll
        for (int i = 0; i < 4; i++) {
            int c = i * 256 + tid;               // 0..1023 (16B chunks)
            int row = c >> 3, ch = c & 7;
            uint32_t dst = qb + row * KPITCH + ch * 16;
            const __half* src = qsrc + (size_t)row * DHEAD + ch * 8;
            asm volatile("cp.async.cg.shared.global [%0], [%1], 16;\n" :: "r"(dst), "l"(src) : "memory");
        }
        asm volatile("cp.async.commit_group;\n" ::: "memory");
    }
    load_tile(0, 0);
    asm volatile("cp.async.commit_group;\n" ::: "memory");
    load_tile(1, 1);
    asm volatile("cp.async.commit_group;\n" ::: "memory");

    // Q group done when <=2 groups pending
    asm volatile("cp.async.wait_group 2;\n" ::: "memory");
    __syncthreads();

    uint32_t qf[4][4];
#pragma unroll
    for (int ck = 0; ck < 4; ck++) {
        uint32_t addr = qb + (warp * 16 + a_row_off) * KPITCH + ck * 32 + a_kch * 16;
        LDMATRIX_X4(qf[ck][0], qf[ck][1], qf[ck][2], qf[ck][3], addr);
    }

    float oacc[8][4];
#pragma unroll
    for (int t = 0; t < 8; t++)
#pragma unroll
        for (int r = 0; r < 4; r++) oacc[t][r] = 0.f;
    float m0 = -1e30f, m1 = -1e30f, l0 = 0.f, l1 = 0.f;

    for (int kt = 0; kt < nkt; kt++) {
        asm volatile("cp.async.wait_group 1;\n" ::: "memory");
        __syncthreads();
        const int st = kt & 1;
        uint32_t ks = sb + st * FSTAGE;
        uint32_t vs = ks + KS_BYTES;

        // warps 0-3 on the last k-tile are fully above the diagonal:
        // their P is exactly 0 there, so skip the compute entirely.
        const bool active = !(kt == nkt - 1 && warp < 4);
        if (active) {
            // ---- S = Q.K^T  (4 k16 chunks over DHEAD=64)
            float sacc[8][4];
#pragma unroll
            for (int t = 0; t < 8; t++)
#pragma unroll
                for (int r = 0; r < 4; r++) sacc[t][r] = 0.f;
#pragma unroll
            for (int ck = 0; ck < 4; ck++) {
                uint32_t bfr[4][4];
#pragma unroll
                for (int nj = 0; nj < 4; nj++) {
                    uint32_t addr = ks + (nj * 16 + b_row_off) * KPITCH + ck * 32 + b_kch * 16;
                    LDMATRIX_X4(bfr[nj][0], bfr[nj][1], bfr[nj][2], bfr[nj][3], addr);
                }
#pragma unroll
                for (int ni = 0; ni < 8; ni++)
                    MMA_F16(sacc[ni], qf[ck][0], qf[ck][1], qf[ck][2], qf[ck][3],
                            bfr[ni >> 1][(ni & 1) * 2 + 0], bfr[ni >> 1][(ni & 1) * 2 + 1]);
            }

            // ---- causal mask on the two diagonal-spanning k-tiles
            if (kt >= nkt - 2) {
                const int kt0 = kt * 64;
                int rq0 = q0 + warp * 16 + gr;
                int rq1 = rq0 + 8;
#pragma unroll
                for (int t = 0; t < 8; t++) {
                    int c0 = kt0 + 8 * t + 2 * tc;
                    if (c0 > rq0)     sacc[t][0] = -1e30f;
                    if (c0 + 1 > rq0) sacc[t][1] = -1e30f;
                    if (c0 > rq1)     sacc[t][2] = -1e30f;
                    if (c0 + 1 > rq1) sacc[t][3] = -1e30f;
                }
            }

            // ---- online softmax (base-2, quad reductions)
            float mx0 = -1e30f, mx1 = -1e30f;
#pragma unroll
            for (int t = 0; t < 8; t++) {
                mx0 = fmaxf(mx0, fmaxf(sacc[t][0], sacc[t][1]));
                mx1 = fmaxf(mx1, fmaxf(sacc[t][2], sacc[t][3]));
            }
            mx0 = fmaxf(mx0, __shfl_xor_sync(0xffffffffu, mx0, 1));
            mx0 = fmaxf(mx0, __shfl_xor_sync(0xffffffffu, mx0, 2));
            mx1 = fmaxf(mx1, __shfl_xor_sync(0xffffffffu, mx1, 1));
            mx1 = fmaxf(mx1, __shfl_xor_sync(0xffffffffu, mx1, 2));
            float mn0 = fmaxf(m0, mx0), mn1 = fmaxf(m1, mx1);
            float cr0 = fast_exp2(m0 - mn0), cr1 = fast_exp2(m1 - mn1);
            m0 = mn0; m1 = mn1;
            l0 *= cr0; l1 *= cr1;
#pragma unroll
            for (int t = 0; t < 8; t++) {
                oacc[t][0] *= cr0; oacc[t][1] *= cr0;
                oacc[t][2] *= cr1; oacc[t][3] *= cr1;
            }
            uint32_t phi[8][2];
            float rs0 = 0.f, rs1 = 0.f;
#pragma unroll
            for (int t = 0; t < 8; t++) {
                float p0 = fast_exp2(sacc[t][0] - m0);
                float p1 = fast_exp2(sacc[t][1] - m0);
                float p2 = fast_exp2(sacc[t][2] - m1);
                float p3 = fast_exp2(sacc[t][3] - m1);
                rs0 += p0 + p1; rs1 += p2 + p3;
                phi[t][0] = pack_f16x2(p0, p1);
                phi[t][1] = pack_f16x2(p2, p3);
            }
            rs0 += __shfl_xor_sync(0xffffffffu, rs0, 1);
            rs0 += __shfl_xor_sync(0xffffffffu, rs0, 2);
            rs1 += __shfl_xor_sync(0xffffffffu, rs1, 1);
            rs1 += __shfl_xor_sync(0xffffffffu, rs1, 2);
            l0 += rs0; l1 += rs1;

            // ---- PV: O += P.V  (V row-major; B-frags via ldmatrix.trans)
#pragma unroll
            for (int ck = 0; ck < 4; ck++) {
                uint32_t aph[4] = { phi[2 * ck][0], phi[2 * ck][1],
                                    phi[2 * ck + 1][0], phi[2 * ck + 1][1] };
                uint32_t vfr[4][4];
#pragma unroll
                for (int dt = 0; dt < 4; dt++) {
                    uint32_t addr = vs + (ck * 16 + v_row_off) * KPITCH + dt * 32 + v_coff;
                    LDMATRIX_X4_TRANS(vfr[dt][0], vfr[dt][1], vfr[dt][2], vfr[dt][3], addr);
                }
#pragma unroll
                for (int ni = 0; ni < 8; ni++)
                    MMA_F16(oacc[ni], aph[0], aph[1], aph[2], aph[3],
                            vfr[ni >> 1][(ni & 1) * 2 + 0], vfr[ni >> 1][(ni & 1) * 2 + 1]);
            }
        }

        __syncthreads();
        if (kt + 2 < nkt) load_tile(kt + 2, st);
        asm volatile("cp.async.commit_group;\n" ::: "memory");
    }

    // ---- epilogue: write plain fp16 attention output into aP [M x 1024]
    const float inv0 = 1.f / l0, inv1 = 1.f / l1;
    const int qr0 = q0 + warp * 16 + gr;
    const int qr1 = qr0 + 8;
#pragma unroll
    for (int t = 0; t < 8; t++) {
        int col = h * DHEAD + 8 * t + 2 * tc;
        *(__half2*)(aP + ((size_t)(b * SEQ + qr0)) * DMODEL + col) =
            __half2(__float2half_rn(oacc[t][0] * inv0), __float2half_rn(oacc[t][1] * inv0));
        *(__half2*)(aP + ((size_t)(b * SEQ + qr1)) * DMODEL + col) =
            __half2(__float2half_rn(oacc[t][2] * inv1), __float2half_rn(oacc[t][3] * inv1));
    }
}

// ---------------------------------------------------------------------------
extern "C" void kernel_launch(void* const* d_in, const int* in_sizes, int n_in,
                              void* d_out, int out_size)
{
    const float* x     = (const float*)d_in[0];
    const float* W_qkv = (const float*)d_in[1];
    const float* W_o   = (const float*)d_in[2];
    float* out = (float*)d_out;

    __half *aP, *w1P, *w2P, *qp, *kp, *vp;
    cudaGetSymbolAddress((void**)&aP, g_aP);
    cudaGetSymbolAddress((void**)&w1P, g_w1P);
    cudaGetSymbolAddress((void**)&w2P, g_w2P);
    cudaGetSymbolAddress((void**)&qp, g_qp);
    cudaGetSymbolAddress((void**)&kp, g_kp);
    cudaGetSymbolAddress((void**)&vp, g_vp);

    cudaFuncSetAttribute(flash_mma_kernel,
                         cudaFuncAttributeMaxDynamicSharedMemorySize, FSMEM);
    cudaFuncSetAttribute(mma_gemm_kernel,
                         cudaFuncAttributeMaxDynamicSharedMemorySize, GSMEM);
    cudaFuncSetAttribute(mma_gemm_qkv_kernel,
                         cudaFuncAttributeMaxDynamicSharedMemorySize, GSMEM);

    // all conversions in one launch
    conv_all_kernel<<<4096 + 3072 + 1024, 256>>>(x, W_qkv, W_o, aP, w1P, w2P);

    // 1) QKV GEMM with fused Q/K/V fp16 epilogue   (M=4096, N=3072, K=1024)
    {
        dim3 grid(QKV_COLS / 128, MROWS / 128);
        mma_gemm_qkv_kernel<<<grid, 128, GSMEM>>>(aP, w1P, qp, kp, vp,
                                                  QKV_COLS, DMODEL);
    }
    // 2) flash attention (q-tile 128, writes fp16 aP for out-proj)
    {
        dim3 grid(SEQ / 128, NHEAD, BATCH);
        flash_mma_kernel<<<grid, 256, FSMEM>>>(qp, kp, vp, aP);
    }
    // 3) out = attn_out @ W_o   (M=4096, N=1024, K=1024)
    {
        dim3 grid(DMODEL / 128, MROWS / 128);
        mma_gemm_kernel<<<grid, 128, GSMEM>>>(aP, w2P, out, DMODEL, DMODEL);
    }
}